// round 9
// baseline (speedup 1.0000x reference)
#include <cuda_runtime.h>
#include <cuda_bf16.h>
#include <math.h>
#include <stdint.h>

#define N_NODES  50000
#define N_EDGES  800000
#define N_GRAPHS 2500

// ---------------- scratch (device globals; no allocations allowed) ----------
__device__ __align__(256) float g_q[N_NODES * 256];
__device__ __align__(256) float g_skip[N_NODES * 256];
__device__ __align__(256) float g_h[N_NODES * 128];
__device__ __align__(256) float g_cw[N_EDGES];
__device__ __align__(256) int   g_csrc[N_EDGES];
__device__ __align__(256) int   g_rowptr[N_NODES + 1];
__device__ __align__(256) int   g_wof[N_NODES];
__device__ __align__(256) int   g_bsum[256];
__device__ __align__(256) float g_cnt[N_GRAPHS];
__device__ __align__(256) float g_bias[1024];
// bf16 operands
__device__ __align__(256) __nv_bfloat16 g_kv[N_NODES * 512];   // [k(256) | v(256)]
__device__ __align__(256) __nv_bfloat16 g_ahi[N_NODES * 256];
__device__ __align__(256) __nv_bfloat16 g_alo[N_NODES * 256];
__device__ __align__(256) __nv_bfloat16 g_whi[262144];         // packed [K, NTOT]
__device__ __align__(256) __nv_bfloat16 g_wlo[262144];

// ================= warp-MMA helpers ==========================================
__device__ __forceinline__ uint32_t smem_u32(const void* p) {
    uint32_t a;
    asm("{ .reg .u64 t; cvta.to.shared.u64 t, %1; cvt.u32.u64 %0, t; }"
        : "=r"(a) : "l"(p));
    return a;
}

__device__ __forceinline__ void ldsm_x4(uint32_t r[4], uint32_t addr) {
    asm volatile("ldmatrix.sync.aligned.m8n8.x4.shared.b16 {%0,%1,%2,%3}, [%4];"
        : "=r"(r[0]), "=r"(r[1]), "=r"(r[2]), "=r"(r[3]) : "r"(addr));
}
__device__ __forceinline__ void ldsm_x4_t(uint32_t r[4], uint32_t addr) {
    asm volatile("ldmatrix.sync.aligned.m8n8.x4.trans.shared.b16 {%0,%1,%2,%3}, [%4];"
        : "=r"(r[0]), "=r"(r[1]), "=r"(r[2]), "=r"(r[3]) : "r"(addr));
}

__device__ __forceinline__ void mma16816(float d[4], const uint32_t a[4],
                                         const uint32_t b[2]) {
    asm volatile(
        "mma.sync.aligned.m16n8k16.row.col.f32.bf16.bf16.f32 "
        "{%0,%1,%2,%3}, {%4,%5,%6,%7}, {%8,%9}, {%0,%1,%2,%3};"
        : "+f"(d[0]), "+f"(d[1]), "+f"(d[2]), "+f"(d[3])
        : "r"(a[0]), "r"(a[1]), "r"(a[2]), "r"(a[3]), "r"(b[0]), "r"(b[1]));
}

__device__ __forceinline__ void cp_async16(uint32_t dst, const void* src, int sz) {
    asm volatile("cp.async.cg.shared.global [%0], [%1], 16, %2;"
        :: "r"(dst), "l"(src), "r"(sz));
}
__device__ __forceinline__ void cp_commit() {
    asm volatile("cp.async.commit_group;" ::: "memory");
}

__device__ __forceinline__ void bf8_to_f(const uint4& u, float* f) {
    float2 p;
    p = __bfloat1622float2(*(const __nv_bfloat162*)&u.x); f[0] = p.x; f[1] = p.y;
    p = __bfloat1622float2(*(const __nv_bfloat162*)&u.y); f[2] = p.x; f[3] = p.y;
    p = __bfloat1622float2(*(const __nv_bfloat162*)&u.z); f[4] = p.x; f[5] = p.y;
    p = __bfloat1622float2(*(const __nv_bfloat162*)&u.w); f[6] = p.x; f[7] = p.y;
}

// =============== fp32 -> bf16 hi/lo split ======================================
__device__ __forceinline__ void split4(float4 v, uint2& hv, uint2& lv) {
    __nv_bfloat16 h0 = __float2bfloat16(v.x);
    __nv_bfloat16 h1 = __float2bfloat16(v.y);
    __nv_bfloat16 h2 = __float2bfloat16(v.z);
    __nv_bfloat16 h3 = __float2bfloat16(v.w);
    __nv_bfloat16 l0 = __float2bfloat16(v.x - __bfloat162float(h0));
    __nv_bfloat16 l1 = __float2bfloat16(v.y - __bfloat162float(h1));
    __nv_bfloat16 l2 = __float2bfloat16(v.z - __bfloat162float(h2));
    __nv_bfloat16 l3 = __float2bfloat16(v.w - __bfloat162float(h3));
    __nv_bfloat162 hp0 = __halves2bfloat162(h0, h1);
    __nv_bfloat162 hp1 = __halves2bfloat162(h2, h3);
    __nv_bfloat162 lp0 = __halves2bfloat162(l0, l1);
    __nv_bfloat162 lp1 = __halves2bfloat162(l2, l3);
    hv = make_uint2(*(uint32_t*)&hp0, *(uint32_t*)&hp1);
    lv = make_uint2(*(uint32_t*)&lp0, *(uint32_t*)&lp1);
}

__global__ __launch_bounds__(256) void cvt_split_kernel(
    const float* __restrict__ src, __nv_bfloat16* __restrict__ hi,
    __nv_bfloat16* __restrict__ lo, int n4)
{
    int i = blockIdx.x * blockDim.x + threadIdx.x;
    if (i >= n4) return;
    uint2 hv, lv;
    split4(((const float4*)src)[i], hv, lv);
    *(uint2*)&hi[i * 4] = hv;
    *(uint2*)&lo[i * 4] = lv;
}

// pack 4 weight matrices [K,wm] into one [K,NTOT] bf16 hi/lo, seg offsets 0/256/512/768
__global__ __launch_bounds__(256) void pack_w_kernel(
    const float* s0, const float* s1, const float* s2, const float* s3,
    int w3, int K, int NTOT,
    __nv_bfloat16* __restrict__ hi, __nv_bfloat16* __restrict__ lo)
{
    const float* srcs[4] = {s0, s1, s2, s3};
    int m = blockIdx.y;
    int wm = (m == 3) ? w3 : 256;
    int wm4 = wm >> 2;
    int total4 = K * wm4;
    int i = blockIdx.x * 256 + threadIdx.x;
    if (i >= total4) return;
    int kk = i / wm4;
    int n4 = i - kk * wm4;
    uint2 hv, lv;
    split4(((const float4*)srcs[m])[i], hv, lv);
    size_t d = (size_t)kk * NTOT + (m << 8) + n4 * 4;
    *(uint2*)&hi[d] = hv;
    *(uint2*)&lo[d] = lv;
}

__global__ __launch_bounds__(256) void pack_bias_kernel(
    const float* bq, const float* bk, const float* bv, const float* bs, int NTOT)
{
    int i = blockIdx.x * 256 + threadIdx.x;
    if (i >= NTOT) return;
    int seg = i >> 8, col = i & 255;
    float v = (seg == 0) ? bq[col] : (seg == 1) ? bk[col]
            : (seg == 2) ? bv[col] : bs[col];
    g_bias[i] = v;
}

// ================= fused q/k/v/skip GEMM (cp.async double-buffered) ==========
// smem stage layout (bytes): A_hi[128][40] | A_lo[128][40] | B_hi[32][136] | B_lo[32][136]
#define ST_A_HI 0
#define ST_A_LO 10240
#define ST_B_HI 20480
#define ST_B_LO 29184
#define ST_SIZE 37888
#define GSMEM_TOT (2 * ST_SIZE)

// Column segments of packed W: [0,256)=q fp32, [256,512)=k->kv, [512,768)=v->kv,
// [768,...)=skip fp32 (width 256 if CONCAT else 128).
template <int CONCAT>
__global__ __launch_bounds__(256) void gemm_fused_kernel(
    const __nv_bfloat16* __restrict__ aHi, const __nv_bfloat16* __restrict__ aLo,
    float* __restrict__ Yq, __nv_bfloat16* __restrict__ Ykv,
    float* __restrict__ Ys, int K, int NTOT)
{
    extern __shared__ __align__(16) char smem[];
    const uint32_t sb = smem_u32(smem);
    const __nv_bfloat16* wHi = g_whi;
    const __nv_bfloat16* wLo = g_wlo;

    const int t    = threadIdx.x;
    const int lane = t & 31;
    const int wid  = t >> 5;
    const int wm   = wid & 3;
    const int wn   = wid >> 2;
    const int r0   = blockIdx.x * 128;
    const int c0   = blockIdx.y * 128;

    float acc[2][8][4] = {};

    const int aRow = lane & 15;
    const int aCol = (lane >> 4) * 8;
    const int bK   = lane & 15;
    const int bN   = (lane >> 4) * 8;

    const int nChunks = K >> 5;

    auto stage = [&](int c, int buf) {
        uint32_t st = sb + buf * ST_SIZE;
        int kc = c << 5;
#pragma unroll
        for (int it = 0; it < 2; ++it) {
            int fid = t + it * 256;
            int row = fid >> 2;
            int col = (fid & 3) * 8;
            int rg  = r0 + row;
            int ok  = (rg < N_NODES) ? 16 : 0;
            int rc  = (rg < N_NODES) ? rg : (N_NODES - 1);
            size_t gidx = (size_t)rc * K + kc + col;
            uint32_t d = st + row * 80 + col * 2;
            cp_async16(d + ST_A_HI, &aHi[gidx], ok);
            cp_async16(d + ST_A_LO, &aLo[gidx], ok);
        }
#pragma unroll
        for (int it = 0; it < 2; ++it) {
            int fid = t + it * 256;
            int kk  = fid >> 4;
            int n   = (fid & 15) * 8;
            size_t gidx = (size_t)(kc + kk) * NTOT + c0 + n;
            uint32_t d = st + kk * 272 + n * 2;
            cp_async16(d + ST_B_HI, &wHi[gidx], 16);
            cp_async16(d + ST_B_LO, &wLo[gidx], 16);
        }
        cp_commit();
    };

    stage(0, 0);
    for (int c = 0; c < nChunks; ++c) {
        bool more = (c + 1 < nChunks);
        if (more) stage(c + 1, (c + 1) & 1);
        if (more) asm volatile("cp.async.wait_group 1;" ::: "memory");
        else      asm volatile("cp.async.wait_group 0;" ::: "memory");
        __syncthreads();

        uint32_t st = sb + (c & 1) * ST_SIZE;
#pragma unroll
        for (int ks = 0; ks < 2; ++ks) {
            uint32_t aH[2][4], aL[2][4], bf[4][4];
#pragma unroll
            for (int mi = 0; mi < 2; ++mi) {
                uint32_t ar = st + (wm * 32 + mi * 16 + aRow) * 80 + (ks * 16 + aCol) * 2;
                ldsm_x4(aH[mi], ar + ST_A_HI);
                ldsm_x4(aL[mi], ar + ST_A_LO);
            }
#pragma unroll
            for (int pi = 0; pi < 4; ++pi)
                ldsm_x4_t(bf[pi], st + ST_B_HI + (ks * 16 + bK) * 272
                                     + (wn * 64 + pi * 16 + bN) * 2);
#pragma unroll
            for (int mi = 0; mi < 2; ++mi)
#pragma unroll
                for (int pi = 0; pi < 4; ++pi) {
                    mma16816(acc[mi][2 * pi],     aH[mi], &bf[pi][0]);
                    mma16816(acc[mi][2 * pi + 1], aH[mi], &bf[pi][2]);
                }
#pragma unroll
            for (int mi = 0; mi < 2; ++mi)
#pragma unroll
                for (int pi = 0; pi < 4; ++pi) {
                    mma16816(acc[mi][2 * pi],     aL[mi], &bf[pi][0]);
                    mma16816(acc[mi][2 * pi + 1], aL[mi], &bf[pi][2]);
                }
#pragma unroll
            for (int pi = 0; pi < 4; ++pi)
                ldsm_x4_t(bf[pi], st + ST_B_LO + (ks * 16 + bK) * 272
                                     + (wn * 64 + pi * 16 + bN) * 2);
#pragma unroll
            for (int mi = 0; mi < 2; ++mi)
#pragma unroll
                for (int pi = 0; pi < 4; ++pi) {
                    mma16816(acc[mi][2 * pi],     aH[mi], &bf[pi][0]);
                    mma16816(acc[mi][2 * pi + 1], aH[mi], &bf[pi][2]);
                }
        }
        __syncthreads();
    }

    // ---- epilogue: route segment to q / kv / skip -----------------------------
    const int seg = c0 >> 8;
#pragma unroll
    for (int mi = 0; mi < 2; ++mi) {
        int rA = r0 + wm * 32 + mi * 16 + (lane >> 2);
        int rB = rA + 8;
#pragma unroll
        for (int ni = 0; ni < 8; ++ni) {
            int cc  = c0 + wn * 64 + ni * 8 + (lane & 3) * 2;   // packed col
            float2 bv = *(const float2*)&g_bias[cc];
            float x0 = acc[mi][ni][0] + bv.x, y0 = acc[mi][ni][1] + bv.y;
            float x1 = acc[mi][ni][2] + bv.x, y1 = acc[mi][ni][3] + bv.y;
            int col = cc - (seg << 8);                           // in-segment col
            if (seg == 1 || seg == 2) {
                int kcol = col + ((seg == 2) ? 256 : 0);
                if (rA < N_NODES)
                    *(__nv_bfloat162*)&Ykv[(size_t)rA * 512 + kcol] =
                        __floats2bfloat162_rn(x0, y0);
                if (rB < N_NODES)
                    *(__nv_bfloat162*)&Ykv[(size_t)rB * 512 + kcol] =
                        __floats2bfloat162_rn(x1, y1);
            } else {
                float* Y = (seg == 0) ? Yq : Ys;
                int ld = (seg == 0) ? 256 : (CONCAT ? 256 : 128);
                if (rA < N_NODES)
                    *(float2*)&Y[(size_t)rA * ld + col] = make_float2(x0, y0);
                if (rB < N_NODES)
                    *(float2*)&Y[(size_t)rB * ld + col] = make_float2(x1, y1);
            }
        }
    }
}

// =============== CSR build ====================================================
__global__ __launch_bounds__(256) void zero_wof_kernel() {
    int i = blockIdx.x * blockDim.x + threadIdx.x;
    if (i < N_NODES) g_wof[i] = 0;
}

__global__ __launch_bounds__(256) void hist_kernel(const int* __restrict__ ei) {
    int e = blockIdx.x * blockDim.x + threadIdx.x;
    if (e < N_EDGES) atomicAdd(&g_wof[ei[N_EDGES + e]], 1);
}

__global__ __launch_bounds__(256) void scan1_kernel() {
    __shared__ int sb[2][256];
    int t = threadIdx.x;
    int i = blockIdx.x * 256 + t;
    int v = (i < N_NODES) ? g_wof[i] : 0;
    int pin = 0;
    sb[0][t] = v;
    __syncthreads();
#pragma unroll
    for (int off = 1; off < 256; off <<= 1) {
        int x = sb[pin][t];
        if (t >= off) x += sb[pin][t - off];
        sb[pin ^ 1][t] = x;
        __syncthreads();
        pin ^= 1;
    }
    int incl = sb[pin][t];
    if (i < N_NODES) g_rowptr[i] = incl - v;
    if (t == 255) g_bsum[blockIdx.x] = incl;
}

__global__ __launch_bounds__(256) void scan2_kernel(int nblk) {
    __shared__ int sb[2][256];
    int t = threadIdx.x;
    int v = (t < nblk) ? g_bsum[t] : 0;
    int pin = 0;
    sb[0][t] = v;
    __syncthreads();
#pragma unroll
    for (int off = 1; off < 256; off <<= 1) {
        int x = sb[pin][t];
        if (t >= off) x += sb[pin][t - off];
        sb[pin ^ 1][t] = x;
        __syncthreads();
        pin ^= 1;
    }
    if (t < nblk) g_bsum[t] = sb[pin][t] - v;
    if (t == 0) g_rowptr[N_NODES] = N_EDGES;
}

__global__ __launch_bounds__(256) void scan3_kernel() {
    int i = blockIdx.x * 256 + threadIdx.x;
    if (i >= N_NODES) return;
    int r = g_rowptr[i] + g_bsum[blockIdx.x];
    g_rowptr[i] = r;
    g_wof[i]    = r;
}

__global__ __launch_bounds__(256) void csr_scatter_kernel(
    const int* __restrict__ ei, const float* __restrict__ ea)
{
    int e = blockIdx.x * blockDim.x + threadIdx.x;
    if (e >= N_EDGES) return;
    int src = ei[e];
    int dst = ei[N_EDGES + e];
    int pos = atomicAdd(&g_wof[dst], 1);
    g_csrc[pos] = src;
    g_cw[pos]   = ea[e];
}

// =============== per-node attention: unroll-4, deep load pipelining ==========
template <int CONCAT>
__global__ __launch_bounds__(256, 2) void node_attn_kernel(
    const float* __restrict__ q, const __nv_bfloat16* __restrict__ kv,
    const float* __restrict__ skip, const float* __restrict__ We,
    float* __restrict__ outf, __nv_bfloat16* __restrict__ ohi,
    __nv_bfloat16* __restrict__ olo)
{
    int n = blockIdx.x * 8 + (threadIdx.x >> 5);
    if (n >= N_NODES) return;
    int lane = threadIdx.x & 31;
    int beg = g_rowptr[n], end = g_rowptr[n + 1];

    const float scale = 0.08838834764831845f;   // 1/sqrt(128)

    float qv[8], ev[8];
    {
        const float* qr = q + (size_t)n * 256 + lane * 8;
        *(float4*)&qv[0] = *(const float4*)(qr);
        *(float4*)&qv[4] = *(const float4*)(qr + 4);
        *(float4*)&ev[0] = *(const float4*)(We + lane * 8);
        *(float4*)&ev[4] = *(const float4*)(We + lane * 8 + 4);
    }
    float qe = 0.f;
#pragma unroll
    for (int i = 0; i < 8; ++i) qe = fmaf(qv[i], ev[i], qe);
#pragma unroll
    for (int o = 8; o; o >>= 1) qe += __shfl_xor_sync(0xffffffffu, qe, o);
    qe *= scale;

    float d = 0.f, cw = 0.f;
    float a[8] = {};

    int p = beg;
    // ---- unroll 4: all 8 kv loads issued before any consumption ----
    for (; p + 3 < end; p += 4) {
        int ss[4]; float ww[4];
#pragma unroll
        for (int j = 0; j < 4; ++j) { ss[j] = g_csrc[p + j]; ww[j] = g_cw[p + j]; }
        uint4 ku[4], vu[4];
#pragma unroll
        for (int j = 0; j < 4; ++j) {
            const uint4* r = (const uint4*)(kv + (size_t)ss[j] * 512);
            ku[j] = r[lane];
            vu[j] = r[32 + lane];
        }
        float tt[4];
#pragma unroll
        for (int j = 0; j < 4; ++j) {
            float kf[8];
            bf8_to_f(ku[j], kf);
            float t = 0.f;
#pragma unroll
            for (int i = 0; i < 8; ++i) t = fmaf(qv[i], kf[i], t);
            tt[j] = t;
        }
#pragma unroll
        for (int o = 8; o; o >>= 1) {
#pragma unroll
            for (int j = 0; j < 4; ++j)
                tt[j] += __shfl_xor_sync(0xffffffffu, tt[j], o);
        }
        float x[4];
#pragma unroll
        for (int j = 0; j < 4; ++j) {
            x[j] = __expf(fmaf(ww[j], qe, tt[j] * scale));
            d += x[j];
            cw += x[j] * ww[j];
        }
#pragma unroll
        for (int j = 0; j < 4; ++j) {
            float vf[8];
            bf8_to_f(vu[j], vf);
#pragma unroll
            for (int i = 0; i < 8; ++i) a[i] += x[j] * vf[i];
        }
    }
    // ---- tail (<=3 edges) ----
    for (; p < end; ++p) {
        int s = g_csrc[p];
        float w = g_cw[p];
        const uint4* r = (const uint4*)(kv + (size_t)s * 512);
        uint4 ku = r[lane], vu = r[32 + lane];
        float kf[8];
        bf8_to_f(ku, kf);
        float t = 0.f;
#pragma unroll
        for (int i = 0; i < 8; ++i) t = fmaf(qv[i], kf[i], t);
#pragma unroll
        for (int o = 8; o; o >>= 1) t += __shfl_xor_sync(0xffffffffu, t, o);
        float x = __expf(fmaf(w, qe, t * scale));
        d += x; cw += x * w;
        float vf[8];
        bf8_to_f(vu, vf);
#pragma unroll
        for (int i = 0; i < 8; ++i) a[i] += x * vf[i];
    }

    float r = d > 0.f ? 1.f / d : 0.f;
    float o8[8];
#pragma unroll
    for (int i = 0; i < 8; ++i) o8[i] = (a[i] + cw * ev[i]) * r;

    if (CONCAT) {
        float sk[8];
        const float* sr = skip + (size_t)n * 256 + lane * 8;
        *(float4*)&sk[0] = *(const float4*)(sr);
        *(float4*)&sk[4] = *(const float4*)(sr + 4);
        __align__(16) __nv_bfloat16 hb[8], lb[8];
#pragma unroll
        for (int i = 0; i < 8; ++i) {
            float o = fmaxf(o8[i] + sk[i], 0.f);
            hb[i] = __float2bfloat16(o);
            lb[i] = __float2bfloat16(o - __bfloat162float(hb[i]));
        }
        *(uint4*)&ohi[(size_t)n * 256 + lane * 8] = *(uint4*)hb;
        *(uint4*)&olo[(size_t)n * 256 + lane * 8] = *(uint4*)lb;
    } else {
        float m[8];
#pragma unroll
        for (int i = 0; i < 8; ++i) {
            float other = __shfl_xor_sync(0xffffffffu, o8[i], 16);
            m[i] = 0.5f * (o8[i] + other);
        }
        if (lane < 16) {
            const float* sr = skip + (size_t)n * 128 + lane * 8;
            float4 s0 = *(const float4*)(sr);
            float4 s1 = *(const float4*)(sr + 4);
            float4 w0 = make_float4(m[0] + s0.x, m[1] + s0.y, m[2] + s0.z, m[3] + s0.w);
            float4 w1 = make_float4(m[4] + s1.x, m[5] + s1.y, m[6] + s1.z, m[7] + s1.w);
            *(float4*)&outf[(size_t)n * 128 + lane * 8]     = w0;
            *(float4*)&outf[(size_t)n * 128 + lane * 8 + 4] = w1;
        }
    }
}

// =============== pooling =======================================================
__global__ __launch_bounds__(256) void pool_zero_kernel(float* __restrict__ out) {
    int i = blockIdx.x * blockDim.x + threadIdx.x;
    if (i < N_GRAPHS * 128) out[i] = 0.f;
    if (i < N_GRAPHS) g_cnt[i] = 0.f;
}

__global__ __launch_bounds__(128) void pool_sum_kernel(
    const int* __restrict__ batch, const float* __restrict__ h,
    float* __restrict__ out)
{
    int n = blockIdx.x;
    int c = threadIdx.x;
    int g = batch[n];
    atomicAdd(&out[(size_t)g * 128 + c], h[(size_t)n * 128 + c]);
    if (c == 0) atomicAdd(&g_cnt[g], 1.f);
}

__global__ __launch_bounds__(256) void pool_div_kernel(float* __restrict__ out) {
    int i = blockIdx.x * blockDim.x + threadIdx.x;
    if (i >= N_GRAPHS * 128) return;
    out[i] /= fmaxf(g_cnt[i >> 7], 1.f);
}

// =============== launch =========================================================
extern "C" void kernel_launch(void* const* d_in, const int* in_sizes, int n_in,
                              void* d_out, int out_size)
{
    const float* x     = (const float*)d_in[0];
    const int*   ei    = (const int*)d_in[1];
    const int*   batch = (const int*)d_in[2];
    const float* ea    = (const float*)d_in[3];
    const float* Wq1 = (const float*)d_in[4];
    const float* bq1 = (const float*)d_in[5];
    const float* Wk1 = (const float*)d_in[6];
    const float* bk1 = (const float*)d_in[7];
    const float* Wv1 = (const float*)d_in[8];
    const float* bv1 = (const float*)d_in[9];
    const float* We1 = (const float*)d_in[10];
    const float* Ws1 = (const float*)d_in[11];
    const float* bs1 = (const float*)d_in[12];
    const float* Wq2 = (const float*)d_in[13];
    const float* bq2 = (const float*)d_in[14];
    const float* Wk2 = (const float*)d_in[15];
    const float* bk2 = (const float*)d_in[16];
    const float* Wv2 = (const float*)d_in[17];
    const float* bv2 = (const float*)d_in[18];
    const float* We2 = (const float*)d_in[19];
    const float* Ws2 = (const float*)d_in[20];
    const float* bs2 = (const float*)d_in[21];
    float* out = (float*)d_out;

    float *pq, *pskip, *ph;
    __nv_bfloat16 *pkv, *pahi, *palo, *pwhi, *pwlo;
    cudaGetSymbolAddress((void**)&pq,    g_q);
    cudaGetSymbolAddress((void**)&pskip, g_skip);
    cudaGetSymbolAddress((void**)&ph,    g_h);
    cudaGetSymbolAddress((void**)&pkv,   g_kv);
    cudaGetSymbolAddress((void**)&pahi,  g_ahi);
    cudaGetSymbolAddress((void**)&palo,  g_alo);
    cudaGetSymbolAddress((void**)&pwhi,  g_whi);
    cudaGetSymbolAddress((void**)&pwlo,  g_wlo);

    cudaFuncSetAttribute(gemm_fused_kernel<1>,
                         cudaFuncAttributeMaxDynamicSharedMemorySize, GSMEM_TOT);
    cudaFuncSetAttribute(gemm_fused_kernel<0>,
                         cudaFuncAttributeMaxDynamicSharedMemorySize, GSMEM_TOT);

    const int RT  = (N_NODES + 127) / 128;            // 391 row tiles
    const int EB  = (N_EDGES + 255) / 256;
    const int NB  = (N_NODES + 255) / 256;            // 196
    const int NWB = (N_NODES + 7) / 8;
    const int PZ  = (N_GRAPHS * 128 + 255) / 256;

    // ---- CSR build ----
    zero_wof_kernel<<<NB, 256>>>();
    hist_kernel<<<EB, 256>>>(ei);
    scan1_kernel<<<NB, 256>>>();
    scan2_kernel<<<1, 256>>>(NB);
    scan3_kernel<<<NB, 256>>>();
    csr_scatter_kernel<<<EB, 256>>>(ei, ea);

    // ---- layer 1 (K=128, NTOT=1024, concat heads) ----
    cvt_split_kernel<<<(N_NODES * 128 / 4 + 255) / 256, 256>>>(x, pahi, palo, N_NODES * 128 / 4);
    pack_w_kernel<<<dim3(32, 4), 256>>>(Wq1, Wk1, Wv1, Ws1, 256, 128, 1024, pwhi, pwlo);
    pack_bias_kernel<<<4, 256>>>(bq1, bk1, bv1, bs1, 1024);
    gemm_fused_kernel<1><<<dim3(RT, 8), 256, GSMEM_TOT>>>(pahi, palo, pq, pkv, pskip, 128, 1024);
    node_attn_kernel<1><<<NWB, 256>>>(pq, pkv, pskip, We1, nullptr, pahi, palo);

    // ---- layer 2 (K=256, NTOT=896, mean heads); A = hi/lo written by attn<1> ----
    pack_w_kernel<<<dim3(64, 4), 256>>>(Wq2, Wk2, Wv2, Ws2, 128, 256, 896, pwhi, pwlo);
    pack_bias_kernel<<<4, 256>>>(bq2, bk2, bv2, bs2, 896);
    gemm_fused_kernel<0><<<dim3(RT, 7), 256, GSMEM_TOT>>>(pahi, palo, pq, pkv, pskip, 256, 896);
    node_attn_kernel<0><<<NWB, 256>>>(pq, pkv, pskip, We2, ph, nullptr, nullptr);

    // ---- global mean pool ----
    pool_zero_kernel<<<PZ, 256>>>(out);
    pool_sum_kernel<<<N_NODES, 128>>>(batch, ph, out);
    pool_div_kernel<<<PZ, 256>>>(out);
}

// round 10
// speedup vs baseline: 1.1500x; 1.1500x over previous
#include <cuda_runtime.h>
#include <cuda_bf16.h>
#include <math.h>
#include <stdint.h>

#define N_NODES  50000
#define N_EDGES  800000
#define N_GRAPHS 2500

// ---------------- scratch (device globals; no allocations allowed) ----------
__device__ __align__(256) float g_q[N_NODES * 256];
__device__ __align__(256) float g_skip[N_NODES * 256];
__device__ __align__(256) float g_h[N_NODES * 128];
__device__ __align__(256) float g_cw[N_EDGES];
__device__ __align__(256) int   g_csrc[N_EDGES];
__device__ __align__(256) int   g_rowptr[N_NODES + 1];
__device__ __align__(256) int   g_wof[N_NODES];
__device__ __align__(256) int   g_bsum[256];
__device__ __align__(256) float g_cnt[N_GRAPHS];
// bf16 operands
__device__ __align__(256) __nv_bfloat16 g_kv[N_NODES * 512];   // [k(256) | v(256)]
__device__ __align__(256) __nv_bfloat16 g_ahi[N_NODES * 256];
__device__ __align__(256) __nv_bfloat16 g_alo[N_NODES * 256];
__device__ __align__(256) __nv_bfloat16 g_whi[262144];
__device__ __align__(256) __nv_bfloat16 g_wlo[262144];

// ================= warp-MMA helpers ==========================================
__device__ __forceinline__ uint32_t smem_u32(const void* p) {
    uint32_t a;
    asm("{ .reg .u64 t; cvta.to.shared.u64 t, %1; cvt.u32.u64 %0, t; }"
        : "=r"(a) : "l"(p));
    return a;
}

__device__ __forceinline__ void ldsm_x4(uint32_t r[4], uint32_t addr) {
    asm volatile("ldmatrix.sync.aligned.m8n8.x4.shared.b16 {%0,%1,%2,%3}, [%4];"
        : "=r"(r[0]), "=r"(r[1]), "=r"(r[2]), "=r"(r[3]) : "r"(addr));
}
__device__ __forceinline__ void ldsm_x4_t(uint32_t r[4], uint32_t addr) {
    asm volatile("ldmatrix.sync.aligned.m8n8.x4.trans.shared.b16 {%0,%1,%2,%3}, [%4];"
        : "=r"(r[0]), "=r"(r[1]), "=r"(r[2]), "=r"(r[3]) : "r"(addr));
}

__device__ __forceinline__ void mma16816(float d[4], const uint32_t a[4],
                                         const uint32_t b[2]) {
    asm volatile(
        "mma.sync.aligned.m16n8k16.row.col.f32.bf16.bf16.f32 "
        "{%0,%1,%2,%3}, {%4,%5,%6,%7}, {%8,%9}, {%0,%1,%2,%3};"
        : "+f"(d[0]), "+f"(d[1]), "+f"(d[2]), "+f"(d[3])
        : "r"(a[0]), "r"(a[1]), "r"(a[2]), "r"(a[3]), "r"(b[0]), "r"(b[1]));
}

__device__ __forceinline__ void cp_async16(uint32_t dst, const void* src, int sz) {
    asm volatile("cp.async.cg.shared.global [%0], [%1], 16, %2;"
        :: "r"(dst), "l"(src), "r"(sz));
}
__device__ __forceinline__ void cp_commit() {
    asm volatile("cp.async.commit_group;" ::: "memory");
}

__device__ __forceinline__ void bf8_to_f(const uint4& u, float* f) {
    float2 p;
    p = __bfloat1622float2(*(const __nv_bfloat162*)&u.x); f[0] = p.x; f[1] = p.y;
    p = __bfloat1622float2(*(const __nv_bfloat162*)&u.y); f[2] = p.x; f[3] = p.y;
    p = __bfloat1622float2(*(const __nv_bfloat162*)&u.z); f[4] = p.x; f[5] = p.y;
    p = __bfloat1622float2(*(const __nv_bfloat162*)&u.w); f[6] = p.x; f[7] = p.y;
}

// =============== fp32 -> bf16 hi/lo split ======================================
__device__ __forceinline__ void split4(float4 v, uint2& hv, uint2& lv) {
    __nv_bfloat16 h0 = __float2bfloat16(v.x);
    __nv_bfloat16 h1 = __float2bfloat16(v.y);
    __nv_bfloat16 h2 = __float2bfloat16(v.z);
    __nv_bfloat16 h3 = __float2bfloat16(v.w);
    __nv_bfloat16 l0 = __float2bfloat16(v.x - __bfloat162float(h0));
    __nv_bfloat16 l1 = __float2bfloat16(v.y - __bfloat162float(h1));
    __nv_bfloat16 l2 = __float2bfloat16(v.z - __bfloat162float(h2));
    __nv_bfloat16 l3 = __float2bfloat16(v.w - __bfloat162float(h3));
    __nv_bfloat162 hp0 = __halves2bfloat162(h0, h1);
    __nv_bfloat162 hp1 = __halves2bfloat162(h2, h3);
    __nv_bfloat162 lp0 = __halves2bfloat162(l0, l1);
    __nv_bfloat162 lp1 = __halves2bfloat162(l2, l3);
    hv = make_uint2(*(uint32_t*)&hp0, *(uint32_t*)&hp1);
    lv = make_uint2(*(uint32_t*)&lp0, *(uint32_t*)&lp1);
}

__global__ __launch_bounds__(256) void cvt_split_kernel(
    const float* __restrict__ src, __nv_bfloat16* __restrict__ hi,
    __nv_bfloat16* __restrict__ lo, int n4)
{
    int i = blockIdx.x * blockDim.x + threadIdx.x;
    if (i >= n4) return;
    uint2 hv, lv;
    split4(((const float4*)src)[i], hv, lv);
    *(uint2*)&hi[i * 4] = hv;
    *(uint2*)&lo[i * 4] = lv;
}

// 4 weight matrices in one launch (grid.y selects matrix)
__global__ __launch_bounds__(256) void cvt_split4_kernel(
    const float* s0, const float* s1, const float* s2, const float* s3,
    __nv_bfloat16* hi, __nv_bfloat16* lo,
    int n4_0, int n4_1, int n4_2, int n4_3)
{
    const float* srcs[4] = {s0, s1, s2, s3};
    int n4s[4]  = {n4_0, n4_1, n4_2, n4_3};
    int offs[4] = {0, 65536, 131072, 196608};
    int m = blockIdx.y;
    int i = blockIdx.x * blockDim.x + threadIdx.x;
    if (i >= n4s[m]) return;
    uint2 hv, lv;
    split4(((const float4*)srcs[m])[i], hv, lv);
    *(uint2*)&hi[offs[m] + i * 4] = hv;
    *(uint2*)&lo[offs[m] + i * 4] = lv;
}

// ================= tensor-core GEMM (cp.async double-buffered) ===============
#define ST_A_HI 0
#define ST_A_LO 10240
#define ST_B_HI 20480
#define ST_B_LO 29184
#define ST_SIZE 37888
#define GSMEM_TOT (2 * ST_SIZE)

template <int N_OUT, int BF16OUT>
__global__ __launch_bounds__(256) void gemm_mma_kernel(
    const __nv_bfloat16* __restrict__ aHi, const __nv_bfloat16* __restrict__ aLo,
    const __nv_bfloat16* __restrict__ wHi, const __nv_bfloat16* __restrict__ wLo,
    const float* __restrict__ bias, float* __restrict__ Yf,
    __nv_bfloat16* __restrict__ Yb, int ldY, int colOff, int K)
{
    extern __shared__ __align__(16) char smem[];
    const uint32_t sb = smem_u32(smem);

    const int t    = threadIdx.x;
    const int lane = t & 31;
    const int wid  = t >> 5;
    const int wm   = wid & 3;
    const int wn   = wid >> 2;
    const int r0   = blockIdx.x * 128;
    const int c0   = blockIdx.y * 128;

    float acc[2][8][4] = {};

    const int aRow = lane & 15;
    const int aCol = (lane >> 4) * 8;
    const int bK   = lane & 15;
    const int bN   = (lane >> 4) * 8;

    const int nChunks = K >> 5;

    auto stage = [&](int c, int buf) {
        uint32_t st = sb + buf * ST_SIZE;
        int kc = c << 5;
#pragma unroll
        for (int it = 0; it < 2; ++it) {
            int fid = t + it * 256;
            int row = fid >> 2;
            int col = (fid & 3) * 8;
            int rg  = r0 + row;
            int ok  = (rg < N_NODES) ? 16 : 0;
            int rc  = (rg < N_NODES) ? rg : (N_NODES - 1);
            size_t gidx = (size_t)rc * K + kc + col;
            uint32_t d = st + row * 80 + col * 2;
            cp_async16(d + ST_A_HI, &aHi[gidx], ok);
            cp_async16(d + ST_A_LO, &aLo[gidx], ok);
        }
#pragma unroll
        for (int it = 0; it < 2; ++it) {
            int fid = t + it * 256;
            int kk  = fid >> 4;
            int n   = (fid & 15) * 8;
            size_t gidx = (size_t)(kc + kk) * N_OUT + c0 + n;
            uint32_t d = st + kk * 272 + n * 2;
            cp_async16(d + ST_B_HI, &wHi[gidx], 16);
            cp_async16(d + ST_B_LO, &wLo[gidx], 16);
        }
        cp_commit();
    };

    stage(0, 0);
    for (int c = 0; c < nChunks; ++c) {
        bool more = (c + 1 < nChunks);
        if (more) stage(c + 1, (c + 1) & 1);
        if (more) asm volatile("cp.async.wait_group 1;" ::: "memory");
        else      asm volatile("cp.async.wait_group 0;" ::: "memory");
        __syncthreads();

        uint32_t st = sb + (c & 1) * ST_SIZE;
#pragma unroll
        for (int ks = 0; ks < 2; ++ks) {
            uint32_t aH[2][4], aL[2][4], bf[4][4];
#pragma unroll
            for (int mi = 0; mi < 2; ++mi) {
                uint32_t ar = st + (wm * 32 + mi * 16 + aRow) * 80 + (ks * 16 + aCol) * 2;
                ldsm_x4(aH[mi], ar + ST_A_HI);
                ldsm_x4(aL[mi], ar + ST_A_LO);
            }
#pragma unroll
            for (int pi = 0; pi < 4; ++pi)
                ldsm_x4_t(bf[pi], st + ST_B_HI + (ks * 16 + bK) * 272
                                     + (wn * 64 + pi * 16 + bN) * 2);
#pragma unroll
            for (int mi = 0; mi < 2; ++mi)
#pragma unroll
                for (int pi = 0; pi < 4; ++pi) {
                    mma16816(acc[mi][2 * pi],     aH[mi], &bf[pi][0]);
                    mma16816(acc[mi][2 * pi + 1], aH[mi], &bf[pi][2]);
                }
#pragma unroll
            for (int mi = 0; mi < 2; ++mi)
#pragma unroll
                for (int pi = 0; pi < 4; ++pi) {
                    mma16816(acc[mi][2 * pi],     aL[mi], &bf[pi][0]);
                    mma16816(acc[mi][2 * pi + 1], aL[mi], &bf[pi][2]);
                }
#pragma unroll
            for (int pi = 0; pi < 4; ++pi)
                ldsm_x4_t(bf[pi], st + ST_B_LO + (ks * 16 + bK) * 272
                                     + (wn * 64 + pi * 16 + bN) * 2);
#pragma unroll
            for (int mi = 0; mi < 2; ++mi)
#pragma unroll
                for (int pi = 0; pi < 4; ++pi) {
                    mma16816(acc[mi][2 * pi],     aH[mi], &bf[pi][0]);
                    mma16816(acc[mi][2 * pi + 1], aH[mi], &bf[pi][2]);
                }
        }
        __syncthreads();
    }

#pragma unroll
    for (int mi = 0; mi < 2; ++mi) {
        int rA = r0 + wm * 32 + mi * 16 + (lane >> 2);
        int rB = rA + 8;
#pragma unroll
        for (int ni = 0; ni < 8; ++ni) {
            int cc  = c0 + wn * 64 + ni * 8 + (lane & 3) * 2;
            float2 bv = *(const float2*)&bias[cc];
            float x0 = acc[mi][ni][0] + bv.x, y0 = acc[mi][ni][1] + bv.y;
            float x1 = acc[mi][ni][2] + bv.x, y1 = acc[mi][ni][3] + bv.y;
            int col = colOff + cc;
            if (BF16OUT) {
                if (rA < N_NODES)
                    *(__nv_bfloat162*)&Yb[(size_t)rA * ldY + col] =
                        __floats2bfloat162_rn(x0, y0);
                if (rB < N_NODES)
                    *(__nv_bfloat162*)&Yb[(size_t)rB * ldY + col] =
                        __floats2bfloat162_rn(x1, y1);
            } else {
                if (rA < N_NODES)
                    *(float2*)&Yf[(size_t)rA * ldY + col] = make_float2(x0, y0);
                if (rB < N_NODES)
                    *(float2*)&Yf[(size_t)rB * ldY + col] = make_float2(x1, y1);
            }
        }
    }
}

// =============== CSR build ====================================================
__global__ __launch_bounds__(256) void zero_wof_kernel() {
    int i = blockIdx.x * blockDim.x + threadIdx.x;
    if (i < N_NODES) g_wof[i] = 0;
}

__global__ __launch_bounds__(256) void hist_kernel(const int* __restrict__ ei) {
    int e = blockIdx.x * blockDim.x + threadIdx.x;
    if (e < N_EDGES) atomicAdd(&g_wof[ei[N_EDGES + e]], 1);
}

__global__ __launch_bounds__(256) void scan1_kernel() {
    __shared__ int sb[2][256];
    int t = threadIdx.x;
    int i = blockIdx.x * 256 + t;
    int v = (i < N_NODES) ? g_wof[i] : 0;
    int pin = 0;
    sb[0][t] = v;
    __syncthreads();
#pragma unroll
    for (int off = 1; off < 256; off <<= 1) {
        int x = sb[pin][t];
        if (t >= off) x += sb[pin][t - off];
        sb[pin ^ 1][t] = x;
        __syncthreads();
        pin ^= 1;
    }
    int incl = sb[pin][t];
    if (i < N_NODES) g_rowptr[i] = incl - v;        // local exclusive
    if (t == 255) g_bsum[blockIdx.x] = incl;        // block total
}

// scan3 computes its own block-offset prefix (folds old scan2)
__global__ __launch_bounds__(256) void scan3_kernel() {
    __shared__ int sp[8];
    int t = threadIdx.x;
    int bid = blockIdx.x;
    int part = 0;
    for (int j = t; j < bid; j += 256) part += g_bsum[j];
#pragma unroll
    for (int o = 16; o; o >>= 1) part += __shfl_xor_sync(0xffffffffu, part, o);
    if ((t & 31) == 0) sp[t >> 5] = part;
    __syncthreads();
    if (t == 0) {
        int s = 0;
#pragma unroll
        for (int w = 0; w < 8; ++w) s += sp[w];
        sp[0] = s;
        if (bid == 0) g_rowptr[N_NODES] = N_EDGES;
    }
    __syncthreads();
    int off = sp[0];
    int i = bid * 256 + t;
    if (i < N_NODES) {
        int r = g_rowptr[i] + off;
        g_rowptr[i] = r;
        g_wof[i]    = r;
    }
}

__global__ __launch_bounds__(256) void csr_scatter_kernel(
    const int* __restrict__ ei, const float* __restrict__ ea)
{
    int e = blockIdx.x * blockDim.x + threadIdx.x;
    if (e >= N_EDGES) return;
    int src = ei[e];
    int dst = ei[N_EDGES + e];
    int pos = atomicAdd(&g_wof[dst], 1);
    g_csrc[pos] = src;
    g_cw[pos]   = ea[e];
}

// =============== per-node attention: bf16 kv gather, half-warp heads ========
// unroll-2 (validated in R8); min 3 CTAs/SM for higher MLP
template <int CONCAT>
__global__ __launch_bounds__(256, 3) void node_attn_kernel(
    const float* __restrict__ q, const __nv_bfloat16* __restrict__ kv,
    const float* __restrict__ skip, const float* __restrict__ We,
    float* __restrict__ outf, __nv_bfloat16* __restrict__ ohi,
    __nv_bfloat16* __restrict__ olo)
{
    int n = blockIdx.x * 8 + (threadIdx.x >> 5);
    if (n >= N_NODES) return;
    int lane = threadIdx.x & 31;
    int beg = g_rowptr[n], end = g_rowptr[n + 1];

    const float scale = 0.08838834764831845f;   // 1/sqrt(128)

    float qv[8], ev[8];
    {
        const float* qr = q + (size_t)n * 256 + lane * 8;
        *(float4*)&qv[0] = *(const float4*)(qr);
        *(float4*)&qv[4] = *(const float4*)(qr + 4);
        *(float4*)&ev[0] = *(const float4*)(We + lane * 8);
        *(float4*)&ev[4] = *(const float4*)(We + lane * 8 + 4);
    }
    float qe = 0.f;
#pragma unroll
    for (int i = 0; i < 8; ++i) qe = fmaf(qv[i], ev[i], qe);
#pragma unroll
    for (int o = 8; o; o >>= 1) qe += __shfl_xor_sync(0xffffffffu, qe, o);
    qe *= scale;

    float d = 0.f, cw = 0.f;
    float a[8] = {};

    int p = beg;
    for (; p + 1 < end; p += 2) {
        int  sa = g_csrc[p],  sb = g_csrc[p + 1];
        float wa = g_cw[p],   wb = g_cw[p + 1];
        const uint4* ra = (const uint4*)(kv + (size_t)sa * 512);
        const uint4* rb = (const uint4*)(kv + (size_t)sb * 512);
        uint4 kua = ra[lane], kub = rb[lane];
        uint4 vua = ra[32 + lane], vub = rb[32 + lane];

        float kfa[8], kfb[8];
        bf8_to_f(kua, kfa);
        bf8_to_f(kub, kfb);
        float ta = 0.f, tb = 0.f;
#pragma unroll
        for (int i = 0; i < 8; ++i) {
            ta = fmaf(qv[i], kfa[i], ta);
            tb = fmaf(qv[i], kfb[i], tb);
        }
#pragma unroll
        for (int o = 8; o; o >>= 1) {
            ta += __shfl_xor_sync(0xffffffffu, ta, o);
            tb += __shfl_xor_sync(0xffffffffu, tb, o);
        }
        float xa = __expf(fmaf(wa, qe, ta * scale));
        float xb = __expf(fmaf(wb, qe, tb * scale));
        d  += xa + xb;
        cw += xa * wa + xb * wb;
        float vfa[8], vfb[8];
        bf8_to_f(vua, vfa);
        bf8_to_f(vub, vfb);
#pragma unroll
        for (int i = 0; i < 8; ++i)
            a[i] += xa * vfa[i] + xb * vfb[i];
    }
    for (; p < end; ++p) {
        int s = g_csrc[p];
        float w = g_cw[p];
        const uint4* r = (const uint4*)(kv + (size_t)s * 512);
        uint4 ku = r[lane], vu = r[32 + lane];
        float kf[8];
        bf8_to_f(ku, kf);
        float t = 0.f;
#pragma unroll
        for (int i = 0; i < 8; ++i) t = fmaf(qv[i], kf[i], t);
#pragma unroll
        for (int o = 8; o; o >>= 1) t += __shfl_xor_sync(0xffffffffu, t, o);
        float x = __expf(fmaf(w, qe, t * scale));
        d += x; cw += x * w;
        float vf[8];
        bf8_to_f(vu, vf);
#pragma unroll
        for (int i = 0; i < 8; ++i) a[i] += x * vf[i];
    }

    float r = d > 0.f ? 1.f / d : 0.f;
    float o8[8];
#pragma unroll
    for (int i = 0; i < 8; ++i) o8[i] = (a[i] + cw * ev[i]) * r;

    if (CONCAT) {
        float sk[8];
        const float* sr = skip + (size_t)n * 256 + lane * 8;
        *(float4*)&sk[0] = *(const float4*)(sr);
        *(float4*)&sk[4] = *(const float4*)(sr + 4);
        __align__(16) __nv_bfloat16 hb[8], lb[8];
#pragma unroll
        for (int i = 0; i < 8; ++i) {
            float o = fmaxf(o8[i] + sk[i], 0.f);
            hb[i] = __float2bfloat16(o);
            lb[i] = __float2bfloat16(o - __bfloat162float(hb[i]));
        }
        *(uint4*)&ohi[(size_t)n * 256 + lane * 8] = *(uint4*)hb;
        *(uint4*)&olo[(size_t)n * 256 + lane * 8] = *(uint4*)lb;
    } else {
        float m[8];
#pragma unroll
        for (int i = 0; i < 8; ++i) {
            float other = __shfl_xor_sync(0xffffffffu, o8[i], 16);
            m[i] = 0.5f * (o8[i] + other);
        }
        if (lane < 16) {
            const float* sr = skip + (size_t)n * 128 + lane * 8;
            float4 s0 = *(const float4*)(sr);
            float4 s1 = *(const float4*)(sr + 4);
            float4 w0 = make_float4(m[0] + s0.x, m[1] + s0.y, m[2] + s0.z, m[3] + s0.w);
            float4 w1 = make_float4(m[4] + s1.x, m[5] + s1.y, m[6] + s1.z, m[7] + s1.w);
            *(float4*)&outf[(size_t)n * 128 + lane * 8]     = w0;
            *(float4*)&outf[(size_t)n * 128 + lane * 8 + 4] = w1;
        }
    }
}

// =============== pooling =======================================================
__global__ __launch_bounds__(256) void pool_zero_kernel(float* __restrict__ out) {
    int i = blockIdx.x * blockDim.x + threadIdx.x;
    if (i < N_GRAPHS * 128) out[i] = 0.f;
    if (i < N_GRAPHS) g_cnt[i] = 0.f;
}

__global__ __launch_bounds__(128) void pool_sum_kernel(
    const int* __restrict__ batch, const float* __restrict__ h,
    float* __restrict__ out)
{
    int n = blockIdx.x;
    int c = threadIdx.x;
    int g = batch[n];
    atomicAdd(&out[(size_t)g * 128 + c], h[(size_t)n * 128 + c]);
    if (c == 0) atomicAdd(&g_cnt[g], 1.f);
}

__global__ __launch_bounds__(256) void pool_div_kernel(float* __restrict__ out) {
    int i = blockIdx.x * blockDim.x + threadIdx.x;
    if (i >= N_GRAPHS * 128) return;
    out[i] /= fmaxf(g_cnt[i >> 7], 1.f);
}

// =============== launch =========================================================
extern "C" void kernel_launch(void* const* d_in, const int* in_sizes, int n_in,
                              void* d_out, int out_size)
{
    const float* x     = (const float*)d_in[0];
    const int*   ei    = (const int*)d_in[1];
    const int*   batch = (const int*)d_in[2];
    const float* ea    = (const float*)d_in[3];
    const float* Wq1 = (const float*)d_in[4];
    const float* bq1 = (const float*)d_in[5];
    const float* Wk1 = (const float*)d_in[6];
    const float* bk1 = (const float*)d_in[7];
    const float* Wv1 = (const float*)d_in[8];
    const float* bv1 = (const float*)d_in[9];
    const float* We1 = (const float*)d_in[10];
    const float* Ws1 = (const float*)d_in[11];
    const float* bs1 = (const float*)d_in[12];
    const float* Wq2 = (const float*)d_in[13];
    const float* bq2 = (const float*)d_in[14];
    const float* Wk2 = (const float*)d_in[15];
    const float* bk2 = (const float*)d_in[16];
    const float* Wv2 = (const float*)d_in[17];
    const float* bv2 = (const float*)d_in[18];
    const float* We2 = (const float*)d_in[19];
    const float* Ws2 = (const float*)d_in[20];
    const float* bs2 = (const float*)d_in[21];
    float* out = (float*)d_out;

    float *pq, *pskip, *ph;
    __nv_bfloat16 *pkv, *pahi, *palo, *pwhi, *pwlo;
    cudaGetSymbolAddress((void**)&pq,    g_q);
    cudaGetSymbolAddress((void**)&pskip, g_skip);
    cudaGetSymbolAddress((void**)&ph,    g_h);
    cudaGetSymbolAddress((void**)&pkv,   g_kv);
    cudaGetSymbolAddress((void**)&pahi,  g_ahi);
    cudaGetSymbolAddress((void**)&palo,  g_alo);
    cudaGetSymbolAddress((void**)&pwhi,  g_whi);
    cudaGetSymbolAddress((void**)&pwlo,  g_wlo);

    cudaFuncSetAttribute(gemm_mma_kernel<256, 0>,
                         cudaFuncAttributeMaxDynamicSharedMemorySize, GSMEM_TOT);
    cudaFuncSetAttribute(gemm_mma_kernel<256, 1>,
                         cudaFuncAttributeMaxDynamicSharedMemorySize, GSMEM_TOT);
    cudaFuncSetAttribute(gemm_mma_kernel<128, 0>,
                         cudaFuncAttributeMaxDynamicSharedMemorySize, GSMEM_TOT);

    const int RT  = (N_NODES + 127) / 128;            // 391 row tiles
    dim3 gm2(RT, 2), gm1(RT, 1);

    const int EB  = (N_EDGES + 255) / 256;
    const int NB  = (N_NODES + 255) / 256;            // 196
    const int NWB = (N_NODES + 7) / 8;
    const int PZ  = (N_GRAPHS * 128 + 255) / 256;

    // ---- CSR build ----
    zero_wof_kernel<<<NB, 256>>>();
    hist_kernel<<<EB, 256>>>(ei);
    scan1_kernel<<<NB, 256>>>();
    scan3_kernel<<<NB, 256>>>();
    csr_scatter_kernel<<<EB, 256>>>(ei, ea);

    // ---- layer 1 (in=128, concat heads) ----
    cvt_split_kernel<<<(N_NODES * 128 / 4 + 255) / 256, 256>>>(x, pahi, palo, N_NODES * 128 / 4);
    cvt_split4_kernel<<<dim3(8192 / 256, 4), 256>>>(Wq1, Wk1, Wv1, Ws1, pwhi, pwlo,
                                                    8192, 8192, 8192, 8192);
    gemm_mma_kernel<256, 0><<<gm2, 256, GSMEM_TOT>>>(pahi, palo, pwhi,          pwlo,          bq1, pq,      nullptr, 256, 0,   128);
    gemm_mma_kernel<256, 1><<<gm2, 256, GSMEM_TOT>>>(pahi, palo, pwhi + 65536,  pwlo + 65536,  bk1, nullptr, pkv,     512, 0,   128);
    gemm_mma_kernel<256, 1><<<gm2, 256, GSMEM_TOT>>>(pahi, palo, pwhi + 131072, pwlo + 131072, bv1, nullptr, pkv,     512, 256, 128);
    gemm_mma_kernel<256, 0><<<gm2, 256, GSMEM_TOT>>>(pahi, palo, pwhi + 196608, pwlo + 196608, bs1, pskip,   nullptr, 256, 0,   128);
    node_attn_kernel<1><<<NWB, 256>>>(pq, pkv, pskip, We1, nullptr, pahi, palo);

    // ---- layer 2 (in=256, mean heads); A = hi/lo written by attn<1> ----
    cvt_split4_kernel<<<dim3(16384 / 256, 4), 256>>>(Wq2, Wk2, Wv2, Ws2, pwhi, pwlo,
                                                     16384, 16384, 16384, 8192);
    gemm_mma_kernel<256, 0><<<gm2, 256, GSMEM_TOT>>>(pahi, palo, pwhi,          pwlo,          bq2, pq,      nullptr, 256, 0,   256);
    gemm_mma_kernel<256, 1><<<gm2, 256, GSMEM_TOT>>>(pahi, palo, pwhi + 65536,  pwlo + 65536,  bk2, nullptr, pkv,     512, 0,   256);
    gemm_mma_kernel<256, 1><<<gm2, 256, GSMEM_TOT>>>(pahi, palo, pwhi + 131072, pwlo + 131072, bv2, nullptr, pkv,     512, 256, 256);
    gemm_mma_kernel<128, 0><<<gm1, 256, GSMEM_TOT>>>(pahi, palo, pwhi + 196608, pwlo + 196608, bs2, pskip,   nullptr, 128, 0,   256);
    node_attn_kernel<0><<<NWB, 256>>>(pq, pkv, pskip, We2, ph, nullptr, nullptr);

    // ---- global mean pool ----
    pool_zero_kernel<<<PZ, 256>>>(out);
    pool_sum_kernel<<<N_NODES, 128>>>(batch, ph, out);
    pool_div_kernel<<<PZ, 256>>>(out);
}

// round 12
// speedup vs baseline: 1.2902x; 1.1219x over previous
#include <cuda_runtime.h>
#include <cuda_bf16.h>
#include <math.h>
#include <stdint.h>

#define N_NODES  50000
#define N_EDGES  800000
#define N_GRAPHS 2500

// ---------------- scratch (device globals; no allocations allowed) ----------
__device__ __align__(256) float g_q[N_NODES * 256];
__device__ __align__(256) float g_skip[N_NODES * 256];
__device__ __align__(256) float g_cw[N_EDGES];
__device__ __align__(256) int   g_csrc[N_EDGES];
__device__ __align__(256) int   g_rowptr[N_NODES + 1];
__device__ __align__(256) int   g_wof[N_NODES];
__device__ __align__(256) int   g_bsum[256];
__device__ __align__(256) float g_cnt[N_GRAPHS];
// bf16 operands
__device__ __align__(256) __nv_bfloat16 g_kv[N_NODES * 512];   // [k(256) | v(256)]
__device__ __align__(256) __nv_bfloat16 g_ahi[N_NODES * 256];
__device__ __align__(256) __nv_bfloat16 g_alo[N_NODES * 256];
__device__ __align__(256) __nv_bfloat16 g_whi[262144];
__device__ __align__(256) __nv_bfloat16 g_wlo[262144];

// ================= warp-MMA helpers ==========================================
__device__ __forceinline__ uint32_t smem_u32(const void* p) {
    uint32_t a;
    asm("{ .reg .u64 t; cvta.to.shared.u64 t, %1; cvt.u32.u64 %0, t; }"
        : "=r"(a) : "l"(p));
    return a;
}

__device__ __forceinline__ void ldsm_x4(uint32_t r[4], uint32_t addr) {
    asm volatile("ldmatrix.sync.aligned.m8n8.x4.shared.b16 {%0,%1,%2,%3}, [%4];"
        : "=r"(r[0]), "=r"(r[1]), "=r"(r[2]), "=r"(r[3]) : "r"(addr));
}
__device__ __forceinline__ void ldsm_x4_t(uint32_t r[4], uint32_t addr) {
    asm volatile("ldmatrix.sync.aligned.m8n8.x4.trans.shared.b16 {%0,%1,%2,%3}, [%4];"
        : "=r"(r[0]), "=r"(r[1]), "=r"(r[2]), "=r"(r[3]) : "r"(addr));
}

__device__ __forceinline__ void mma16816(float d[4], const uint32_t a[4],
                                         const uint32_t b[2]) {
    asm volatile(
        "mma.sync.aligned.m16n8k16.row.col.f32.bf16.bf16.f32 "
        "{%0,%1,%2,%3}, {%4,%5,%6,%7}, {%8,%9}, {%0,%1,%2,%3};"
        : "+f"(d[0]), "+f"(d[1]), "+f"(d[2]), "+f"(d[3])
        : "r"(a[0]), "r"(a[1]), "r"(a[2]), "r"(a[3]), "r"(b[0]), "r"(b[1]));
}

__device__ __forceinline__ void cp_async16(uint32_t dst, const void* src, int sz) {
    asm volatile("cp.async.cg.shared.global [%0], [%1], 16, %2;"
        :: "r"(dst), "l"(src), "r"(sz));
}
__device__ __forceinline__ void cp_commit() {
    asm volatile("cp.async.commit_group;" ::: "memory");
}

__device__ __forceinline__ void bf8_to_f(const uint4& u, float* f) {
    float2 p;
    p = __bfloat1622float2(*(const __nv_bfloat162*)&u.x); f[0] = p.x; f[1] = p.y;
    p = __bfloat1622float2(*(const __nv_bfloat162*)&u.y); f[2] = p.x; f[3] = p.y;
    p = __bfloat1622float2(*(const __nv_bfloat162*)&u.z); f[4] = p.x; f[5] = p.y;
    p = __bfloat1622float2(*(const __nv_bfloat162*)&u.w); f[6] = p.x; f[7] = p.y;
}

// =============== fp32 -> bf16 hi/lo split ======================================
__device__ __forceinline__ void split4(float4 v, uint2& hv, uint2& lv) {
    __nv_bfloat16 h0 = __float2bfloat16(v.x);
    __nv_bfloat16 h1 = __float2bfloat16(v.y);
    __nv_bfloat16 h2 = __float2bfloat16(v.z);
    __nv_bfloat16 h3 = __float2bfloat16(v.w);
    __nv_bfloat16 l0 = __float2bfloat16(v.x - __bfloat162float(h0));
    __nv_bfloat16 l1 = __float2bfloat16(v.y - __bfloat162float(h1));
    __nv_bfloat16 l2 = __float2bfloat16(v.z - __bfloat162float(h2));
    __nv_bfloat16 l3 = __float2bfloat16(v.w - __bfloat162float(h3));
    __nv_bfloat162 hp0 = __halves2bfloat162(h0, h1);
    __nv_bfloat162 hp1 = __halves2bfloat162(h2, h3);
    __nv_bfloat162 lp0 = __halves2bfloat162(l0, l1);
    __nv_bfloat162 lp1 = __halves2bfloat162(l2, l3);
    hv = make_uint2(*(uint32_t*)&hp0, *(uint32_t*)&hp1);
    lv = make_uint2(*(uint32_t*)&lp0, *(uint32_t*)&lp1);
}

__global__ __launch_bounds__(256) void cvt_split_kernel(
    const float* __restrict__ src, __nv_bfloat16* __restrict__ hi,
    __nv_bfloat16* __restrict__ lo, int n4)
{
    int i = blockIdx.x * blockDim.x + threadIdx.x;
    if (i >= n4) return;
    uint2 hv, lv;
    split4(((const float4*)src)[i], hv, lv);
    *(uint2*)&hi[i * 4] = hv;
    *(uint2*)&lo[i * 4] = lv;
}

// 4 weight matrices in one launch (grid.y selects matrix)
__global__ __launch_bounds__(256) void cvt_split4_kernel(
    const float* s0, const float* s1, const float* s2, const float* s3,
    __nv_bfloat16* hi, __nv_bfloat16* lo,
    int n4_0, int n4_1, int n4_2, int n4_3)
{
    const float* srcs[4] = {s0, s1, s2, s3};
    int n4s[4]  = {n4_0, n4_1, n4_2, n4_3};
    int offs[4] = {0, 65536, 131072, 196608};
    int m = blockIdx.y;
    int i = blockIdx.x * blockDim.x + threadIdx.x;
    if (i >= n4s[m]) return;
    uint2 hv, lv;
    split4(((const float4*)srcs[m])[i], hv, lv);
    *(uint2*)&hi[offs[m] + i * 4] = hv;
    *(uint2*)&lo[offs[m] + i * 4] = lv;
}

// ================= tensor-core GEMM (cp.async double-buffered) ===============
#define ST_A_HI 0
#define ST_A_LO 10240
#define ST_B_HI 20480
#define ST_B_LO 29184
#define ST_SIZE 37888
#define GSMEM_TOT (2 * ST_SIZE)

template <int NW>  // NW: W row width
__device__ __forceinline__ void gemm_core(
    const __nv_bfloat16* __restrict__ aHi, const __nv_bfloat16* __restrict__ aLo,
    const __nv_bfloat16* __restrict__ wHi, const __nv_bfloat16* __restrict__ wLo,
    int K, int r0, int c0, uint32_t sb, float acc[2][8][4])
{
    const int t    = threadIdx.x;
    const int lane = t & 31;
    const int wid  = t >> 5;
    const int wm   = wid & 3;
    const int wn   = wid >> 2;

    const int aRow = lane & 15;
    const int aCol = (lane >> 4) * 8;
    const int bK   = lane & 15;
    const int bN   = (lane >> 4) * 8;

    const int nChunks = K >> 5;

    auto stage = [&](int c, int buf) {
        uint32_t st = sb + buf * ST_SIZE;
        int kc = c << 5;
#pragma unroll
        for (int it = 0; it < 2; ++it) {
            int fid = t + it * 256;
            int row = fid >> 2;
            int col = (fid & 3) * 8;
            int rg  = r0 + row;
            int ok  = (rg < N_NODES) ? 16 : 0;
            int rc  = (rg < N_NODES) ? rg : (N_NODES - 1);
            size_t gidx = (size_t)rc * K + kc + col;
            uint32_t d = st + row * 80 + col * 2;
            cp_async16(d + ST_A_HI, &aHi[gidx], ok);
            cp_async16(d + ST_A_LO, &aLo[gidx], ok);
        }
#pragma unroll
        for (int it = 0; it < 2; ++it) {
            int fid = t + it * 256;
            int kk  = fid >> 4;
            int n   = (fid & 15) * 8;
            size_t gidx = (size_t)(kc + kk) * NW + c0 + n;
            uint32_t d = st + kk * 272 + n * 2;
            cp_async16(d + ST_B_HI, &wHi[gidx], 16);
            cp_async16(d + ST_B_LO, &wLo[gidx], 16);
        }
        cp_commit();
    };

    stage(0, 0);
    for (int c = 0; c < nChunks; ++c) {
        bool more = (c + 1 < nChunks);
        if (more) stage(c + 1, (c + 1) & 1);
        if (more) asm volatile("cp.async.wait_group 1;" ::: "memory");
        else      asm volatile("cp.async.wait_group 0;" ::: "memory");
        __syncthreads();

        uint32_t st = sb + (c & 1) * ST_SIZE;
#pragma unroll
        for (int ks = 0; ks < 2; ++ks) {
            uint32_t aH[2][4], aL[2][4], bf[4][4];
#pragma unroll
            for (int mi = 0; mi < 2; ++mi) {
                uint32_t ar = st + (wm * 32 + mi * 16 + aRow) * 80 + (ks * 16 + aCol) * 2;
                ldsm_x4(aH[mi], ar + ST_A_HI);
                ldsm_x4(aL[mi], ar + ST_A_LO);
            }
#pragma unroll
            for (int pi = 0; pi < 4; ++pi)
                ldsm_x4_t(bf[pi], st + ST_B_HI + (ks * 16 + bK) * 272
                                     + (wn * 64 + pi * 16 + bN) * 2);
#pragma unroll
            for (int mi = 0; mi < 2; ++mi)
#pragma unroll
                for (int pi = 0; pi < 4; ++pi) {
                    mma16816(acc[mi][2 * pi],     aH[mi], &bf[pi][0]);
                    mma16816(acc[mi][2 * pi + 1], aH[mi], &bf[pi][2]);
                }
#pragma unroll
            for (int mi = 0; mi < 2; ++mi)
#pragma unroll
                for (int pi = 0; pi < 4; ++pi) {
                    mma16816(acc[mi][2 * pi],     aL[mi], &bf[pi][0]);
                    mma16816(acc[mi][2 * pi + 1], aL[mi], &bf[pi][2]);
                }
#pragma unroll
            for (int pi = 0; pi < 4; ++pi)
                ldsm_x4_t(bf[pi], st + ST_B_LO + (ks * 16 + bK) * 272
                                     + (wn * 64 + pi * 16 + bN) * 2);
#pragma unroll
            for (int mi = 0; mi < 2; ++mi)
#pragma unroll
                for (int pi = 0; pi < 4; ++pi) {
                    mma16816(acc[mi][2 * pi],     aH[mi], &bf[pi][0]);
                    mma16816(acc[mi][2 * pi + 1], aH[mi], &bf[pi][2]);
                }
        }
        __syncthreads();
    }
}

// ---- merged q/k/v(/skip) GEMM: blockIdx.y = gi*2 + col_tile -----------------
// gi: 0=q (fp32, ld256), 1=k (bf16 kv col 0), 2=v (bf16 kv col 256),
//     3=skip (fp32, ld256; layer1 only)
__global__ __launch_bounds__(256) void gemm_qkvs_kernel(
    const __nv_bfloat16* __restrict__ aHi, const __nv_bfloat16* __restrict__ aLo,
    const float* __restrict__ b0, const float* __restrict__ b1,
    const float* __restrict__ b2, const float* __restrict__ b3,
    float* __restrict__ Yq, __nv_bfloat16* __restrict__ Ykv,
    float* __restrict__ Ys, int K)
{
    extern __shared__ __align__(16) char smem[];
    const uint32_t sb = smem_u32(smem);

    const int gi = blockIdx.y >> 1;
    const int c0 = (blockIdx.y & 1) * 128;
    const int r0 = blockIdx.x * 128;

    const __nv_bfloat16* wHi = g_whi + gi * 65536;
    const __nv_bfloat16* wLo = g_wlo + gi * 65536;
    const float* bias = (gi == 0) ? b0 : (gi == 1) ? b1 : (gi == 2) ? b2 : b3;

    float acc[2][8][4] = {};
    gemm_core<256>(aHi, aLo, wHi, wLo, K, r0, c0, sb, acc);

    const int lane = threadIdx.x & 31;
    const int wid  = threadIdx.x >> 5;
    const int wm   = wid & 3;
    const int wn   = wid >> 2;

#pragma unroll
    for (int mi = 0; mi < 2; ++mi) {
        int rA = r0 + wm * 32 + mi * 16 + (lane >> 2);
        int rB = rA + 8;
#pragma unroll
        for (int ni = 0; ni < 8; ++ni) {
            int cc  = c0 + wn * 64 + ni * 8 + (lane & 3) * 2;
            float2 bv = *(const float2*)&bias[cc];
            float x0 = acc[mi][ni][0] + bv.x, y0 = acc[mi][ni][1] + bv.y;
            float x1 = acc[mi][ni][2] + bv.x, y1 = acc[mi][ni][3] + bv.y;
            if (gi == 1 || gi == 2) {
                int kcol = cc + ((gi == 2) ? 256 : 0);
                if (rA < N_NODES)
                    *(__nv_bfloat162*)&Ykv[(size_t)rA * 512 + kcol] =
                        __floats2bfloat162_rn(x0, y0);
                if (rB < N_NODES)
                    *(__nv_bfloat162*)&Ykv[(size_t)rB * 512 + kcol] =
                        __floats2bfloat162_rn(x1, y1);
            } else {
                float* Y = (gi == 0) ? Yq : Ys;
                if (rA < N_NODES)
                    *(float2*)&Y[(size_t)rA * 256 + cc] = make_float2(x0, y0);
                if (rB < N_NODES)
                    *(float2*)&Y[(size_t)rB * 256 + cc] = make_float2(x1, y1);
            }
        }
    }
}

// ---- standalone skip GEMM for layer 2 (W width 128) --------------------------
__global__ __launch_bounds__(256) void gemm_skip2_kernel(
    const __nv_bfloat16* __restrict__ aHi, const __nv_bfloat16* __restrict__ aLo,
    const float* __restrict__ bias, float* __restrict__ Ys, int K)
{
    extern __shared__ __align__(16) char smem[];
    const uint32_t sb = smem_u32(smem);
    const int r0 = blockIdx.x * 128;

    float acc[2][8][4] = {};
    gemm_core<128>(aHi, aLo, g_whi + 196608, g_wlo + 196608, K, r0, 0, sb, acc);

    const int lane = threadIdx.x & 31;
    const int wid  = threadIdx.x >> 5;
    const int wm   = wid & 3;
    const int wn   = wid >> 2;

#pragma unroll
    for (int mi = 0; mi < 2; ++mi) {
        int rA = r0 + wm * 32 + mi * 16 + (lane >> 2);
        int rB = rA + 8;
#pragma unroll
        for (int ni = 0; ni < 8; ++ni) {
            int cc  = wn * 64 + ni * 8 + (lane & 3) * 2;
            float2 bv = *(const float2*)&bias[cc];
            if (rA < N_NODES)
                *(float2*)&Ys[(size_t)rA * 128 + cc] =
                    make_float2(acc[mi][ni][0] + bv.x, acc[mi][ni][1] + bv.y);
            if (rB < N_NODES)
                *(float2*)&Ys[(size_t)rB * 128 + cc] =
                    make_float2(acc[mi][ni][2] + bv.x, acc[mi][ni][3] + bv.y);
        }
    }
}

// =============== init + CSR build =============================================
__global__ __launch_bounds__(256) void init_zero_kernel(float* __restrict__ out) {
    int i = blockIdx.x * blockDim.x + threadIdx.x;
    if (i < N_GRAPHS * 128) out[i] = 0.f;
    if (i < N_NODES) g_wof[i] = 0;
    if (i < N_GRAPHS) g_cnt[i] = 0.f;
}

__global__ __launch_bounds__(256) void hist_kernel(const int* __restrict__ ei) {
    int e = blockIdx.x * blockDim.x + threadIdx.x;
    if (e < N_EDGES) atomicAdd(&g_wof[ei[N_EDGES + e]], 1);
}

__global__ __launch_bounds__(256) void scan1_kernel() {
    __shared__ int sb[2][256];
    int t = threadIdx.x;
    int i = blockIdx.x * 256 + t;
    int v = (i < N_NODES) ? g_wof[i] : 0;
    int pin = 0;
    sb[0][t] = v;
    __syncthreads();
#pragma unroll
    for (int off = 1; off < 256; off <<= 1) {
        int x = sb[pin][t];
        if (t >= off) x += sb[pin][t - off];
        sb[pin ^ 1][t] = x;
        __syncthreads();
        pin ^= 1;
    }
    int incl = sb[pin][t];
    if (i < N_NODES) g_rowptr[i] = incl - v;
    if (t == 255) g_bsum[blockIdx.x] = incl;
}

__global__ __launch_bounds__(256) void scan3_kernel() {
    __shared__ int sp[8];
    int t = threadIdx.x;
    int bid = blockIdx.x;
    int part = 0;
    for (int j = t; j < bid; j += 256) part += g_bsum[j];
#pragma unroll
    for (int o = 16; o; o >>= 1) part += __shfl_xor_sync(0xffffffffu, part, o);
    if ((t & 31) == 0) sp[t >> 5] = part;
    __syncthreads();
    if (t == 0) {
        int s = 0;
#pragma unroll
        for (int w = 0; w < 8; ++w) s += sp[w];
        sp[0] = s;
        if (bid == 0) g_rowptr[N_NODES] = N_EDGES;
    }
    __syncthreads();
    int off = sp[0];
    int i = bid * 256 + t;
    if (i < N_NODES) {
        int r = g_rowptr[i] + off;
        g_rowptr[i] = r;
        g_wof[i]    = r;
    }
}

__global__ __launch_bounds__(256) void csr_scatter_kernel(
    const int* __restrict__ ei, const float* __restrict__ ea)
{
    int e = blockIdx.x * blockDim.x + threadIdx.x;
    if (e >= N_EDGES) return;
    int src = ei[e];
    int dst = ei[N_EDGES + e];
    int pos = atomicAdd(&g_wof[dst], 1);
    g_csrc[pos] = src;
    g_cw[pos]   = ea[e];
}

// =============== per-node attention ===========================================
// CONCAT=1: writes hi/lo bf16 split of relu(attn+skip) [N,256]
// CONCAT=0: pools (mean_heads + skip) directly into out[graph] via atomics
template <int CONCAT>
__global__ __launch_bounds__(256, 3) void node_attn_kernel(
    const float* __restrict__ q, const __nv_bfloat16* __restrict__ kv,
    const float* __restrict__ skip, const float* __restrict__ We,
    const int* __restrict__ batch, float* __restrict__ out,
    __nv_bfloat16* __restrict__ ohi, __nv_bfloat16* __restrict__ olo)
{
    int n = blockIdx.x * 8 + (threadIdx.x >> 5);
    if (n >= N_NODES) return;
    int lane = threadIdx.x & 31;
    int beg = g_rowptr[n], end = g_rowptr[n + 1];

    const float scale = 0.08838834764831845f;   // 1/sqrt(128)

    float qv[8], ev[8];
    {
        const float* qr = q + (size_t)n * 256 + lane * 8;
        *(float4*)&qv[0] = *(const float4*)(qr);
        *(float4*)&qv[4] = *(const float4*)(qr + 4);
        *(float4*)&ev[0] = *(const float4*)(We + lane * 8);
        *(float4*)&ev[4] = *(const float4*)(We + lane * 8 + 4);
    }
    float qe = 0.f;
#pragma unroll
    for (int i = 0; i < 8; ++i) qe = fmaf(qv[i], ev[i], qe);
#pragma unroll
    for (int o = 8; o; o >>= 1) qe += __shfl_xor_sync(0xffffffffu, qe, o);
    qe *= scale;

    float d = 0.f, cw = 0.f;
    float a[8] = {};

    int p = beg;
    for (; p + 1 < end; p += 2) {
        int  sa = g_csrc[p],  sb = g_csrc[p + 1];
        float wa = g_cw[p],   wb = g_cw[p + 1];
        const uint4* ra = (const uint4*)(kv + (size_t)sa * 512);
        const uint4* rb = (const uint4*)(kv + (size_t)sb * 512);
        uint4 kua = ra[lane], kub = rb[lane];
        uint4 vua = ra[32 + lane], vub = rb[32 + lane];

        float kfa[8], kfb[8];
        bf8_to_f(kua, kfa);
        bf8_to_f(kub, kfb);
        float ta = 0.f, tb = 0.f;
#pragma unroll
        for (int i = 0; i < 8; ++i) {
            ta = fmaf(qv[i], kfa[i], ta);
            tb = fmaf(qv[i], kfb[i], tb);
        }
#pragma unroll
        for (int o = 8; o; o >>= 1) {
            ta += __shfl_xor_sync(0xffffffffu, ta, o);
            tb += __shfl_xor_sync(0xffffffffu, tb, o);
        }
        float xa = __expf(fmaf(wa, qe, ta * scale));
        float xb = __expf(fmaf(wb, qe, tb * scale));
        d  += xa + xb;
        cw += xa * wa + xb * wb;
        float vfa[8], vfb[8];
        bf8_to_f(vua, vfa);
        bf8_to_f(vub, vfb);
#pragma unroll
        for (int i = 0; i < 8; ++i)
            a[i] += xa * vfa[i] + xb * vfb[i];
    }
    for (; p < end; ++p) {
        int s = g_csrc[p];
        float w = g_cw[p];
        const uint4* r = (const uint4*)(kv + (size_t)s * 512);
        uint4 ku = r[lane], vu = r[32 + lane];
        float kf[8];
        bf8_to_f(ku, kf);
        float t = 0.f;
#pragma unroll
        for (int i = 0; i < 8; ++i) t = fmaf(qv[i], kf[i], t);
#pragma unroll
        for (int o = 8; o; o >>= 1) t += __shfl_xor_sync(0xffffffffu, t, o);
        float x = __expf(fmaf(w, qe, t * scale));
        d += x; cw += x * w;
        float vf[8];
        bf8_to_f(vu, vf);
#pragma unroll
        for (int i = 0; i < 8; ++i) a[i] += x * vf[i];
    }

    float r = d > 0.f ? 1.f / d : 0.f;
    float o8[8];
#pragma unroll
    for (int i = 0; i < 8; ++i) o8[i] = (a[i] + cw * ev[i]) * r;

    if (CONCAT) {
        float sk[8];
        const float* sr = skip + (size_t)n * 256 + lane * 8;
        *(float4*)&sk[0] = *(const float4*)(sr);
        *(float4*)&sk[4] = *(const float4*)(sr + 4);
        __align__(16) __nv_bfloat16 hb[8], lb[8];
#pragma unroll
        for (int i = 0; i < 8; ++i) {
            float o = fmaxf(o8[i] + sk[i], 0.f);
            hb[i] = __float2bfloat16(o);
            lb[i] = __float2bfloat16(o - __bfloat162float(hb[i]));
        }
        *(uint4*)&ohi[(size_t)n * 256 + lane * 8] = *(uint4*)hb;
        *(uint4*)&olo[(size_t)n * 256 + lane * 8] = *(uint4*)lb;
    } else {
        // mean over heads (partner lane = lane ^ 16), + skip, pool into out[graph]
        float m[8];
#pragma unroll
        for (int i = 0; i < 8; ++i) {
            float other = __shfl_xor_sync(0xffffffffu, o8[i], 16);
            m[i] = 0.5f * (o8[i] + other);
        }
        int g = batch[n];
        if (lane < 16) {
            const float* sr = skip + (size_t)n * 128 + lane * 8;
            float4 s0 = *(const float4*)(sr);
            float4 s1 = *(const float4*)(sr + 4);
            float h0 = m[0] + s0.x, h1 = m[1] + s0.y, h2 = m[2] + s0.z, h3 = m[3] + s0.w;
            float h4 = m[4] + s1.x, h5 = m[5] + s1.y, h6 = m[6] + s1.z, h7 = m[7] + s1.w;
            float* dst = out + (size_t)g * 128 + lane * 8;
            atomicAdd(dst + 0, h0); atomicAdd(dst + 1, h1);
            atomicAdd(dst + 2, h2); atomicAdd(dst + 3, h3);
            atomicAdd(dst + 4, h4); atomicAdd(dst + 5, h5);
            atomicAdd(dst + 6, h6); atomicAdd(dst + 7, h7);
        }
        if (lane == 0) atomicAdd(&g_cnt[g], 1.f);
    }
}

// =============== pooling finish ================================================
__global__ __launch_bounds__(256) void pool_div_kernel(float* __restrict__ out) {
    int i = blockIdx.x * blockDim.x + threadIdx.x;
    if (i >= N_GRAPHS * 128) return;
    out[i] /= fmaxf(g_cnt[i >> 7], 1.f);
}

// =============== launch =========================================================
extern "C" void kernel_launch(void* const* d_in, const int* in_sizes, int n_in,
                              void* d_out, int out_size)
{
    const float* x     = (const float*)d_in[0];
    const int*   ei    = (const int*)d_in[1];
    const int*   batch = (const int*)d_in[2];
    const float* ea    = (const float*)d_in[3];
    const float* Wq1 = (const float*)d_in[4];
    const float* bq1 = (const float*)d_in[5];
    const float* Wk1 = (const float*)d_in[6];
    const float* bk1 = (const float*)d_in[7];
    const float* Wv1 = (const float*)d_in[8];
    const float* bv1 = (const float*)d_in[9];
    const float* We1 = (const float*)d_in[10];
    const float* Ws1 = (const float*)d_in[11];
    const float* bs1 = (const float*)d_in[12];
    const float* Wq2 = (const float*)d_in[13];
    const float* bq2 = (const float*)d_in[14];
    const float* Wk2 = (const float*)d_in[15];
    const float* bk2 = (const float*)d_in[16];
    const float* Wv2 = (const float*)d_in[17];
    const float* bv2 = (const float*)d_in[18];
    const float* We2 = (const float*)d_in[19];
    const float* Ws2 = (const float*)d_in[20];
    const float* bs2 = (const float*)d_in[21];
    float* out = (float*)d_out;

    float *pq, *pskip;
    __nv_bfloat16 *pkv, *pahi, *palo, *pwhi, *pwlo;
    cudaGetSymbolAddress((void**)&pq,    g_q);
    cudaGetSymbolAddress((void**)&pskip, g_skip);
    cudaGetSymbolAddress((void**)&pkv,   g_kv);
    cudaGetSymbolAddress((void**)&pahi,  g_ahi);
    cudaGetSymbolAddress((void**)&palo,  g_alo);
    cudaGetSymbolAddress((void**)&pwhi,  g_whi);
    cudaGetSymbolAddress((void**)&pwlo,  g_wlo);

    cudaFuncSetAttribute(gemm_qkvs_kernel,
                         cudaFuncAttributeMaxDynamicSharedMemorySize, GSMEM_TOT);
    cudaFuncSetAttribute(gemm_skip2_kernel,
                         cudaFuncAttributeMaxDynamicSharedMemorySize, GSMEM_TOT);

    const int RT  = (N_NODES + 127) / 128;            // 391 row tiles
    const int EB  = (N_EDGES + 255) / 256;
    const int NB  = (N_NODES + 255) / 256;            // 196
    const int NWB = (N_NODES + 7) / 8;
    const int PZ  = (N_GRAPHS * 128 + 255) / 256;     // 1250

    // ---- init + CSR build ----
    init_zero_kernel<<<PZ, 256>>>(out);
    hist_kernel<<<EB, 256>>>(ei);
    scan1_kernel<<<NB, 256>>>();
    scan3_kernel<<<NB, 256>>>();
    csr_scatter_kernel<<<EB, 256>>>(ei, ea);

    // ---- layer 1 (in=128, concat heads): one merged GEMM launch ----
    cvt_split_kernel<<<(N_NODES * 128 / 4 + 255) / 256, 256>>>(x, pahi, palo, N_NODES * 128 / 4);
    cvt_split4_kernel<<<dim3(8192 / 256, 4), 256>>>(Wq1, Wk1, Wv1, Ws1,
                                                    pwhi, pwlo, 8192, 8192, 8192, 8192);
    gemm_qkvs_kernel<<<dim3(RT, 8), 256, GSMEM_TOT>>>(
        pahi, palo, bq1, bk1, bv1, bs1, pq, pkv, pskip, 128);
    node_attn_kernel<1><<<NWB, 256>>>(pq, pkv, pskip, We1, batch, nullptr, pahi, palo);

    // ---- layer 2 (in=256, mean heads + fused pool) ----
    cvt_split4_kernel<<<dim3(16384 / 256, 4), 256>>>(Wq2, Wk2, Wv2, Ws2,
                                                     pwhi, pwlo, 16384, 16384, 16384, 8192);
    gemm_qkvs_kernel<<<dim3(RT, 6), 256, GSMEM_TOT>>>(
        pahi, palo, bq2, bk2, bv2, bs2, pq, pkv, nullptr, 256);
    gemm_skip2_kernel<<<RT, 256, GSMEM_TOT>>>(pahi, palo, bs2, pskip, 256);
    node_attn_kernel<0><<<NWB, 256>>>(pq, pkv, pskip, We2, batch, out, nullptr, nullptr);

    // ---- pool finish ----
    pool_div_kernel<<<PZ, 256>>>(out);
}

// round 13
// speedup vs baseline: 1.3358x; 1.0354x over previous
#include <cuda_runtime.h>
#include <cuda_bf16.h>
#include <math.h>
#include <stdint.h>

#define N_NODES  50000
#define N_EDGES  800000
#define N_GRAPHS 2500

// ---------------- scratch (device globals; no allocations allowed) ----------
__device__ __align__(256) float g_q[N_NODES * 256];
__device__ __align__(256) float g_skip[N_NODES * 256];
__device__ __align__(256) float g_cw[N_EDGES];
__device__ __align__(256) int   g_csrc[N_EDGES];
__device__ __align__(256) int   g_rowptr[N_NODES + 1];
__device__ __align__(256) int   g_wof[N_NODES];
__device__ __align__(256) int   g_bsum[256];
__device__ __align__(256) float g_cnt[N_GRAPHS];
// bf16 operands
__device__ __align__(256) __nv_bfloat16 g_kv[N_NODES * 512];   // [k(256) | v(256)]
__device__ __align__(256) __nv_bfloat16 g_ahi[N_NODES * 256];
__device__ __align__(256) __nv_bfloat16 g_alo[N_NODES * 256];
__device__ __align__(256) __nv_bfloat16 g_whi[262144];
__device__ __align__(256) __nv_bfloat16 g_wlo[262144];

// ================= warp-MMA helpers ==========================================
__device__ __forceinline__ uint32_t smem_u32(const void* p) {
    uint32_t a;
    asm("{ .reg .u64 t; cvta.to.shared.u64 t, %1; cvt.u32.u64 %0, t; }"
        : "=r"(a) : "l"(p));
    return a;
}

__device__ __forceinline__ void ldsm_x4(uint32_t r[4], uint32_t addr) {
    asm volatile("ldmatrix.sync.aligned.m8n8.x4.shared.b16 {%0,%1,%2,%3}, [%4];"
        : "=r"(r[0]), "=r"(r[1]), "=r"(r[2]), "=r"(r[3]) : "r"(addr));
}
__device__ __forceinline__ void ldsm_x4_t(uint32_t r[4], uint32_t addr) {
    asm volatile("ldmatrix.sync.aligned.m8n8.x4.trans.shared.b16 {%0,%1,%2,%3}, [%4];"
        : "=r"(r[0]), "=r"(r[1]), "=r"(r[2]), "=r"(r[3]) : "r"(addr));
}

__device__ __forceinline__ void mma16816(float d[4], const uint32_t a[4],
                                         const uint32_t b[2]) {
    asm volatile(
        "mma.sync.aligned.m16n8k16.row.col.f32.bf16.bf16.f32 "
        "{%0,%1,%2,%3}, {%4,%5,%6,%7}, {%8,%9}, {%0,%1,%2,%3};"
        : "+f"(d[0]), "+f"(d[1]), "+f"(d[2]), "+f"(d[3])
        : "r"(a[0]), "r"(a[1]), "r"(a[2]), "r"(a[3]), "r"(b[0]), "r"(b[1]));
}

__device__ __forceinline__ void cp_async16(uint32_t dst, const void* src, int sz) {
    asm volatile("cp.async.cg.shared.global [%0], [%1], 16, %2;"
        :: "r"(dst), "l"(src), "r"(sz));
}
__device__ __forceinline__ void cp_commit() {
    asm volatile("cp.async.commit_group;" ::: "memory");
}

__device__ __forceinline__ void bf8_to_f(const uint4& u, float* f) {
    float2 p;
    p = __bfloat1622float2(*(const __nv_bfloat162*)&u.x); f[0] = p.x; f[1] = p.y;
    p = __bfloat1622float2(*(const __nv_bfloat162*)&u.y); f[2] = p.x; f[3] = p.y;
    p = __bfloat1622float2(*(const __nv_bfloat162*)&u.z); f[4] = p.x; f[5] = p.y;
    p = __bfloat1622float2(*(const __nv_bfloat162*)&u.w); f[6] = p.x; f[7] = p.y;
}

// =============== fp32 -> bf16 hi/lo split ======================================
__device__ __forceinline__ void split4(float4 v, uint2& hv, uint2& lv) {
    __nv_bfloat16 h0 = __float2bfloat16(v.x);
    __nv_bfloat16 h1 = __float2bfloat16(v.y);
    __nv_bfloat16 h2 = __float2bfloat16(v.z);
    __nv_bfloat16 h3 = __float2bfloat16(v.w);
    __nv_bfloat16 l0 = __float2bfloat16(v.x - __bfloat162float(h0));
    __nv_bfloat16 l1 = __float2bfloat16(v.y - __bfloat162float(h1));
    __nv_bfloat16 l2 = __float2bfloat16(v.z - __bfloat162float(h2));
    __nv_bfloat16 l3 = __float2bfloat16(v.w - __bfloat162float(h3));
    __nv_bfloat162 hp0 = __halves2bfloat162(h0, h1);
    __nv_bfloat162 hp1 = __halves2bfloat162(h2, h3);
    __nv_bfloat162 lp0 = __halves2bfloat162(l0, l1);
    __nv_bfloat162 lp1 = __halves2bfloat162(l2, l3);
    hv = make_uint2(*(uint32_t*)&hp0, *(uint32_t*)&hp1);
    lv = make_uint2(*(uint32_t*)&lp0, *(uint32_t*)&lp1);
}

__global__ __launch_bounds__(256) void cvt_split_kernel(
    const float* __restrict__ src, __nv_bfloat16* __restrict__ hi,
    __nv_bfloat16* __restrict__ lo, int n4)
{
    int i = blockIdx.x * blockDim.x + threadIdx.x;
    if (i >= n4) return;
    uint2 hv, lv;
    split4(((const float4*)src)[i], hv, lv);
    *(uint2*)&hi[i * 4] = hv;
    *(uint2*)&lo[i * 4] = lv;
}

// 4 weight matrices in one launch (grid.y selects matrix)
__global__ __launch_bounds__(256) void cvt_split4_kernel(
    const float* s0, const float* s1, const float* s2, const float* s3,
    __nv_bfloat16* hi, __nv_bfloat16* lo,
    int n4_0, int n4_1, int n4_2, int n4_3)
{
    const float* srcs[4] = {s0, s1, s2, s3};
    int n4s[4]  = {n4_0, n4_1, n4_2, n4_3};
    int offs[4] = {0, 65536, 131072, 196608};
    int m = blockIdx.y;
    int i = blockIdx.x * blockDim.x + threadIdx.x;
    if (i >= n4s[m]) return;
    uint2 hv, lv;
    split4(((const float4*)srcs[m])[i], hv, lv);
    *(uint2*)&hi[offs[m] + i * 4] = hv;
    *(uint2*)&lo[offs[m] + i * 4] = lv;
}

// ================= tensor-core GEMM (cp.async double-buffered) ===============
#define ST_A_HI 0
#define ST_A_LO 10240
#define ST_B_HI 20480
#define ST_B_LO 29184
#define ST_SIZE 37888
#define GSMEM_TOT (2 * ST_SIZE)

template <int NW>  // NW: W row width
__device__ __forceinline__ void gemm_core(
    const __nv_bfloat16* __restrict__ aHi, const __nv_bfloat16* __restrict__ aLo,
    const __nv_bfloat16* __restrict__ wHi, const __nv_bfloat16* __restrict__ wLo,
    int K, int r0, int c0, uint32_t sb, float acc[2][8][4])
{
    const int t    = threadIdx.x;
    const int lane = t & 31;
    const int wid  = t >> 5;
    const int wm   = wid & 3;
    const int wn   = wid >> 2;

    const int aRow = lane & 15;
    const int aCol = (lane >> 4) * 8;
    const int bK   = lane & 15;
    const int bN   = (lane >> 4) * 8;

    const int nChunks = K >> 5;

    auto stage = [&](int c, int buf) {
        uint32_t st = sb + buf * ST_SIZE;
        int kc = c << 5;
#pragma unroll
        for (int it = 0; it < 2; ++it) {
            int fid = t + it * 256;
            int row = fid >> 2;
            int col = (fid & 3) * 8;
            int rg  = r0 + row;
            int ok  = (rg < N_NODES) ? 16 : 0;
            int rc  = (rg < N_NODES) ? rg : (N_NODES - 1);
            size_t gidx = (size_t)rc * K + kc + col;
            uint32_t d = st + row * 80 + col * 2;
            cp_async16(d + ST_A_HI, &aHi[gidx], ok);
            cp_async16(d + ST_A_LO, &aLo[gidx], ok);
        }
#pragma unroll
        for (int it = 0; it < 2; ++it) {
            int fid = t + it * 256;
            int kk  = fid >> 4;
            int n   = (fid & 15) * 8;
            size_t gidx = (size_t)(kc + kk) * NW + c0 + n;
            uint32_t d = st + kk * 272 + n * 2;
            cp_async16(d + ST_B_HI, &wHi[gidx], 16);
            cp_async16(d + ST_B_LO, &wLo[gidx], 16);
        }
        cp_commit();
    };

    stage(0, 0);
    for (int c = 0; c < nChunks; ++c) {
        bool more = (c + 1 < nChunks);
        if (more) stage(c + 1, (c + 1) & 1);
        if (more) asm volatile("cp.async.wait_group 1;" ::: "memory");
        else      asm volatile("cp.async.wait_group 0;" ::: "memory");
        __syncthreads();

        uint32_t st = sb + (c & 1) * ST_SIZE;
#pragma unroll
        for (int ks = 0; ks < 2; ++ks) {
            uint32_t aH[2][4], aL[2][4], bf[4][4];
#pragma unroll
            for (int mi = 0; mi < 2; ++mi) {
                uint32_t ar = st + (wm * 32 + mi * 16 + aRow) * 80 + (ks * 16 + aCol) * 2;
                ldsm_x4(aH[mi], ar + ST_A_HI);
                ldsm_x4(aL[mi], ar + ST_A_LO);
            }
#pragma unroll
            for (int pi = 0; pi < 4; ++pi)
                ldsm_x4_t(bf[pi], st + ST_B_HI + (ks * 16 + bK) * 272
                                     + (wn * 64 + pi * 16 + bN) * 2);
#pragma unroll
            for (int mi = 0; mi < 2; ++mi)
#pragma unroll
                for (int pi = 0; pi < 4; ++pi) {
                    mma16816(acc[mi][2 * pi],     aH[mi], &bf[pi][0]);
                    mma16816(acc[mi][2 * pi + 1], aH[mi], &bf[pi][2]);
                }
#pragma unroll
            for (int mi = 0; mi < 2; ++mi)
#pragma unroll
                for (int pi = 0; pi < 4; ++pi) {
                    mma16816(acc[mi][2 * pi],     aL[mi], &bf[pi][0]);
                    mma16816(acc[mi][2 * pi + 1], aL[mi], &bf[pi][2]);
                }
#pragma unroll
            for (int pi = 0; pi < 4; ++pi)
                ldsm_x4_t(bf[pi], st + ST_B_LO + (ks * 16 + bK) * 272
                                     + (wn * 64 + pi * 16 + bN) * 2);
#pragma unroll
            for (int mi = 0; mi < 2; ++mi)
#pragma unroll
                for (int pi = 0; pi < 4; ++pi) {
                    mma16816(acc[mi][2 * pi],     aH[mi], &bf[pi][0]);
                    mma16816(acc[mi][2 * pi + 1], aH[mi], &bf[pi][2]);
                }
        }
        __syncthreads();
    }
}

// ---- merged q/k/v(/skip) GEMM -------------------------------------------------
// blockIdx.y in [0,5]: gi = y>>1 (0=q,1=k,2=v), c0 = (y&1)*128, W width 256.
// blockIdx.y == 6 (layer1): gi=3 skip, c0 = handled as y==6/7 via SK256.
// SK256=1 (layer 1): y in [0,7], gi = y>>1 incl. skip width 256.
// SK256=0 (layer 2): y in [0,6]; y==6 -> skip GEMM width 128 (c0=0).
template <int SK256>
__global__ __launch_bounds__(256) void gemm_qkvs_kernel(
    const __nv_bfloat16* __restrict__ aHi, const __nv_bfloat16* __restrict__ aLo,
    const float* __restrict__ b0, const float* __restrict__ b1,
    const float* __restrict__ b2, const float* __restrict__ b3,
    float* __restrict__ Yq, __nv_bfloat16* __restrict__ Ykv,
    float* __restrict__ Ys, int K)
{
    extern __shared__ __align__(16) char smem[];
    const uint32_t sb = smem_u32(smem);
    const int r0 = blockIdx.x * 128;

    const int lane = threadIdx.x & 31;
    const int wid  = threadIdx.x >> 5;
    const int wm   = wid & 3;
    const int wn   = wid >> 2;

    if (!SK256 && blockIdx.y == 6) {
        // layer-2 skip GEMM: W width 128
        float acc[2][8][4] = {};
        gemm_core<128>(aHi, aLo, g_whi + 196608, g_wlo + 196608, K, r0, 0, sb, acc);
#pragma unroll
        for (int mi = 0; mi < 2; ++mi) {
            int rA = r0 + wm * 32 + mi * 16 + (lane >> 2);
            int rB = rA + 8;
#pragma unroll
            for (int ni = 0; ni < 8; ++ni) {
                int cc  = wn * 64 + ni * 8 + (lane & 3) * 2;
                float2 bv = *(const float2*)&b3[cc];
                if (rA < N_NODES)
                    *(float2*)&Ys[(size_t)rA * 128 + cc] =
                        make_float2(acc[mi][ni][0] + bv.x, acc[mi][ni][1] + bv.y);
                if (rB < N_NODES)
                    *(float2*)&Ys[(size_t)rB * 128 + cc] =
                        make_float2(acc[mi][ni][2] + bv.x, acc[mi][ni][3] + bv.y);
            }
        }
        return;
    }

    const int gi = blockIdx.y >> 1;
    const int c0 = (blockIdx.y & 1) * 128;

    const __nv_bfloat16* wHi = g_whi + gi * 65536;
    const __nv_bfloat16* wLo = g_wlo + gi * 65536;
    const float* bias = (gi == 0) ? b0 : (gi == 1) ? b1 : (gi == 2) ? b2 : b3;

    float acc[2][8][4] = {};
    gemm_core<256>(aHi, aLo, wHi, wLo, K, r0, c0, sb, acc);

#pragma unroll
    for (int mi = 0; mi < 2; ++mi) {
        int rA = r0 + wm * 32 + mi * 16 + (lane >> 2);
        int rB = rA + 8;
#pragma unroll
        for (int ni = 0; ni < 8; ++ni) {
            int cc  = c0 + wn * 64 + ni * 8 + (lane & 3) * 2;
            float2 bv = *(const float2*)&bias[cc];
            float x0 = acc[mi][ni][0] + bv.x, y0 = acc[mi][ni][1] + bv.y;
            float x1 = acc[mi][ni][2] + bv.x, y1 = acc[mi][ni][3] + bv.y;
            if (gi == 1 || gi == 2) {
                int kcol = cc + ((gi == 2) ? 256 : 0);
                if (rA < N_NODES)
                    *(__nv_bfloat162*)&Ykv[(size_t)rA * 512 + kcol] =
                        __floats2bfloat162_rn(x0, y0);
                if (rB < N_NODES)
                    *(__nv_bfloat162*)&Ykv[(size_t)rB * 512 + kcol] =
                        __floats2bfloat162_rn(x1, y1);
            } else {
                float* Y = (gi == 0) ? Yq : Ys;
                if (rA < N_NODES)
                    *(float2*)&Y[(size_t)rA * 256 + cc] = make_float2(x0, y0);
                if (rB < N_NODES)
                    *(float2*)&Y[(size_t)rB * 256 + cc] = make_float2(x1, y1);
            }
        }
    }
}

// =============== init + CSR build =============================================
__global__ __launch_bounds__(256) void init_zero_kernel(float* __restrict__ out) {
    int i = blockIdx.x * blockDim.x + threadIdx.x;
    if (i < N_GRAPHS * 128) out[i] = 0.f;
    if (i < N_NODES) g_wof[i] = 0;
    if (i < N_GRAPHS) g_cnt[i] = 0.f;
}

__global__ __launch_bounds__(256) void hist_kernel(const int* __restrict__ ei) {
    int e = blockIdx.x * blockDim.x + threadIdx.x;
    if (e < N_EDGES) atomicAdd(&g_wof[ei[N_EDGES + e]], 1);
}

__global__ __launch_bounds__(256) void scan1_kernel() {
    __shared__ int sb[2][256];
    int t = threadIdx.x;
    int i = blockIdx.x * 256 + t;
    int v = (i < N_NODES) ? g_wof[i] : 0;
    int pin = 0;
    sb[0][t] = v;
    __syncthreads();
#pragma unroll
    for (int off = 1; off < 256; off <<= 1) {
        int x = sb[pin][t];
        if (t >= off) x += sb[pin][t - off];
        sb[pin ^ 1][t] = x;
        __syncthreads();
        pin ^= 1;
    }
    int incl = sb[pin][t];
    if (i < N_NODES) g_rowptr[i] = incl - v;
    if (t == 255) g_bsum[blockIdx.x] = incl;
}

__global__ __launch_bounds__(256) void scan3_kernel() {
    __shared__ int sp[8];
    int t = threadIdx.x;
    int bid = blockIdx.x;
    int part = 0;
    for (int j = t; j < bid; j += 256) part += g_bsum[j];
#pragma unroll
    for (int o = 16; o; o >>= 1) part += __shfl_xor_sync(0xffffffffu, part, o);
    if ((t & 31) == 0) sp[t >> 5] = part;
    __syncthreads();
    if (t == 0) {
        int s = 0;
#pragma unroll
        for (int w = 0; w < 8; ++w) s += sp[w];
        sp[0] = s;
        if (bid == 0) g_rowptr[N_NODES] = N_EDGES;
    }
    __syncthreads();
    int off = sp[0];
    int i = bid * 256 + t;
    if (i < N_NODES) {
        int r = g_rowptr[i] + off;
        g_rowptr[i] = r;
        g_wof[i]    = r;
    }
}

__global__ __launch_bounds__(256) void csr_scatter_kernel(
    const int* __restrict__ ei, const float* __restrict__ ea)
{
    int e = blockIdx.x * blockDim.x + threadIdx.x;
    if (e >= N_EDGES) return;
    int src = ei[e];
    int dst = ei[N_EDGES + e];
    int pos = atomicAdd(&g_wof[dst], 1);
    g_csrc[pos] = src;
    g_cw[pos]   = ea[e];
}

// =============== per-node attention ===========================================
// CONCAT=1: writes hi/lo bf16 split of relu(attn+skip) [N,256]
// CONCAT=0: pools (mean_heads + skip) directly into out[graph] via atomics
template <int CONCAT>
__global__ __launch_bounds__(256, 3) void node_attn_kernel(
    const float* __restrict__ q, const __nv_bfloat16* __restrict__ kv,
    const float* __restrict__ skip, const float* __restrict__ We,
    const int* __restrict__ batch, float* __restrict__ out,
    __nv_bfloat16* __restrict__ ohi, __nv_bfloat16* __restrict__ olo)
{
    int n = blockIdx.x * 8 + (threadIdx.x >> 5);
    if (n >= N_NODES) return;
    int lane = threadIdx.x & 31;
    int beg = g_rowptr[n], end = g_rowptr[n + 1];

    const float scale = 0.08838834764831845f;   // 1/sqrt(128)

    float qv[8], ev[8];
    {
        const float* qr = q + (size_t)n * 256 + lane * 8;
        *(float4*)&qv[0] = *(const float4*)(qr);
        *(float4*)&qv[4] = *(const float4*)(qr + 4);
        *(float4*)&ev[0] = *(const float4*)(We + lane * 8);
        *(float4*)&ev[4] = *(const float4*)(We + lane * 8 + 4);
    }
    float qe = 0.f;
#pragma unroll
    for (int i = 0; i < 8; ++i) qe = fmaf(qv[i], ev[i], qe);
#pragma unroll
    for (int o = 8; o; o >>= 1) qe += __shfl_xor_sync(0xffffffffu, qe, o);
    qe *= scale;

    float d = 0.f, cw = 0.f;
    float a[8] = {};

    int p = beg;
    // prefetched indices for the next pair
    int  nsa = 0, nsb = 0;
    float nwa = 0.f, nwb = 0.f;
    if (p + 1 < end) {
        nsa = g_csrc[p];     nwa = g_cw[p];
        nsb = g_csrc[p + 1]; nwb = g_cw[p + 1];
    }
    for (; p + 1 < end; p += 2) {
        int  sa = nsa,  sb = nsb;
        float wa = nwa, wb = nwb;
        if (p + 3 < end) {
            nsa = g_csrc[p + 2]; nwa = g_cw[p + 2];
            nsb = g_csrc[p + 3]; nwb = g_cw[p + 3];
        }
        const uint4* ra = (const uint4*)(kv + (size_t)sa * 512);
        const uint4* rb = (const uint4*)(kv + (size_t)sb * 512);
        uint4 kua = ra[lane], kub = rb[lane];
        uint4 vua = ra[32 + lane], vub = rb[32 + lane];

        float kfa[8], kfb[8];
        bf8_to_f(kua, kfa);
        bf8_to_f(kub, kfb);
        float ta = 0.f, tb = 0.f;
#pragma unroll
        for (int i = 0; i < 8; ++i) {
            ta = fmaf(qv[i], kfa[i], ta);
            tb = fmaf(qv[i], kfb[i], tb);
        }
#pragma unroll
        for (int o = 8; o; o >>= 1) {
            ta += __shfl_xor_sync(0xffffffffu, ta, o);
            tb += __shfl_xor_sync(0xffffffffu, tb, o);
        }
        float xa = __expf(fmaf(wa, qe, ta * scale));
        float xb = __expf(fmaf(wb, qe, tb * scale));
        d  += xa + xb;
        cw += xa * wa + xb * wb;
        float vfa[8], vfb[8];
        bf8_to_f(vua, vfa);
        bf8_to_f(vub, vfb);
#pragma unroll
        for (int i = 0; i < 8; ++i)
            a[i] += xa * vfa[i] + xb * vfb[i];
    }
    for (; p < end; ++p) {
        int s = g_csrc[p];
        float w = g_cw[p];
        const uint4* r = (const uint4*)(kv + (size_t)s * 512);
        uint4 ku = r[lane], vu = r[32 + lane];
        float kf[8];
        bf8_to_f(ku, kf);
        float t = 0.f;
#pragma unroll
        for (int i = 0; i < 8; ++i) t = fmaf(qv[i], kf[i], t);
#pragma unroll
        for (int o = 8; o; o >>= 1) t += __shfl_xor_sync(0xffffffffu, t, o);
        float x = __expf(fmaf(w, qe, t * scale));
        d += x; cw += x * w;
        float vf[8];
        bf8_to_f(vu, vf);
#pragma unroll
        for (int i = 0; i < 8; ++i) a[i] += x * vf[i];
    }

    float r = d > 0.f ? 1.f / d : 0.f;
    float o8[8];
#pragma unroll
    for (int i = 0; i < 8; ++i) o8[i] = (a[i] + cw * ev[i]) * r;

    if (CONCAT) {
        float sk[8];
        const float* sr = skip + (size_t)n * 256 + lane * 8;
        *(float4*)&sk[0] = *(const float4*)(sr);
        *(float4*)&sk[4] = *(const float4*)(sr + 4);
        __align__(16) __nv_bfloat16 hb[8], lb[8];
#pragma unroll
        for (int i = 0; i < 8; ++i) {
            float o = fmaxf(o8[i] + sk[i], 0.f);
            hb[i] = __float2bfloat16(o);
            lb[i] = __float2bfloat16(o - __bfloat162float(hb[i]));
        }
        *(uint4*)&ohi[(size_t)n * 256 + lane * 8] = *(uint4*)hb;
        *(uint4*)&olo[(size_t)n * 256 + lane * 8] = *(uint4*)lb;
    } else {
        // mean over heads (partner lane = lane ^ 16), + skip, pool into out[graph]
        float m[8];
#pragma unroll
        for (int i = 0; i < 8; ++i) {
            float other = __shfl_xor_sync(0xffffffffu, o8[i], 16);
            m[i] = 0.5f * (o8[i] + other);
        }
        int g = batch[n];
        if (lane < 16) {
            const float* sr = skip + (size_t)n * 128 + lane * 8;
            float4 s0 = *(const float4*)(sr);
            float4 s1 = *(const float4*)(sr + 4);
            float h0 = m[0] + s0.x, h1 = m[1] + s0.y, h2 = m[2] + s0.z, h3 = m[3] + s0.w;
            float h4 = m[4] + s1.x, h5 = m[5] + s1.y, h6 = m[6] + s1.z, h7 = m[7] + s1.w;
            float* dst = out + (size_t)g * 128 + lane * 8;
            atomicAdd(dst + 0, h0); atomicAdd(dst + 1, h1);
            atomicAdd(dst + 2, h2); atomicAdd(dst + 3, h3);
            atomicAdd(dst + 4, h4); atomicAdd(dst + 5, h5);
            atomicAdd(dst + 6, h6); atomicAdd(dst + 7, h7);
        }
        if (lane == 0) atomicAdd(&g_cnt[g], 1.f);
    }
}

// =============== pooling finish ================================================
__global__ __launch_bounds__(256) void pool_div_kernel(float* __restrict__ out) {
    int i = blockIdx.x * blockDim.x + threadIdx.x;
    if (i >= N_GRAPHS * 128) return;
    out[i] /= fmaxf(g_cnt[i >> 7], 1.f);
}

// =============== launch =========================================================
extern "C" void kernel_launch(void* const* d_in, const int* in_sizes, int n_in,
                              void* d_out, int out_size)
{
    const float* x     = (const float*)d_in[0];
    const int*   ei    = (const int*)d_in[1];
    const int*   batch = (const int*)d_in[2];
    const float* ea    = (const float*)d_in[3];
    const float* Wq1 = (const float*)d_in[4];
    const float* bq1 = (const float*)d_in[5];
    const float* Wk1 = (const float*)d_in[6];
    const float* bk1 = (const float*)d_in[7];
    const float* Wv1 = (const float*)d_in[8];
    const float* bv1 = (const float*)d_in[9];
    const float* We1 = (const float*)d_in[10];
    const float* Ws1 = (const float*)d_in[11];
    const float* bs1 = (const float*)d_in[12];
    const float* Wq2 = (const float*)d_in[13];
    const float* bq2 = (const float*)d_in[14];
    const float* Wk2 = (const float*)d_in[15];
    const float* bk2 = (const float*)d_in[16];
    const float* Wv2 = (const float*)d_in[17];
    const float* bv2 = (const float*)d_in[18];
    const float* We2 = (const float*)d_in[19];
    const float* Ws2 = (const float*)d_in[20];
    const float* bs2 = (const float*)d_in[21];
    float* out = (float*)d_out;

    float *pq, *pskip;
    __nv_bfloat16 *pkv, *pahi, *palo, *pwhi, *pwlo;
    cudaGetSymbolAddress((void**)&pq,    g_q);
    cudaGetSymbolAddress((void**)&pskip, g_skip);
    cudaGetSymbolAddress((void**)&pkv,   g_kv);
    cudaGetSymbolAddress((void**)&pahi,  g_ahi);
    cudaGetSymbolAddress((void**)&palo,  g_alo);
    cudaGetSymbolAddress((void**)&pwhi,  g_whi);
    cudaGetSymbolAddress((void**)&pwlo,  g_wlo);

    cudaFuncSetAttribute(gemm_qkvs_kernel<1>,
                         cudaFuncAttributeMaxDynamicSharedMemorySize, GSMEM_TOT);
    cudaFuncSetAttribute(gemm_qkvs_kernel<0>,
                         cudaFuncAttributeMaxDynamicSharedMemorySize, GSMEM_TOT);

    const int RT  = (N_NODES + 127) / 128;            // 391 row tiles
    const int EB  = (N_EDGES + 255) / 256;
    const int NB  = (N_NODES + 255) / 256;            // 196
    const int NWB = (N_NODES + 7) / 8;
    const int PZ  = (N_GRAPHS * 128 + 255) / 256;     // 1250

    // ---- init + CSR build ----
    init_zero_kernel<<<PZ, 256>>>(out);
    hist_kernel<<<EB, 256>>>(ei);
    scan1_kernel<<<NB, 256>>>();
    scan3_kernel<<<NB, 256>>>();
    csr_scatter_kernel<<<EB, 256>>>(ei, ea);

    // ---- layer 1 (in=128, concat heads): one merged GEMM launch ----
    cvt_split_kernel<<<(N_NODES * 128 / 4 + 255) / 256, 256>>>(x, pahi, palo, N_NODES * 128 / 4);
    cvt_split4_kernel<<<dim3(8192 / 256, 4), 256>>>(Wq1, Wk1, Wv1, Ws1,
                                                    pwhi, pwlo, 8192, 8192, 8192, 8192);
    gemm_qkvs_kernel<1><<<dim3(RT, 8), 256, GSMEM_TOT>>>(
        pahi, palo, bq1, bk1, bv1, bs1, pq, pkv, pskip, 128);
    node_attn_kernel<1><<<NWB, 256>>>(pq, pkv, pskip, We1, batch, nullptr, pahi, palo);

    // ---- layer 2 (in=256, mean heads + fused pool): skip folded into y==6 ----
    cvt_split4_kernel<<<dim3(16384 / 256, 4), 256>>>(Wq2, Wk2, Wv2, Ws2,
                                                     pwhi, pwlo, 16384, 16384, 16384, 8192);
    gemm_qkvs_kernel<0><<<dim3(RT, 7), 256, GSMEM_TOT>>>(
        pahi, palo, bq2, bk2, bv2, bs2, pq, pkv, pskip, 256);
    node_attn_kernel<0><<<NWB, 256>>>(pq, pkv, pskip, We2, batch, out, nullptr, nullptr);

    // ---- pool finish ----
    pool_div_kernel<<<PZ, 256>>>(out);
}

// round 14
// speedup vs baseline: 1.3693x; 1.0250x over previous
#include <cuda_runtime.h>
#include <cuda_bf16.h>
#include <math.h>
#include <stdint.h>

#define N_NODES  50000
#define N_EDGES  800000
#define N_GRAPHS 2500

// ---------------- scratch (device globals; no allocations allowed) ----------
__device__ __align__(256) float g_q[N_NODES * 256];
__device__ __align__(256) float g_skip[N_NODES * 256];
__device__ __align__(256) float g_cw[N_EDGES];
__device__ __align__(256) int   g_csrc[N_EDGES];
__device__ __align__(256) int   g_rowptr[N_NODES + 1];
__device__ __align__(256) int   g_wof[N_NODES];
__device__ __align__(256) int   g_bsum[256];
__device__ __align__(256) float g_cnt[N_GRAPHS];
// bf16 operands
__device__ __align__(256) __nv_bfloat16 g_kv[N_NODES * 512];   // [k(256) | v(256)]
__device__ __align__(256) __nv_bfloat16 g_ahi[N_NODES * 256];
__device__ __align__(256) __nv_bfloat16 g_alo[N_NODES * 256];
__device__ __align__(256) __nv_bfloat16 g_whi[262144];
__device__ __align__(256) __nv_bfloat16 g_wlo[262144];

// ================= warp-MMA helpers ==========================================
__device__ __forceinline__ uint32_t smem_u32(const void* p) {
    uint32_t a;
    asm("{ .reg .u64 t; cvta.to.shared.u64 t, %1; cvt.u32.u64 %0, t; }"
        : "=r"(a) : "l"(p));
    return a;
}

__device__ __forceinline__ void ldsm_x4(uint32_t r[4], uint32_t addr) {
    asm volatile("ldmatrix.sync.aligned.m8n8.x4.shared.b16 {%0,%1,%2,%3}, [%4];"
        : "=r"(r[0]), "=r"(r[1]), "=r"(r[2]), "=r"(r[3]) : "r"(addr));
}
__device__ __forceinline__ void ldsm_x4_t(uint32_t r[4], uint32_t addr) {
    asm volatile("ldmatrix.sync.aligned.m8n8.x4.trans.shared.b16 {%0,%1,%2,%3}, [%4];"
        : "=r"(r[0]), "=r"(r[1]), "=r"(r[2]), "=r"(r[3]) : "r"(addr));
}

__device__ __forceinline__ void mma16816(float d[4], const uint32_t a[4],
                                         const uint32_t b[2]) {
    asm volatile(
        "mma.sync.aligned.m16n8k16.row.col.f32.bf16.bf16.f32 "
        "{%0,%1,%2,%3}, {%4,%5,%6,%7}, {%8,%9}, {%0,%1,%2,%3};"
        : "+f"(d[0]), "+f"(d[1]), "+f"(d[2]), "+f"(d[3])
        : "r"(a[0]), "r"(a[1]), "r"(a[2]), "r"(a[3]), "r"(b[0]), "r"(b[1]));
}

__device__ __forceinline__ void cp_async16(uint32_t dst, const void* src, int sz) {
    asm volatile("cp.async.cg.shared.global [%0], [%1], 16, %2;"
        :: "r"(dst), "l"(src), "r"(sz));
}
__device__ __forceinline__ void cp_commit() {
    asm volatile("cp.async.commit_group;" ::: "memory");
}

__device__ __forceinline__ void bf8_to_f(const uint4& u, float* f) {
    float2 p;
    p = __bfloat1622float2(*(const __nv_bfloat162*)&u.x); f[0] = p.x; f[1] = p.y;
    p = __bfloat1622float2(*(const __nv_bfloat162*)&u.y); f[2] = p.x; f[3] = p.y;
    p = __bfloat1622float2(*(const __nv_bfloat162*)&u.z); f[4] = p.x; f[5] = p.y;
    p = __bfloat1622float2(*(const __nv_bfloat162*)&u.w); f[6] = p.x; f[7] = p.y;
}

// =============== fp32 -> bf16 hi/lo split ======================================
__device__ __forceinline__ void split4(float4 v, uint2& hv, uint2& lv) {
    __nv_bfloat16 h0 = __float2bfloat16(v.x);
    __nv_bfloat16 h1 = __float2bfloat16(v.y);
    __nv_bfloat16 h2 = __float2bfloat16(v.z);
    __nv_bfloat16 h3 = __float2bfloat16(v.w);
    __nv_bfloat16 l0 = __float2bfloat16(v.x - __bfloat162float(h0));
    __nv_bfloat16 l1 = __float2bfloat16(v.y - __bfloat162float(h1));
    __nv_bfloat16 l2 = __float2bfloat16(v.z - __bfloat162float(h2));
    __nv_bfloat16 l3 = __float2bfloat16(v.w - __bfloat162float(h3));
    __nv_bfloat162 hp0 = __halves2bfloat162(h0, h1);
    __nv_bfloat162 hp1 = __halves2bfloat162(h2, h3);
    __nv_bfloat162 lp0 = __halves2bfloat162(l0, l1);
    __nv_bfloat162 lp1 = __halves2bfloat162(l2, l3);
    hv = make_uint2(*(uint32_t*)&hp0, *(uint32_t*)&hp1);
    lv = make_uint2(*(uint32_t*)&lp0, *(uint32_t*)&lp1);
}

__global__ __launch_bounds__(256) void cvt_split_kernel(
    const float* __restrict__ src, __nv_bfloat16* __restrict__ hi,
    __nv_bfloat16* __restrict__ lo, int n4)
{
    int i = blockIdx.x * blockDim.x + threadIdx.x;
    if (i >= n4) return;
    uint2 hv, lv;
    split4(((const float4*)src)[i], hv, lv);
    *(uint2*)&hi[i * 4] = hv;
    *(uint2*)&lo[i * 4] = lv;
}

// 4 weight matrices in one launch (grid.y selects matrix)
__global__ __launch_bounds__(256) void cvt_split4_kernel(
    const float* s0, const float* s1, const float* s2, const float* s3,
    __nv_bfloat16* hi, __nv_bfloat16* lo,
    int n4_0, int n4_1, int n4_2, int n4_3)
{
    const float* srcs[4] = {s0, s1, s2, s3};
    int n4s[4]  = {n4_0, n4_1, n4_2, n4_3};
    int offs[4] = {0, 65536, 131072, 196608};
    int m = blockIdx.y;
    int i = blockIdx.x * blockDim.x + threadIdx.x;
    if (i >= n4s[m]) return;
    uint2 hv, lv;
    split4(((const float4*)srcs[m])[i], hv, lv);
    *(uint2*)&hi[offs[m] + i * 4] = hv;
    *(uint2*)&lo[offs[m] + i * 4] = lv;
}

// ================= tensor-core GEMM (cp.async double-buffered) ===============
#define ST_A_HI 0
#define ST_A_LO 10240
#define ST_B_HI 20480
#define ST_B_LO 29184
#define ST_SIZE 37888
#define GSMEM_TOT (2 * ST_SIZE)

template <int NW>  // NW: W row width
__device__ __forceinline__ void gemm_core(
    const __nv_bfloat16* __restrict__ aHi, const __nv_bfloat16* __restrict__ aLo,
    const __nv_bfloat16* __restrict__ wHi, const __nv_bfloat16* __restrict__ wLo,
    int K, int r0, int c0, uint32_t sb, float acc[2][8][4])
{
    const int t    = threadIdx.x;
    const int lane = t & 31;
    const int wid  = t >> 5;
    const int wm   = wid & 3;
    const int wn   = wid >> 2;

    const int aRow = lane & 15;
    const int aCol = (lane >> 4) * 8;
    const int bK   = lane & 15;
    const int bN   = (lane >> 4) * 8;

    const int nChunks = K >> 5;

    auto stage = [&](int c, int buf) {
        uint32_t st = sb + buf * ST_SIZE;
        int kc = c << 5;
#pragma unroll
        for (int it = 0; it < 2; ++it) {
            int fid = t + it * 256;
            int row = fid >> 2;
            int col = (fid & 3) * 8;
            int rg  = r0 + row;
            int ok  = (rg < N_NODES) ? 16 : 0;
            int rc  = (rg < N_NODES) ? rg : (N_NODES - 1);
            size_t gidx = (size_t)rc * K + kc + col;
            uint32_t d = st + row * 80 + col * 2;
            cp_async16(d + ST_A_HI, &aHi[gidx], ok);
            cp_async16(d + ST_A_LO, &aLo[gidx], ok);
        }
#pragma unroll
        for (int it = 0; it < 2; ++it) {
            int fid = t + it * 256;
            int kk  = fid >> 4;
            int n   = (fid & 15) * 8;
            size_t gidx = (size_t)(kc + kk) * NW + c0 + n;
            uint32_t d = st + kk * 272 + n * 2;
            cp_async16(d + ST_B_HI, &wHi[gidx], 16);
            cp_async16(d + ST_B_LO, &wLo[gidx], 16);
        }
        cp_commit();
    };

    stage(0, 0);
    for (int c = 0; c < nChunks; ++c) {
        bool more = (c + 1 < nChunks);
        if (more) stage(c + 1, (c + 1) & 1);
        if (more) asm volatile("cp.async.wait_group 1;" ::: "memory");
        else      asm volatile("cp.async.wait_group 0;" ::: "memory");
        __syncthreads();

        uint32_t st = sb + (c & 1) * ST_SIZE;
#pragma unroll
        for (int ks = 0; ks < 2; ++ks) {
            uint32_t aH[2][4], aL[2][4], bf[4][4];
#pragma unroll
            for (int mi = 0; mi < 2; ++mi) {
                uint32_t ar = st + (wm * 32 + mi * 16 + aRow) * 80 + (ks * 16 + aCol) * 2;
                ldsm_x4(aH[mi], ar + ST_A_HI);
                ldsm_x4(aL[mi], ar + ST_A_LO);
            }
#pragma unroll
            for (int pi = 0; pi < 4; ++pi)
                ldsm_x4_t(bf[pi], st + ST_B_HI + (ks * 16 + bK) * 272
                                     + (wn * 64 + pi * 16 + bN) * 2);
#pragma unroll
            for (int mi = 0; mi < 2; ++mi)
#pragma unroll
                for (int pi = 0; pi < 4; ++pi) {
                    mma16816(acc[mi][2 * pi],     aH[mi], &bf[pi][0]);
                    mma16816(acc[mi][2 * pi + 1], aH[mi], &bf[pi][2]);
                }
#pragma unroll
            for (int mi = 0; mi < 2; ++mi)
#pragma unroll
                for (int pi = 0; pi < 4; ++pi) {
                    mma16816(acc[mi][2 * pi],     aL[mi], &bf[pi][0]);
                    mma16816(acc[mi][2 * pi + 1], aL[mi], &bf[pi][2]);
                }
#pragma unroll
            for (int pi = 0; pi < 4; ++pi)
                ldsm_x4_t(bf[pi], st + ST_B_LO + (ks * 16 + bK) * 272
                                     + (wn * 64 + pi * 16 + bN) * 2);
#pragma unroll
            for (int mi = 0; mi < 2; ++mi)
#pragma unroll
                for (int pi = 0; pi < 4; ++pi) {
                    mma16816(acc[mi][2 * pi],     aH[mi], &bf[pi][0]);
                    mma16816(acc[mi][2 * pi + 1], aH[mi], &bf[pi][2]);
                }
        }
        __syncthreads();
    }
}

// ---- merged q/k/v(/skip) GEMM -------------------------------------------------
// SK256=1 (layer 1): y in [0,7], gi = y>>1 incl. skip width 256.
// SK256=0 (layer 2): y in [0,6]; y==6 -> skip GEMM width 128 (c0=0).
template <int SK256>
__global__ __launch_bounds__(256) void gemm_qkvs_kernel(
    const __nv_bfloat16* __restrict__ aHi, const __nv_bfloat16* __restrict__ aLo,
    const float* __restrict__ b0, const float* __restrict__ b1,
    const float* __restrict__ b2, const float* __restrict__ b3,
    float* __restrict__ Yq, __nv_bfloat16* __restrict__ Ykv,
    float* __restrict__ Ys, int K)
{
    extern __shared__ __align__(16) char smem[];
    const uint32_t sb = smem_u32(smem);
    const int r0 = blockIdx.x * 128;

    const int lane = threadIdx.x & 31;
    const int wid  = threadIdx.x >> 5;
    const int wm   = wid & 3;
    const int wn   = wid >> 2;

    if (!SK256 && blockIdx.y == 6) {
        // layer-2 skip GEMM: W width 128
        float acc[2][8][4] = {};
        gemm_core<128>(aHi, aLo, g_whi + 196608, g_wlo + 196608, K, r0, 0, sb, acc);
#pragma unroll
        for (int mi = 0; mi < 2; ++mi) {
            int rA = r0 + wm * 32 + mi * 16 + (lane >> 2);
            int rB = rA + 8;
#pragma unroll
            for (int ni = 0; ni < 8; ++ni) {
                int cc  = wn * 64 + ni * 8 + (lane & 3) * 2;
                float2 bv = *(const float2*)&b3[cc];
                if (rA < N_NODES)
                    *(float2*)&Ys[(size_t)rA * 128 + cc] =
                        make_float2(acc[mi][ni][0] + bv.x, acc[mi][ni][1] + bv.y);
                if (rB < N_NODES)
                    *(float2*)&Ys[(size_t)rB * 128 + cc] =
                        make_float2(acc[mi][ni][2] + bv.x, acc[mi][ni][3] + bv.y);
            }
        }
        return;
    }

    const int gi = blockIdx.y >> 1;
    const int c0 = (blockIdx.y & 1) * 128;

    const __nv_bfloat16* wHi = g_whi + gi * 65536;
    const __nv_bfloat16* wLo = g_wlo + gi * 65536;
    const float* bias = (gi == 0) ? b0 : (gi == 1) ? b1 : (gi == 2) ? b2 : b3;

    float acc[2][8][4] = {};
    gemm_core<256>(aHi, aLo, wHi, wLo, K, r0, c0, sb, acc);

#pragma unroll
    for (int mi = 0; mi < 2; ++mi) {
        int rA = r0 + wm * 32 + mi * 16 + (lane >> 2);
        int rB = rA + 8;
#pragma unroll
        for (int ni = 0; ni < 8; ++ni) {
            int cc  = c0 + wn * 64 + ni * 8 + (lane & 3) * 2;
            float2 bv = *(const float2*)&bias[cc];
            float x0 = acc[mi][ni][0] + bv.x, y0 = acc[mi][ni][1] + bv.y;
            float x1 = acc[mi][ni][2] + bv.x, y1 = acc[mi][ni][3] + bv.y;
            if (gi == 1 || gi == 2) {
                int kcol = cc + ((gi == 2) ? 256 : 0);
                if (rA < N_NODES)
                    *(__nv_bfloat162*)&Ykv[(size_t)rA * 512 + kcol] =
                        __floats2bfloat162_rn(x0, y0);
                if (rB < N_NODES)
                    *(__nv_bfloat162*)&Ykv[(size_t)rB * 512 + kcol] =
                        __floats2bfloat162_rn(x1, y1);
            } else {
                float* Y = (gi == 0) ? Yq : Ys;
                if (rA < N_NODES)
                    *(float2*)&Y[(size_t)rA * 256 + cc] = make_float2(x0, y0);
                if (rB < N_NODES)
                    *(float2*)&Y[(size_t)rB * 256 + cc] = make_float2(x1, y1);
            }
        }
    }
}

// =============== init + CSR build =============================================
__global__ __launch_bounds__(256) void init_zero_kernel(float* __restrict__ out) {
    int i = blockIdx.x * blockDim.x + threadIdx.x;
    if (i < N_GRAPHS * 128) out[i] = 0.f;
    if (i < N_NODES) g_wof[i] = 0;
    if (i < N_GRAPHS) g_cnt[i] = 0.f;
}

__global__ __launch_bounds__(256) void hist_kernel(const int* __restrict__ ei) {
    int e = blockIdx.x * blockDim.x + threadIdx.x;
    if (e < N_EDGES) atomicAdd(&g_wof[ei[N_EDGES + e]], 1);
}

__global__ __launch_bounds__(256) void scan1_kernel() {
    __shared__ int sb[2][256];
    int t = threadIdx.x;
    int i = blockIdx.x * 256 + t;
    int v = (i < N_NODES) ? g_wof[i] : 0;
    int pin = 0;
    sb[0][t] = v;
    __syncthreads();
#pragma unroll
    for (int off = 1; off < 256; off <<= 1) {
        int x = sb[pin][t];
        if (t >= off) x += sb[pin][t - off];
        sb[pin ^ 1][t] = x;
        __syncthreads();
        pin ^= 1;
    }
    int incl = sb[pin][t];
    if (i < N_NODES) g_rowptr[i] = incl - v;
    if (t == 255) g_bsum[blockIdx.x] = incl;
}

__global__ __launch_bounds__(256) void scan3_kernel() {
    __shared__ int sp[8];
    int t = threadIdx.x;
    int bid = blockIdx.x;
    int part = 0;
    for (int j = t; j < bid; j += 256) part += g_bsum[j];
#pragma unroll
    for (int o = 16; o; o >>= 1) part += __shfl_xor_sync(0xffffffffu, part, o);
    if ((t & 31) == 0) sp[t >> 5] = part;
    __syncthreads();
    if (t == 0) {
        int s = 0;
#pragma unroll
        for (int w = 0; w < 8; ++w) s += sp[w];
        sp[0] = s;
        if (bid == 0) g_rowptr[N_NODES] = N_EDGES;
    }
    __syncthreads();
    int off = sp[0];
    int i = bid * 256 + t;
    if (i < N_NODES) {
        int r = g_rowptr[i] + off;
        g_rowptr[i] = r;
        g_wof[i]    = r;
    }
}

__global__ __launch_bounds__(256) void csr_scatter_kernel(
    const int* __restrict__ ei, const float* __restrict__ ea)
{
    int e = blockIdx.x * blockDim.x + threadIdx.x;
    if (e >= N_EDGES) return;
    int src = ei[e];
    int dst = ei[N_EDGES + e];
    int pos = atomicAdd(&g_wof[dst], 1);
    g_csrc[pos] = src;
    g_cw[pos]   = ea[e];
}

// =============== per-node attention ===========================================
// CONCAT=1: writes hi/lo bf16 split of relu(attn+skip) [N,256]
// CONCAT=0: pools (mean_heads + skip) directly into out[graph] via atomics
template <int CONCAT>
__global__ __launch_bounds__(256, 3) void node_attn_kernel(
    const float* __restrict__ q, const __nv_bfloat16* __restrict__ kv,
    const float* __restrict__ skip, const float* __restrict__ We,
    const int* __restrict__ batch, float* __restrict__ out,
    __nv_bfloat16* __restrict__ ohi, __nv_bfloat16* __restrict__ olo)
{
    int n = blockIdx.x * 8 + (threadIdx.x >> 5);
    if (n >= N_NODES) return;
    int lane = threadIdx.x & 31;
    int beg = g_rowptr[n], end = g_rowptr[n + 1];

    const float scale = 0.08838834764831845f;   // 1/sqrt(128)

    float qv[8], ev[8];
    {
        const float* qr = q + (size_t)n * 256 + lane * 8;
        *(float4*)&qv[0] = *(const float4*)(qr);
        *(float4*)&qv[4] = *(const float4*)(qr + 4);
        *(float4*)&ev[0] = *(const float4*)(We + lane * 8);
        *(float4*)&ev[4] = *(const float4*)(We + lane * 8 + 4);
    }
    float qe = 0.f;
#pragma unroll
    for (int i = 0; i < 8; ++i) qe = fmaf(qv[i], ev[i], qe);
#pragma unroll
    for (int o = 8; o; o >>= 1) qe += __shfl_xor_sync(0xffffffffu, qe, o);
    qe *= scale;

    float d = 0.f, cw = 0.f;
    float a[8] = {};

    int p = beg;
    // prefetched indices for the next pair
    int  nsa = 0, nsb = 0;
    float nwa = 0.f, nwb = 0.f;
    if (p + 1 < end) {
        nsa = g_csrc[p];     nwa = g_cw[p];
        nsb = g_csrc[p + 1]; nwb = g_cw[p + 1];
    }
    for (; p + 1 < end; p += 2) {
        int  sa = nsa,  sb = nsb;
        float wa = nwa, wb = nwb;
        if (p + 3 < end) {
            nsa = g_csrc[p + 2]; nwa = g_cw[p + 2];
            nsb = g_csrc[p + 3]; nwb = g_cw[p + 3];
        }
        const uint4* ra = (const uint4*)(kv + (size_t)sa * 512);
        const uint4* rb = (const uint4*)(kv + (size_t)sb * 512);
        uint4 kua = ra[lane], kub = rb[lane];
        uint4 vua = ra[32 + lane], vub = rb[32 + lane];

        float kfa[8], kfb[8];
        bf8_to_f(kua, kfa);
        bf8_to_f(kub, kfb);
        float ta = 0.f, tb = 0.f;
#pragma unroll
        for (int i = 0; i < 8; ++i) {
            ta = fmaf(qv[i], kfa[i], ta);
            tb = fmaf(qv[i], kfb[i], tb);
        }
#pragma unroll
        for (int o = 8; o; o >>= 1) {
            ta += __shfl_xor_sync(0xffffffffu, ta, o);
            tb += __shfl_xor_sync(0xffffffffu, tb, o);
        }
        float xa = __expf(fmaf(wa, qe, ta * scale));
        float xb = __expf(fmaf(wb, qe, tb * scale));
        d  += xa + xb;
        cw += xa * wa + xb * wb;
        float vfa[8], vfb[8];
        bf8_to_f(vua, vfa);
        bf8_to_f(vub, vfb);
#pragma unroll
        for (int i = 0; i < 8; ++i)
            a[i] += xa * vfa[i] + xb * vfb[i];
    }
    for (; p < end; ++p) {
        int s = g_csrc[p];
        float w = g_cw[p];
        const uint4* r = (const uint4*)(kv + (size_t)s * 512);
        uint4 ku = r[lane], vu = r[32 + lane];
        float kf[8];
        bf8_to_f(ku, kf);
        float t = 0.f;
#pragma unroll
        for (int i = 0; i < 8; ++i) t = fmaf(qv[i], kf[i], t);
#pragma unroll
        for (int o = 8; o; o >>= 1) t += __shfl_xor_sync(0xffffffffu, t, o);
        float x = __expf(fmaf(w, qe, t * scale));
        d += x; cw += x * w;
        float vf[8];
        bf8_to_f(vu, vf);
#pragma unroll
        for (int i = 0; i < 8; ++i) a[i] += x * vf[i];
    }

    float r = d > 0.f ? 1.f / d : 0.f;
    float o8[8];
#pragma unroll
    for (int i = 0; i < 8; ++i) o8[i] = (a[i] + cw * ev[i]) * r;

    if (CONCAT) {
        float sk[8];
        const float* sr = skip + (size_t)n * 256 + lane * 8;
        *(float4*)&sk[0] = *(const float4*)(sr);
        *(float4*)&sk[4] = *(const float4*)(sr + 4);
        __align__(16) __nv_bfloat16 hb[8], lb[8];
#pragma unroll
        for (int i = 0; i < 8; ++i) {
            float o = fmaxf(o8[i] + sk[i], 0.f);
            hb[i] = __float2bfloat16(o);
            lb[i] = __float2bfloat16(o - __bfloat162float(hb[i]));
        }
        *(uint4*)&ohi[(size_t)n * 256 + lane * 8] = *(uint4*)hb;
        *(uint4*)&olo[(size_t)n * 256 + lane * 8] = *(uint4*)lb;
    } else {
        // mean over heads (partner lane = lane ^ 16), + skip, pool into out[graph]
        float m[8];
#pragma unroll
        for (int i = 0; i < 8; ++i) {
            float other = __shfl_xor_sync(0xffffffffu, o8[i], 16);
            m[i] = 0.5f * (o8[i] + other);
        }
        int g = batch[n];
        if (lane < 16) {
            const float* sr = skip + (size_t)n * 128 + lane * 8;
            float4 s0 = *(const float4*)(sr);
            float4 s1 = *(const float4*)(sr + 4);
            float h0 = m[0] + s0.x, h1 = m[1] + s0.y, h2 = m[2] + s0.z, h3 = m[3] + s0.w;
            float h4 = m[4] + s1.x, h5 = m[5] + s1.y, h6 = m[6] + s1.z, h7 = m[7] + s1.w;
            float* dst = out + (size_t)g * 128 + lane * 8;
            atomicAdd(dst + 0, h0); atomicAdd(dst + 1, h1);
            atomicAdd(dst + 2, h2); atomicAdd(dst + 3, h3);
            atomicAdd(dst + 4, h4); atomicAdd(dst + 5, h5);
            atomicAdd(dst + 6, h6); atomicAdd(dst + 7, h7);
        }
        if (lane == 0) atomicAdd(&g_cnt[g], 1.f);
    }
}

// =============== pooling finish ================================================
__global__ __launch_bounds__(256) void pool_div_kernel(float* __restrict__ out) {
    int i = blockIdx.x * blockDim.x + threadIdx.x;
    if (i >= N_GRAPHS * 128) return;
    out[i] /= fmaxf(g_cnt[i >> 7], 1.f);
}

// =============== launch =========================================================
extern "C" void kernel_launch(void* const* d_in, const int* in_sizes, int n_in,
                              void* d_out, int out_size)
{
    const float* x     = (const float*)d_in[0];
    const int*   ei    = (const int*)d_in[1];
    const int*   batch = (const int*)d_in[2];
    const float* ea    = (const float*)d_in[3];
    const float* Wq1 = (const float*)d_in[4];
    const float* bq1 = (const float*)d_in[5];
    const float* Wk1 = (const float*)d_in[6];
    const float* bk1 = (const float*)d_in[7];
    const float* Wv1 = (const float*)d_in[8];
    const float* bv1 = (const float*)d_in[9];
    const float* We1 = (const float*)d_in[10];
    const float* Ws1 = (const float*)d_in[11];
    const float* bs1 = (const float*)d_in[12];
    const float* Wq2 = (const float*)d_in[13];
    const float* bq2 = (const float*)d_in[14];
    const float* Wk2 = (const float*)d_in[15];
    const float* bk2 = (const float*)d_in[16];
    const float* Wv2 = (const float*)d_in[17];
    const float* bv2 = (const float*)d_in[18];
    const float* We2 = (const float*)d_in[19];
    const float* Ws2 = (const float*)d_in[20];
    const float* bs2 = (const float*)d_in[21];
    float* out = (float*)d_out;

    float *pq, *pskip;
    __nv_bfloat16 *pkv, *pahi, *palo, *pwhi, *pwlo;
    cudaGetSymbolAddress((void**)&pq,    g_q);
    cudaGetSymbolAddress((void**)&pskip, g_skip);
    cudaGetSymbolAddress((void**)&pkv,   g_kv);
    cudaGetSymbolAddress((void**)&pahi,  g_ahi);
    cudaGetSymbolAddress((void**)&palo,  g_alo);
    cudaGetSymbolAddress((void**)&pwhi,  g_whi);
    cudaGetSymbolAddress((void**)&pwlo,  g_wlo);

    cudaFuncSetAttribute(gemm_qkvs_kernel<1>,
                         cudaFuncAttributeMaxDynamicSharedMemorySize, GSMEM_TOT);
    cudaFuncSetAttribute(gemm_qkvs_kernel<0>,
                         cudaFuncAttributeMaxDynamicSharedMemorySize, GSMEM_TOT);

    // side stream + events (created once, before any capture; reused every call)
    static cudaStream_t s1 = nullptr;
    static cudaEvent_t evFork = nullptr, evCSR = nullptr, evG1 = nullptr, evW2 = nullptr;
    if (s1 == nullptr) {
        cudaStreamCreateWithFlags(&s1, cudaStreamNonBlocking);
        cudaEventCreateWithFlags(&evFork, cudaEventDisableTiming);
        cudaEventCreateWithFlags(&evCSR,  cudaEventDisableTiming);
        cudaEventCreateWithFlags(&evG1,   cudaEventDisableTiming);
        cudaEventCreateWithFlags(&evW2,   cudaEventDisableTiming);
    }

    const int RT  = (N_NODES + 127) / 128;            // 391 row tiles
    const int EB  = (N_EDGES + 255) / 256;
    const int NB  = (N_NODES + 255) / 256;            // 196
    const int NWB = (N_NODES + 7) / 8;
    const int PZ  = (N_GRAPHS * 128 + 255) / 256;     // 1250

    // ---- fork: CSR build on side stream, overlapped with cvt+GEMM1 ----
    cudaEventRecord(evFork, 0);
    cudaStreamWaitEvent(s1, evFork, 0);

    init_zero_kernel<<<PZ, 256, 0, s1>>>(out);
    hist_kernel<<<EB, 256, 0, s1>>>(ei);
    scan1_kernel<<<NB, 256, 0, s1>>>();
    scan3_kernel<<<NB, 256, 0, s1>>>();
    csr_scatter_kernel<<<EB, 256, 0, s1>>>(ei, ea);
    cudaEventRecord(evCSR, s1);

    // ---- main stream: layer 1 cvt + merged GEMM ----
    cvt_split_kernel<<<(N_NODES * 128 / 4 + 255) / 256, 256>>>(x, pahi, palo, N_NODES * 128 / 4);
    cvt_split4_kernel<<<dim3(8192 / 256, 4), 256>>>(Wq1, Wk1, Wv1, Ws1,
                                                    pwhi, pwlo, 8192, 8192, 8192, 8192);
    gemm_qkvs_kernel<1><<<dim3(RT, 8), 256, GSMEM_TOT>>>(
        pahi, palo, bq1, bk1, bv1, bs1, pq, pkv, pskip, 128);
    cudaEventRecord(evG1, 0);

    // side stream: layer-2 weight conversion (after gemm1 done reading W bufs)
    cudaStreamWaitEvent(s1, evG1, 0);
    cvt_split4_kernel<<<dim3(16384 / 256, 4), 256, 0, s1>>>(Wq2, Wk2, Wv2, Ws2,
                                                            pwhi, pwlo, 16384, 16384, 16384, 8192);
    cudaEventRecord(evW2, s1);

    // main stream: attention layer 1 (needs CSR)
    cudaStreamWaitEvent(0, evCSR, 0);
    node_attn_kernel<1><<<NWB, 256>>>(pq, pkv, pskip, We1, batch, nullptr, pahi, palo);

    // ---- layer 2 (needs W2 conversion) ----
    cudaStreamWaitEvent(0, evW2, 0);
    gemm_qkvs_kernel<0><<<dim3(RT, 7), 256, GSMEM_TOT>>>(
        pahi, palo, bq2, bk2, bv2, bs2, pq, pkv, pskip, 256);
    node_attn_kernel<0><<<NWB, 256>>>(pq, pkv, pskip, We2, batch, out, nullptr, nullptr);

    // ---- pool finish ----
    pool_div_kernel<<<PZ, 256>>>(out);
}

// round 15
// speedup vs baseline: 1.5891x; 1.1605x over previous
#include <cuda_runtime.h>
#include <cuda_fp16.h>
#include <math.h>
#include <stdint.h>

#define N_NODES  50000
#define N_EDGES  800000
#define N_GRAPHS 2500

// ---------------- scratch (device globals; no allocations allowed) ----------
__device__ __align__(256) float g_q[N_NODES * 256];
__device__ __align__(256) float g_skip[N_NODES * 256];
__device__ __align__(256) float g_cw[N_EDGES];
__device__ __align__(256) int   g_csrc[N_EDGES];
__device__ __align__(256) int   g_rowptr[N_NODES + 1];
__device__ __align__(256) int   g_wof[N_NODES];
__device__ __align__(256) int   g_bsum[256];
__device__ __align__(256) float g_cnt[N_GRAPHS];
// fp16 operands
__device__ __align__(256) __half g_kv[N_NODES * 512];   // [k(256) | v(256)]
__device__ __align__(256) __half g_ahi[N_NODES * 256];
__device__ __align__(256) __half g_alo[N_NODES * 256];
__device__ __align__(256) __half g_whi[262144];
__device__ __align__(256) __half g_wlo[262144];

// ================= warp-MMA helpers ==========================================
__device__ __forceinline__ uint32_t smem_u32(const void* p) {
    uint32_t a;
    asm("{ .reg .u64 t; cvta.to.shared.u64 t, %1; cvt.u32.u64 %0, t; }"
        : "=r"(a) : "l"(p));
    return a;
}

__device__ __forceinline__ void ldsm_x4(uint32_t r[4], uint32_t addr) {
    asm volatile("ldmatrix.sync.aligned.m8n8.x4.shared.b16 {%0,%1,%2,%3}, [%4];"
        : "=r"(r[0]), "=r"(r[1]), "=r"(r[2]), "=r"(r[3]) : "r"(addr));
}
__device__ __forceinline__ void ldsm_x4_t(uint32_t r[4], uint32_t addr) {
    asm volatile("ldmatrix.sync.aligned.m8n8.x4.trans.shared.b16 {%0,%1,%2,%3}, [%4];"
        : "=r"(r[0]), "=r"(r[1]), "=r"(r[2]), "=r"(r[3]) : "r"(addr));
}

__device__ __forceinline__ void mma16816(float d[4], const uint32_t a[4],
                                         const uint32_t b[2]) {
    asm volatile(
        "mma.sync.aligned.m16n8k16.row.col.f32.f16.f16.f32 "
        "{%0,%1,%2,%3}, {%4,%5,%6,%7}, {%8,%9}, {%0,%1,%2,%3};"
        : "+f"(d[0]), "+f"(d[1]), "+f"(d[2]), "+f"(d[3])
        : "r"(a[0]), "r"(a[1]), "r"(a[2]), "r"(a[3]), "r"(b[0]), "r"(b[1]));
}

__device__ __forceinline__ void cp_async16(uint32_t dst, const void* src, int sz) {
    asm volatile("cp.async.cg.shared.global [%0], [%1], 16, %2;"
        :: "r"(dst), "l"(src), "r"(sz));
}
__device__ __forceinline__ void cp_commit() {
    asm volatile("cp.async.commit_group;" ::: "memory");
}

__device__ __forceinline__ void hf8_to_f(const uint4& u, float* f) {
    float2 p;
    p = __half22float2(*(const __half2*)&u.x); f[0] = p.x; f[1] = p.y;
    p = __half22float2(*(const __half2*)&u.y); f[2] = p.x; f[3] = p.y;
    p = __half22float2(*(const __half2*)&u.z); f[4] = p.x; f[5] = p.y;
    p = __half22float2(*(const __half2*)&u.w); f[6] = p.x; f[7] = p.y;
}

// =============== fp32 -> fp16 hi/lo split ======================================
__device__ __forceinline__ void split4(float4 v, uint2& hv, uint2& lv) {
    __half h0 = __float2half_rn(v.x);
    __half h1 = __float2half_rn(v.y);
    __half h2 = __float2half_rn(v.z);
    __half h3 = __float2half_rn(v.w);
    __half l0 = __float2half_rn(v.x - __half2float(h0));
    __half l1 = __float2half_rn(v.y - __half2float(h1));
    __half l2 = __float2half_rn(v.z - __half2float(h2));
    __half l3 = __float2half_rn(v.w - __half2float(h3));
    __half2 hp0 = __halves2half2(h0, h1);
    __half2 hp1 = __halves2half2(h2, h3);
    __half2 lp0 = __halves2half2(l0, l1);
    __half2 lp1 = __halves2half2(l2, l3);
    hv = make_uint2(*(uint32_t*)&hp0, *(uint32_t*)&hp1);
    lv = make_uint2(*(uint32_t*)&lp0, *(uint32_t*)&lp1);
}

__global__ __launch_bounds__(256) void cvt_split_kernel(
    const float* __restrict__ src, __half* __restrict__ hi,
    __half* __restrict__ lo, int n4)
{
    int i = blockIdx.x * blockDim.x + threadIdx.x;
    if (i >= n4) return;
    uint2 hv, lv;
    split4(((const float4*)src)[i], hv, lv);
    *(uint2*)&hi[i * 4] = hv;
    *(uint2*)&lo[i * 4] = lv;
}

// 4 weight matrices in one launch (grid.y selects matrix)
__global__ __launch_bounds__(256) void cvt_split4_kernel(
    const float* s0, const float* s1, const float* s2, const float* s3,
    __half* hi, __half* lo,
    int n4_0, int n4_1, int n4_2, int n4_3)
{
    const float* srcs[4] = {s0, s1, s2, s3};
    int n4s[4]  = {n4_0, n4_1, n4_2, n4_3};
    int offs[4] = {0, 65536, 131072, 196608};
    int m = blockIdx.y;
    int i = blockIdx.x * blockDim.x + threadIdx.x;
    if (i >= n4s[m]) return;
    uint2 hv, lv;
    split4(((const float4*)srcs[m])[i], hv, lv);
    *(uint2*)&hi[offs[m] + i * 4] = hv;
    *(uint2*)&lo[offs[m] + i * 4] = lv;
}

// ================= tensor-core GEMM (cp.async double-buffered) ===============
// 2-term fp16 split: D = Ah*Bh + Al*Bh  (dropped A*Bl term ~2^-11 relative)
#define ST_A_HI 0
#define ST_A_LO 10240
#define ST_B_HI 20480
#define ST_SIZE 29184
#define GSMEM_TOT (2 * ST_SIZE)

template <int NW>  // NW: W row width
__device__ __forceinline__ void gemm_core(
    const __half* __restrict__ aHi, const __half* __restrict__ aLo,
    const __half* __restrict__ wHi,
    int K, int r0, int c0, uint32_t sb, float acc[2][8][4])
{
    const int t    = threadIdx.x;
    const int lane = t & 31;
    const int wid  = t >> 5;
    const int wm   = wid & 3;
    const int wn   = wid >> 2;

    const int aRow = lane & 15;
    const int aCol = (lane >> 4) * 8;
    const int bK   = lane & 15;
    const int bN   = (lane >> 4) * 8;

    const int nChunks = K >> 5;

    auto stage = [&](int c, int buf) {
        uint32_t st = sb + buf * ST_SIZE;
        int kc = c << 5;
#pragma unroll
        for (int it = 0; it < 2; ++it) {
            int fid = t + it * 256;
            int row = fid >> 2;
            int col = (fid & 3) * 8;
            int rg  = r0 + row;
            int ok  = (rg < N_NODES) ? 16 : 0;
            int rc  = (rg < N_NODES) ? rg : (N_NODES - 1);
            size_t gidx = (size_t)rc * K + kc + col;
            uint32_t d = st + row * 80 + col * 2;
            cp_async16(d + ST_A_HI, &aHi[gidx], ok);
            cp_async16(d + ST_A_LO, &aLo[gidx], ok);
        }
#pragma unroll
        for (int it = 0; it < 2; ++it) {
            int fid = t + it * 256;
            int kk  = fid >> 4;
            int n   = (fid & 15) * 8;
            size_t gidx = (size_t)(kc + kk) * NW + c0 + n;
            uint32_t d = st + kk * 272 + n * 2;
            cp_async16(d + ST_B_HI, &wHi[gidx], 16);
        }
        cp_commit();
    };

    stage(0, 0);
    for (int c = 0; c < nChunks; ++c) {
        bool more = (c + 1 < nChunks);
        if (more) stage(c + 1, (c + 1) & 1);
        if (more) asm volatile("cp.async.wait_group 1;" ::: "memory");
        else      asm volatile("cp.async.wait_group 0;" ::: "memory");
        __syncthreads();

        uint32_t st = sb + (c & 1) * ST_SIZE;
#pragma unroll
        for (int ks = 0; ks < 2; ++ks) {
            uint32_t aH[2][4], aL[2][4], bf[4][4];
#pragma unroll
            for (int mi = 0; mi < 2; ++mi) {
                uint32_t ar = st + (wm * 32 + mi * 16 + aRow) * 80 + (ks * 16 + aCol) * 2;
                ldsm_x4(aH[mi], ar + ST_A_HI);
                ldsm_x4(aL[mi], ar + ST_A_LO);
            }
#pragma unroll
            for (int pi = 0; pi < 4; ++pi)
                ldsm_x4_t(bf[pi], st + ST_B_HI + (ks * 16 + bK) * 272
                                     + (wn * 64 + pi * 16 + bN) * 2);
#pragma unroll
            for (int mi = 0; mi < 2; ++mi)
#pragma unroll
                for (int pi = 0; pi < 4; ++pi) {
                    mma16816(acc[mi][2 * pi],     aH[mi], &bf[pi][0]);
                    mma16816(acc[mi][2 * pi + 1], aH[mi], &bf[pi][2]);
                }
#pragma unroll
            for (int mi = 0; mi < 2; ++mi)
#pragma unroll
                for (int pi = 0; pi < 4; ++pi) {
                    mma16816(acc[mi][2 * pi],     aL[mi], &bf[pi][0]);
                    mma16816(acc[mi][2 * pi + 1], aL[mi], &bf[pi][2]);
                }
        }
        __syncthreads();
    }
}

// ---- merged q/k/v(/skip) GEMM -------------------------------------------------
// SK256=1 (layer 1): y in [0,7], gi = y>>1 incl. skip width 256.
// SK256=0 (layer 2): y in [0,6]; y==6 -> skip GEMM width 128 (c0=0).
template <int SK256>
__global__ __launch_bounds__(256) void gemm_qkvs_kernel(
    const __half* __restrict__ aHi, const __half* __restrict__ aLo,
    const float* __restrict__ b0, const float* __restrict__ b1,
    const float* __restrict__ b2, const float* __restrict__ b3,
    float* __restrict__ Yq, __half* __restrict__ Ykv,
    float* __restrict__ Ys, int K)
{
    extern __shared__ __align__(16) char smem[];
    const uint32_t sb = smem_u32(smem);
    const int r0 = blockIdx.x * 128;

    const int lane = threadIdx.x & 31;
    const int wid  = threadIdx.x >> 5;
    const int wm   = wid & 3;
    const int wn   = wid >> 2;

    if (!SK256 && blockIdx.y == 6) {
        // layer-2 skip GEMM: W width 128
        float acc[2][8][4] = {};
        gemm_core<128>(aHi, aLo, g_whi + 196608, K, r0, 0, sb, acc);
#pragma unroll
        for (int mi = 0; mi < 2; ++mi) {
            int rA = r0 + wm * 32 + mi * 16 + (lane >> 2);
            int rB = rA + 8;
#pragma unroll
            for (int ni = 0; ni < 8; ++ni) {
                int cc  = wn * 64 + ni * 8 + (lane & 3) * 2;
                float2 bv = *(const float2*)&b3[cc];
                if (rA < N_NODES)
                    *(float2*)&Ys[(size_t)rA * 128 + cc] =
                        make_float2(acc[mi][ni][0] + bv.x, acc[mi][ni][1] + bv.y);
                if (rB < N_NODES)
                    *(float2*)&Ys[(size_t)rB * 128 + cc] =
                        make_float2(acc[mi][ni][2] + bv.x, acc[mi][ni][3] + bv.y);
            }
        }
        return;
    }

    const int gi = blockIdx.y >> 1;
    const int c0 = (blockIdx.y & 1) * 128;

    const __half* wHi = g_whi + gi * 65536;
    const float* bias = (gi == 0) ? b0 : (gi == 1) ? b1 : (gi == 2) ? b2 : b3;

    float acc[2][8][4] = {};
    gemm_core<256>(aHi, aLo, wHi, K, r0, c0, sb, acc);

#pragma unroll
    for (int mi = 0; mi < 2; ++mi) {
        int rA = r0 + wm * 32 + mi * 16 + (lane >> 2);
        int rB = rA + 8;
#pragma unroll
        for (int ni = 0; ni < 8; ++ni) {
            int cc  = c0 + wn * 64 + ni * 8 + (lane & 3) * 2;
            float2 bv = *(const float2*)&bias[cc];
            float x0 = acc[mi][ni][0] + bv.x, y0 = acc[mi][ni][1] + bv.y;
            float x1 = acc[mi][ni][2] + bv.x, y1 = acc[mi][ni][3] + bv.y;
            if (gi == 1 || gi == 2) {
                int kcol = cc + ((gi == 2) ? 256 : 0);
                if (rA < N_NODES)
                    *(__half2*)&Ykv[(size_t)rA * 512 + kcol] =
                        __floats2half2_rn(x0, y0);
                if (rB < N_NODES)
                    *(__half2*)&Ykv[(size_t)rB * 512 + kcol] =
                        __floats2half2_rn(x1, y1);
            } else {
                float* Y = (gi == 0) ? Yq : Ys;
                if (rA < N_NODES)
                    *(float2*)&Y[(size_t)rA * 256 + cc] = make_float2(x0, y0);
                if (rB < N_NODES)
                    *(float2*)&Y[(size_t)rB * 256 + cc] = make_float2(x1, y1);
            }
        }
    }
}

// =============== init + CSR build =============================================
__global__ __launch_bounds__(256) void init_zero_kernel(float* __restrict__ out) {
    int i = blockIdx.x * blockDim.x + threadIdx.x;
    if (i < N_GRAPHS * 128) out[i] = 0.f;
    if (i < N_NODES) g_wof[i] = 0;
    if (i < N_GRAPHS) g_cnt[i] = 0.f;
}

__global__ __launch_bounds__(256) void hist_kernel(const int* __restrict__ ei) {
    int e = blockIdx.x * blockDim.x + threadIdx.x;
    if (e < N_EDGES) atomicAdd(&g_wof[ei[N_EDGES + e]], 1);
}

__global__ __launch_bounds__(256) void scan1_kernel() {
    __shared__ int sb[2][256];
    int t = threadIdx.x;
    int i = blockIdx.x * 256 + t;
    int v = (i < N_NODES) ? g_wof[i] : 0;
    int pin = 0;
    sb[0][t] = v;
    __syncthreads();
#pragma unroll
    for (int off = 1; off < 256; off <<= 1) {
        int x = sb[pin][t];
        if (t >= off) x += sb[pin][t - off];
        sb[pin ^ 1][t] = x;
        __syncthreads();
        pin ^= 1;
    }
    int incl = sb[pin][t];
    if (i < N_NODES) g_rowptr[i] = incl - v;
    if (t == 255) g_bsum[blockIdx.x] = incl;
}

__global__ __launch_bounds__(256) void scan3_kernel() {
    __shared__ int sp[8];
    int t = threadIdx.x;
    int bid = blockIdx.x;
    int part = 0;
    for (int j = t; j < bid; j += 256) part += g_bsum[j];
#pragma unroll
    for (int o = 16; o; o >>= 1) part += __shfl_xor_sync(0xffffffffu, part, o);
    if ((t & 31) == 0) sp[t >> 5] = part;
    __syncthreads();
    if (t == 0) {
        int s = 0;
#pragma unroll
        for (int w = 0; w < 8; ++w) s += sp[w];
        sp[0] = s;
        if (bid == 0) g_rowptr[N_NODES] = N_EDGES;
    }
    __syncthreads();
    int off = sp[0];
    int i = bid * 256 + t;
    if (i < N_NODES) {
        int r = g_rowptr[i] + off;
        g_rowptr[i] = r;
        g_wof[i]    = r;
    }
}

__global__ __launch_bounds__(256) void csr_scatter_kernel(
    const int* __restrict__ ei, const float* __restrict__ ea)
{
    int e = blockIdx.x * blockDim.x + threadIdx.x;
    if (e >= N_EDGES) return;
    int src = ei[e];
    int dst = ei[N_EDGES + e];
    int pos = atomicAdd(&g_wof[dst], 1);
    g_csrc[pos] = src;
    g_cw[pos]   = ea[e];
}

// =============== per-node attention ===========================================
// CONCAT=1: writes hi/lo fp16 split of relu(attn+skip) [N,256]
// CONCAT=0: pools (mean_heads + skip) directly into out[graph] via atomics
template <int CONCAT>
__global__ __launch_bounds__(256, 3) void node_attn_kernel(
    const float* __restrict__ q, const __half* __restrict__ kv,
    const float* __restrict__ skip, const float* __restrict__ We,
    const int* __restrict__ batch, float* __restrict__ out,
    __half* __restrict__ ohi, __half* __restrict__ olo)
{
    int n = blockIdx.x * 8 + (threadIdx.x >> 5);
    if (n >= N_NODES) return;
    int lane = threadIdx.x & 31;
    int beg = g_rowptr[n], end = g_rowptr[n + 1];

    const float scale = 0.08838834764831845f;   // 1/sqrt(128)

    float qv[8], ev[8];
    {
        const float* qr = q + (size_t)n * 256 + lane * 8;
        *(float4*)&qv[0] = *(const float4*)(qr);
        *(float4*)&qv[4] = *(const float4*)(qr + 4);
        *(float4*)&ev[0] = *(const float4*)(We + lane * 8);
        *(float4*)&ev[4] = *(const float4*)(We + lane * 8 + 4);
    }
    float qe = 0.f;
#pragma unroll
    for (int i = 0; i < 8; ++i) qe = fmaf(qv[i], ev[i], qe);
#pragma unroll
    for (int o = 8; o; o >>= 1) qe += __shfl_xor_sync(0xffffffffu, qe, o);
    qe *= scale;

    float d = 0.f, cw = 0.f;
    float a[8] = {};

    int p = beg;
    // prefetched indices for the next pair
    int  nsa = 0, nsb = 0;
    float nwa = 0.f, nwb = 0.f;
    if (p + 1 < end) {
        nsa = g_csrc[p];     nwa = g_cw[p];
        nsb = g_csrc[p + 1]; nwb = g_cw[p + 1];
    }
    for (; p + 1 < end; p += 2) {
        int  sa = nsa,  sb = nsb;
        float wa = nwa, wb = nwb;
        if (p + 3 < end) {
            nsa = g_csrc[p + 2]; nwa = g_cw[p + 2];
            nsb = g_csrc[p + 3]; nwb = g_cw[p + 3];
        }
        const uint4* ra = (const uint4*)(kv + (size_t)sa * 512);
        const uint4* rb = (const uint4*)(kv + (size_t)sb * 512);
        uint4 kua = ra[lane], kub = rb[lane];
        uint4 vua = ra[32 + lane], vub = rb[32 + lane];

        float kfa[8], kfb[8];
        hf8_to_f(kua, kfa);
        hf8_to_f(kub, kfb);
        float ta = 0.f, tb = 0.f;
#pragma unroll
        for (int i = 0; i < 8; ++i) {
            ta = fmaf(qv[i], kfa[i], ta);
            tb = fmaf(qv[i], kfb[i], tb);
        }
#pragma unroll
        for (int o = 8; o; o >>= 1) {
            ta += __shfl_xor_sync(0xffffffffu, ta, o);
            tb += __shfl_xor_sync(0xffffffffu, tb, o);
        }
        float xa = __expf(fmaf(wa, qe, ta * scale));
        float xb = __expf(fmaf(wb, qe, tb * scale));
        d  += xa + xb;
        cw += xa * wa + xb * wb;
        float vfa[8], vfb[8];
        hf8_to_f(vua, vfa);
        hf8_to_f(vub, vfb);
#pragma unroll
        for (int i = 0; i < 8; ++i)
            a[i] += xa * vfa[i] + xb * vfb[i];
    }
    for (; p < end; ++p) {
        int s = g_csrc[p];
        float w = g_cw[p];
        const uint4* r = (const uint4*)(kv + (size_t)s * 512);
        uint4 ku = r[lane], vu = r[32 + lane];
        float kf[8];
        hf8_to_f(ku, kf);
        float t = 0.f;
#pragma unroll
        for (int i = 0; i < 8; ++i) t = fmaf(qv[i], kf[i], t);
#pragma unroll
        for (int o = 8; o; o >>= 1) t += __shfl_xor_sync(0xffffffffu, t, o);
        float x = __expf(fmaf(w, qe, t * scale));
        d += x; cw += x * w;
        float vf[8];
        hf8_to_f(vu, vf);
#pragma unroll
        for (int i = 0; i < 8; ++i) a[i] += x * vf[i];
    }

    float r = d > 0.f ? 1.f / d : 0.f;
    float o8[8];
#pragma unroll
    for (int i = 0; i < 8; ++i) o8[i] = (a[i] + cw * ev[i]) * r;

    if (CONCAT) {
        float sk[8];
        const float* sr = skip + (size_t)n * 256 + lane * 8;
        *(float4*)&sk[0] = *(const float4*)(sr);
        *(float4*)&sk[4] = *(const float4*)(sr + 4);
        __align__(16) __half hb[8], lb[8];
#pragma unroll
        for (int i = 0; i < 8; ++i) {
            float o = fmaxf(o8[i] + sk[i], 0.f);
            hb[i] = __float2half_rn(o);
            lb[i] = __float2half_rn(o - __half2float(hb[i]));
        }
        *(uint4*)&ohi[(size_t)n * 256 + lane * 8] = *(uint4*)hb;
        *(uint4*)&olo[(size_t)n * 256 + lane * 8] = *(uint4*)lb;
    } else {
        // mean over heads (partner lane = lane ^ 16), + skip, pool into out[graph]
        float m[8];
#pragma unroll
        for (int i = 0; i < 8; ++i) {
            float other = __shfl_xor_sync(0xffffffffu, o8[i], 16);
            m[i] = 0.5f * (o8[i] + other);
        }
        int g = batch[n];
        if (lane < 16) {
            const float* sr = skip + (size_t)n * 128 + lane * 8;
            float4 s0 = *(const float4*)(sr);
            float4 s1 = *(const float4*)(sr + 4);
            float h0 = m[0] + s0.x, h1 = m[1] + s0.y, h2 = m[2] + s0.z, h3 = m[3] + s0.w;
            float h4 = m[4] + s1.x, h5 = m[5] + s1.y, h6 = m[6] + s1.z, h7 = m[7] + s1.w;
            float* dst = out + (size_t)g * 128 + lane * 8;
            atomicAdd(dst + 0, h0); atomicAdd(dst + 1, h1);
            atomicAdd(dst + 2, h2); atomicAdd(dst + 3, h3);
            atomicAdd(dst + 4, h4); atomicAdd(dst + 5, h5);
            atomicAdd(dst + 6, h6); atomicAdd(dst + 7, h7);
        }
        if (lane == 0) atomicAdd(&g_cnt[g], 1.f);
    }
}

// =============== pooling finish ================================================
__global__ __launch_bounds__(256) void pool_div_kernel(float* __restrict__ out) {
    int i = blockIdx.x * blockDim.x + threadIdx.x;
    if (i >= N_GRAPHS * 128) return;
    out[i] /= fmaxf(g_cnt[i >> 7], 1.f);
}

// =============== launch =========================================================
extern "C" void kernel_launch(void* const* d_in, const int* in_sizes, int n_in,
                              void* d_out, int out_size)
{
    const float* x     = (const float*)d_in[0];
    const int*   ei    = (const int*)d_in[1];
    const int*   batch = (const int*)d_in[2];
    const float* ea    = (const float*)d_in[3];
    const float* Wq1 = (const float*)d_in[4];
    const float* bq1 = (const float*)d_in[5];
    const float* Wk1 = (const float*)d_in[6];
    const float* bk1 = (const float*)d_in[7];
    const float* Wv1 = (const float*)d_in[8];
    const float* bv1 = (const float*)d_in[9];
    const float* We1 = (const float*)d_in[10];
    const float* Ws1 = (const float*)d_in[11];
    const float* bs1 = (const float*)d_in[12];
    const float* Wq2 = (const float*)d_in[13];
    const float* bq2 = (const float*)d_in[14];
    const float* Wk2 = (const float*)d_in[15];
    const float* bk2 = (const float*)d_in[16];
    const float* Wv2 = (const float*)d_in[17];
    const float* bv2 = (const float*)d_in[18];
    const float* We2 = (const float*)d_in[19];
    const float* Ws2 = (const float*)d_in[20];
    const float* bs2 = (const float*)d_in[21];
    float* out = (float*)d_out;

    float *pq, *pskip;
    __half *pkv, *pahi, *palo, *pwhi, *pwlo;
    cudaGetSymbolAddress((void**)&pq,    g_q);
    cudaGetSymbolAddress((void**)&pskip, g_skip);
    cudaGetSymbolAddress((void**)&pkv,   g_kv);
    cudaGetSymbolAddress((void**)&pahi,  g_ahi);
    cudaGetSymbolAddress((void**)&palo,  g_alo);
    cudaGetSymbolAddress((void**)&pwhi,  g_whi);
    cudaGetSymbolAddress((void**)&pwlo,  g_wlo);

    cudaFuncSetAttribute(gemm_qkvs_kernel<1>,
                         cudaFuncAttributeMaxDynamicSharedMemorySize, GSMEM_TOT);
    cudaFuncSetAttribute(gemm_qkvs_kernel<0>,
                         cudaFuncAttributeMaxDynamicSharedMemorySize, GSMEM_TOT);

    // side stream + events (created once, before any capture; reused every call)
    static cudaStream_t s1 = nullptr;
    static cudaEvent_t evFork = nullptr, evCSR = nullptr, evG1 = nullptr, evW2 = nullptr;
    if (s1 == nullptr) {
        cudaStreamCreateWithFlags(&s1, cudaStreamNonBlocking);
        cudaEventCreateWithFlags(&evFork, cudaEventDisableTiming);
        cudaEventCreateWithFlags(&evCSR,  cudaEventDisableTiming);
        cudaEventCreateWithFlags(&evG1,   cudaEventDisableTiming);
        cudaEventCreateWithFlags(&evW2,   cudaEventDisableTiming);
    }

    const int RT  = (N_NODES + 127) / 128;            // 391 row tiles
    const int EB  = (N_EDGES + 255) / 256;
    const int NB  = (N_NODES + 255) / 256;            // 196
    const int NWB = (N_NODES + 7) / 8;
    const int PZ  = (N_GRAPHS * 128 + 255) / 256;     // 1250

    // ---- fork: CSR build on side stream, overlapped with cvt+GEMM1 ----
    cudaEventRecord(evFork, 0);
    cudaStreamWaitEvent(s1, evFork, 0);

    init_zero_kernel<<<PZ, 256, 0, s1>>>(out);
    hist_kernel<<<EB, 256, 0, s1>>>(ei);
    scan1_kernel<<<NB, 256, 0, s1>>>();
    scan3_kernel<<<NB, 256, 0, s1>>>();
    csr_scatter_kernel<<<EB, 256, 0, s1>>>(ei, ea);
    cudaEventRecord(evCSR, s1);

    // ---- main stream: layer 1 cvt + merged GEMM ----
    cvt_split_kernel<<<(N_NODES * 128 / 4 + 255) / 256, 256>>>(x, pahi, palo, N_NODES * 128 / 4);
    cvt_split4_kernel<<<dim3(8192 / 256, 4), 256>>>(Wq1, Wk1, Wv1, Ws1,
                                                    pwhi, pwlo, 8192, 8192, 8192, 8192);
    gemm_qkvs_kernel<1><<<dim3(RT, 8), 256, GSMEM_TOT>>>(
        pahi, palo, bq1, bk1, bv1, bs1, pq, pkv, pskip, 128);
    cudaEventRecord(evG1, 0);

    // side stream: layer-2 weight conversion (after gemm1 done reading W bufs)
    cudaStreamWaitEvent(s1, evG1, 0);
    cvt_split4_kernel<<<dim3(16384 / 256, 4), 256, 0, s1>>>(Wq2, Wk2, Wv2, Ws2,
                                                            pwhi, pwlo, 16384, 16384, 16384, 8192);
    cudaEventRecord(evW2, s1);

    // main stream: attention layer 1 (needs CSR)
    cudaStreamWaitEvent(0, evCSR, 0);
    node_attn_kernel<1><<<NWB, 256>>>(pq, pkv, pskip, We1, batch, nullptr, pahi, palo);

    // ---- layer 2 (needs W2 conversion) ----
    cudaStreamWaitEvent(0, evW2, 0);
    gemm_qkvs_kernel<0><<<dim3(RT, 7), 256, GSMEM_TOT>>>(
        pahi, palo, bq2, bk2, bv2, bs2, pq, pkv, pskip, 256);
    node_attn_kernel<0><<<NWB, 256>>>(pq, pkv, pskip, We2, batch, out, nullptr, nullptr);

    // ---- pool finish ----
    pool_div_kernel<<<PZ, 256>>>(out);
}

// round 16
// speedup vs baseline: 1.7509x; 1.1018x over previous
#include <cuda_runtime.h>
#include <cuda_fp16.h>
#include <math.h>
#include <stdint.h>

#define N_NODES  50000
#define N_EDGES  800000
#define N_GRAPHS 2500

// ---------------- scratch (device globals; no allocations allowed) ----------
__device__ __align__(256) float g_q[N_NODES * 256];
__device__ __align__(256) float g_skip[N_NODES * 256];
__device__ __align__(256) float g_cw[N_EDGES];
__device__ __align__(256) int   g_csrc[N_EDGES];
__device__ __align__(256) int   g_rowptr[N_NODES + 1];
__device__ __align__(256) int   g_wof[N_NODES];
__device__ __align__(256) int   g_bsum[256];
__device__ __align__(256) float g_cnt[N_GRAPHS];
// fp16 operands
__device__ __align__(256) __half g_kv[N_NODES * 512];   // [k(256) | v(256)]
__device__ __align__(256) __half g_ahi[N_NODES * 256];
__device__ __align__(256) __half g_alo[N_NODES * 256];
__device__ __align__(256) __half g_whi[262144];
__device__ __align__(256) __half g_wlo[262144];

// ================= warp-MMA helpers ==========================================
__device__ __forceinline__ uint32_t smem_u32(const void* p) {
    uint32_t a;
    asm("{ .reg .u64 t; cvta.to.shared.u64 t, %1; cvt.u32.u64 %0, t; }"
        : "=r"(a) : "l"(p));
    return a;
}

__device__ __forceinline__ void ldsm_x4(uint32_t r[4], uint32_t addr) {
    asm volatile("ldmatrix.sync.aligned.m8n8.x4.shared.b16 {%0,%1,%2,%3}, [%4];"
        : "=r"(r[0]), "=r"(r[1]), "=r"(r[2]), "=r"(r[3]) : "r"(addr));
}
__device__ __forceinline__ void ldsm_x4_t(uint32_t r[4], uint32_t addr) {
    asm volatile("ldmatrix.sync.aligned.m8n8.x4.trans.shared.b16 {%0,%1,%2,%3}, [%4];"
        : "=r"(r[0]), "=r"(r[1]), "=r"(r[2]), "=r"(r[3]) : "r"(addr));
}

__device__ __forceinline__ void mma16816(float d[4], const uint32_t a[4],
                                         const uint32_t b[2]) {
    asm volatile(
        "mma.sync.aligned.m16n8k16.row.col.f32.f16.f16.f32 "
        "{%0,%1,%2,%3}, {%4,%5,%6,%7}, {%8,%9}, {%0,%1,%2,%3};"
        : "+f"(d[0]), "+f"(d[1]), "+f"(d[2]), "+f"(d[3])
        : "r"(a[0]), "r"(a[1]), "r"(a[2]), "r"(a[3]), "r"(b[0]), "r"(b[1]));
}

__device__ __forceinline__ void cp_async16(uint32_t dst, const void* src, int sz) {
    asm volatile("cp.async.cg.shared.global [%0], [%1], 16, %2;"
        :: "r"(dst), "l"(src), "r"(sz));
}
__device__ __forceinline__ void cp_commit() {
    asm volatile("cp.async.commit_group;" ::: "memory");
}

__device__ __forceinline__ void hf8_to_f(const uint4& u, float* f) {
    float2 p;
    p = __half22float2(*(const __half2*)&u.x); f[0] = p.x; f[1] = p.y;
    p = __half22float2(*(const __half2*)&u.y); f[2] = p.x; f[3] = p.y;
    p = __half22float2(*(const __half2*)&u.z); f[4] = p.x; f[5] = p.y;
    p = __half22float2(*(const __half2*)&u.w); f[6] = p.x; f[7] = p.y;
}

// =============== fp32 -> fp16 hi/lo split ======================================
__device__ __forceinline__ void split4(float4 v, uint2& hv, uint2& lv) {
    __half h0 = __float2half_rn(v.x);
    __half h1 = __float2half_rn(v.y);
    __half h2 = __float2half_rn(v.z);
    __half h3 = __float2half_rn(v.w);
    __half l0 = __float2half_rn(v.x - __half2float(h0));
    __half l1 = __float2half_rn(v.y - __half2float(h1));
    __half l2 = __float2half_rn(v.z - __half2float(h2));
    __half l3 = __float2half_rn(v.w - __half2float(h3));
    __half2 hp0 = __halves2half2(h0, h1);
    __half2 hp1 = __halves2half2(h2, h3);
    __half2 lp0 = __halves2half2(l0, l1);
    __half2 lp1 = __halves2half2(l2, l3);
    hv = make_uint2(*(uint32_t*)&hp0, *(uint32_t*)&hp1);
    lv = make_uint2(*(uint32_t*)&lp0, *(uint32_t*)&lp1);
}

__global__ __launch_bounds__(256) void cvt_split_kernel(
    const float* __restrict__ src, __half* __restrict__ hi,
    __half* __restrict__ lo, int n4)
{
    int i = blockIdx.x * blockDim.x + threadIdx.x;
    if (i >= n4) return;
    uint2 hv, lv;
    split4(((const float4*)src)[i], hv, lv);
    *(uint2*)&hi[i * 4] = hv;
    *(uint2*)&lo[i * 4] = lv;
}

// 4 weight matrices in one launch (grid.y selects matrix)
__global__ __launch_bounds__(256) void cvt_split4_kernel(
    const float* s0, const float* s1, const float* s2, const float* s3,
    __half* hi, __half* lo,
    int n4_0, int n4_1, int n4_2, int n4_3)
{
    const float* srcs[4] = {s0, s1, s2, s3};
    int n4s[4]  = {n4_0, n4_1, n4_2, n4_3};
    int offs[4] = {0, 65536, 131072, 196608};
    int m = blockIdx.y;
    int i = blockIdx.x * blockDim.x + threadIdx.x;
    if (i >= n4s[m]) return;
    uint2 hv, lv;
    split4(((const float4*)srcs[m])[i], hv, lv);
    *(uint2*)&hi[offs[m] + i * 4] = hv;
    *(uint2*)&lo[offs[m] + i * 4] = lv;
}

// ================= tensor-core GEMM (cp.async double-buffered) ===============
// USE_LO=1: D = Ah*Bh + Al*Bh (2-term, skip path); USE_LO=0: D = Ah*Bh (q/k/v)
#define ST_A_HI 0
#define ST_A_LO 10240
#define ST_B_HI 20480
#define ST_SIZE 29184
#define GSMEM_TOT (2 * ST_SIZE)

template <int NW, int USE_LO>
__device__ __forceinline__ void gemm_core(
    const __half* __restrict__ aHi, const __half* __restrict__ aLo,
    const __half* __restrict__ wHi,
    int K, int r0, int c0, uint32_t sb, float acc[2][8][4])
{
    const int t    = threadIdx.x;
    const int lane = t & 31;
    const int wid  = t >> 5;
    const int wm   = wid & 3;
    const int wn   = wid >> 2;

    const int aRow = lane & 15;
    const int aCol = (lane >> 4) * 8;
    const int bK   = lane & 15;
    const int bN   = (lane >> 4) * 8;

    const int nChunks = K >> 5;

    auto stage = [&](int c, int buf) {
        uint32_t st = sb + buf * ST_SIZE;
        int kc = c << 5;
#pragma unroll
        for (int it = 0; it < 2; ++it) {
            int fid = t + it * 256;
            int row = fid >> 2;
            int col = (fid & 3) * 8;
            int rg  = r0 + row;
            int ok  = (rg < N_NODES) ? 16 : 0;
            int rc  = (rg < N_NODES) ? rg : (N_NODES - 1);
            size_t gidx = (size_t)rc * K + kc + col;
            uint32_t d = st + row * 80 + col * 2;
            cp_async16(d + ST_A_HI, &aHi[gidx], ok);
            if (USE_LO) cp_async16(d + ST_A_LO, &aLo[gidx], ok);
        }
#pragma unroll
        for (int it = 0; it < 2; ++it) {
            int fid = t + it * 256;
            int kk  = fid >> 4;
            int n   = (fid & 15) * 8;
            size_t gidx = (size_t)(kc + kk) * NW + c0 + n;
            uint32_t d = st + kk * 272 + n * 2;
            cp_async16(d + ST_B_HI, &wHi[gidx], 16);
        }
        cp_commit();
    };

    stage(0, 0);
    for (int c = 0; c < nChunks; ++c) {
        bool more = (c + 1 < nChunks);
        if (more) stage(c + 1, (c + 1) & 1);
        if (more) asm volatile("cp.async.wait_group 1;" ::: "memory");
        else      asm volatile("cp.async.wait_group 0;" ::: "memory");
        __syncthreads();

        uint32_t st = sb + (c & 1) * ST_SIZE;
#pragma unroll
        for (int ks = 0; ks < 2; ++ks) {
            uint32_t aH[2][4], aL[2][4], bf[4][4];
#pragma unroll
            for (int mi = 0; mi < 2; ++mi) {
                uint32_t ar = st + (wm * 32 + mi * 16 + aRow) * 80 + (ks * 16 + aCol) * 2;
                ldsm_x4(aH[mi], ar + ST_A_HI);
                if (USE_LO) ldsm_x4(aL[mi], ar + ST_A_LO);
            }
#pragma unroll
            for (int pi = 0; pi < 4; ++pi)
                ldsm_x4_t(bf[pi], st + ST_B_HI + (ks * 16 + bK) * 272
                                     + (wn * 64 + pi * 16 + bN) * 2);
#pragma unroll
            for (int mi = 0; mi < 2; ++mi)
#pragma unroll
                for (int pi = 0; pi < 4; ++pi) {
                    mma16816(acc[mi][2 * pi],     aH[mi], &bf[pi][0]);
                    mma16816(acc[mi][2 * pi + 1], aH[mi], &bf[pi][2]);
                }
            if (USE_LO) {
#pragma unroll
                for (int mi = 0; mi < 2; ++mi)
#pragma unroll
                    for (int pi = 0; pi < 4; ++pi) {
                        mma16816(acc[mi][2 * pi],     aL[mi], &bf[pi][0]);
                        mma16816(acc[mi][2 * pi + 1], aL[mi], &bf[pi][2]);
                    }
            }
        }
        __syncthreads();
    }
}

// ---- merged q/k/v(/skip) GEMM -------------------------------------------------
// SK256=1 (layer 1): y in [0,7], gi = y>>1; gi==3 is skip (width 256, 2-term).
// SK256=0 (layer 2): y in [0,6]; y==6 -> skip GEMM width 128 (2-term).
// q/k/v slices (gi 0..2) use 1-term (Ah*Bh only).
template <int SK256>
__global__ __launch_bounds__(256) void gemm_qkvs_kernel(
    const __half* __restrict__ aHi, const __half* __restrict__ aLo,
    const float* __restrict__ b0, const float* __restrict__ b1,
    const float* __restrict__ b2, const float* __restrict__ b3,
    float* __restrict__ Yq, __half* __restrict__ Ykv,
    float* __restrict__ Ys, int K)
{
    extern __shared__ __align__(16) char smem[];
    const uint32_t sb = smem_u32(smem);
    const int r0 = blockIdx.x * 128;

    const int lane = threadIdx.x & 31;
    const int wid  = threadIdx.x >> 5;
    const int wm   = wid & 3;
    const int wn   = wid >> 2;

    if (!SK256 && blockIdx.y == 6) {
        // layer-2 skip GEMM: W width 128, 2-term
        float acc[2][8][4] = {};
        gemm_core<128, 1>(aHi, aLo, g_whi + 196608, K, r0, 0, sb, acc);
#pragma unroll
        for (int mi = 0; mi < 2; ++mi) {
            int rA = r0 + wm * 32 + mi * 16 + (lane >> 2);
            int rB = rA + 8;
#pragma unroll
            for (int ni = 0; ni < 8; ++ni) {
                int cc  = wn * 64 + ni * 8 + (lane & 3) * 2;
                float2 bv = *(const float2*)&b3[cc];
                if (rA < N_NODES)
                    *(float2*)&Ys[(size_t)rA * 128 + cc] =
                        make_float2(acc[mi][ni][0] + bv.x, acc[mi][ni][1] + bv.y);
                if (rB < N_NODES)
                    *(float2*)&Ys[(size_t)rB * 128 + cc] =
                        make_float2(acc[mi][ni][2] + bv.x, acc[mi][ni][3] + bv.y);
            }
        }
        return;
    }

    const int gi = blockIdx.y >> 1;
    const int c0 = (blockIdx.y & 1) * 128;

    const __half* wHi = g_whi + gi * 65536;
    const float* bias = (gi == 0) ? b0 : (gi == 1) ? b1 : (gi == 2) ? b2 : b3;

    float acc[2][8][4] = {};
    if (gi == 3) gemm_core<256, 1>(aHi, aLo, wHi, K, r0, c0, sb, acc);  // L1 skip
    else         gemm_core<256, 0>(aHi, aLo, wHi, K, r0, c0, sb, acc);  // q/k/v

#pragma unroll
    for (int mi = 0; mi < 2; ++mi) {
        int rA = r0 + wm * 32 + mi * 16 + (lane >> 2);
        int rB = rA + 8;
#pragma unroll
        for (int ni = 0; ni < 8; ++ni) {
            int cc  = c0 + wn * 64 + ni * 8 + (lane & 3) * 2;
            float2 bv = *(const float2*)&bias[cc];
            float x0 = acc[mi][ni][0] + bv.x, y0 = acc[mi][ni][1] + bv.y;
            float x1 = acc[mi][ni][2] + bv.x, y1 = acc[mi][ni][3] + bv.y;
            if (gi == 1 || gi == 2) {
                int kcol = cc + ((gi == 2) ? 256 : 0);
                if (rA < N_NODES)
                    *(__half2*)&Ykv[(size_t)rA * 512 + kcol] =
                        __floats2half2_rn(x0, y0);
                if (rB < N_NODES)
                    *(__half2*)&Ykv[(size_t)rB * 512 + kcol] =
                        __floats2half2_rn(x1, y1);
            } else {
                float* Y = (gi == 0) ? Yq : Ys;
                if (rA < N_NODES)
                    *(float2*)&Y[(size_t)rA * 256 + cc] = make_float2(x0, y0);
                if (rB < N_NODES)
                    *(float2*)&Y[(size_t)rB * 256 + cc] = make_float2(x1, y1);
            }
        }
    }
}

// =============== init + CSR build =============================================
__global__ __launch_bounds__(256) void init_zero_kernel(float* __restrict__ out) {
    int i = blockIdx.x * blockDim.x + threadIdx.x;
    if (i < N_GRAPHS * 128) out[i] = 0.f;
    if (i < N_NODES) g_wof[i] = 0;
    if (i < N_GRAPHS) g_cnt[i] = 0.f;
}

__global__ __launch_bounds__(256) void hist_kernel(const int* __restrict__ ei) {
    int e = blockIdx.x * blockDim.x + threadIdx.x;
    if (e < N_EDGES) atomicAdd(&g_wof[ei[N_EDGES + e]], 1);
}

__global__ __launch_bounds__(256) void scan1_kernel() {
    __shared__ int sb[2][256];
    int t = threadIdx.x;
    int i = blockIdx.x * 256 + t;
    int v = (i < N_NODES) ? g_wof[i] : 0;
    int pin = 0;
    sb[0][t] = v;
    __syncthreads();
#pragma unroll
    for (int off = 1; off < 256; off <<= 1) {
        int x = sb[pin][t];
        if (t >= off) x += sb[pin][t - off];
        sb[pin ^ 1][t] = x;
        __syncthreads();
        pin ^= 1;
    }
    int incl = sb[pin][t];
    if (i < N_NODES) g_rowptr[i] = incl - v;
    if (t == 255) g_bsum[blockIdx.x] = incl;
}

__global__ __launch_bounds__(256) void scan3_kernel() {
    __shared__ int sp[8];
    int t = threadIdx.x;
    int bid = blockIdx.x;
    int part = 0;
    for (int j = t; j < bid; j += 256) part += g_bsum[j];
#pragma unroll
    for (int o = 16; o; o >>= 1) part += __shfl_xor_sync(0xffffffffu, part, o);
    if ((t & 31) == 0) sp[t >> 5] = part;
    __syncthreads();
    if (t == 0) {
        int s = 0;
#pragma unroll
        for (int w = 0; w < 8; ++w) s += sp[w];
        sp[0] = s;
        if (bid == 0) g_rowptr[N_NODES] = N_EDGES;
    }
    __syncthreads();
    int off = sp[0];
    int i = bid * 256 + t;
    if (i < N_NODES) {
        int r = g_rowptr[i] + off;
        g_rowptr[i] = r;
        g_wof[i]    = r;
    }
}

__global__ __launch_bounds__(256) void csr_scatter_kernel(
    const int* __restrict__ ei, const float* __restrict__ ea)
{
    int e = blockIdx.x * blockDim.x + threadIdx.x;
    if (e >= N_EDGES) return;
    int src = ei[e];
    int dst = ei[N_EDGES + e];
    int pos = atomicAdd(&g_wof[dst], 1);
    g_csrc[pos] = src;
    g_cw[pos]   = ea[e];
}

// =============== per-node attention ===========================================
// CONCAT=1: writes hi/lo fp16 split of relu(attn+skip) [N,256]
// CONCAT=0: pools (mean_heads + skip) directly into out[graph] via atomics
template <int CONCAT>
__global__ __launch_bounds__(256, 3) void node_attn_kernel(
    const float* __restrict__ q, const __half* __restrict__ kv,
    const float* __restrict__ skip, const float* __restrict__ We,
    const int* __restrict__ batch, float* __restrict__ out,
    __half* __restrict__ ohi, __half* __restrict__ olo)
{
    int n = blockIdx.x * 8 + (threadIdx.x >> 5);
    if (n >= N_NODES) return;
    int lane = threadIdx.x & 31;
    int beg = g_rowptr[n], end = g_rowptr[n + 1];

    const float scale = 0.08838834764831845f;   // 1/sqrt(128)

    float qv[8], ev[8];
    {
        const float* qr = q + (size_t)n * 256 + lane * 8;
        *(float4*)&qv[0] = *(const float4*)(qr);
        *(float4*)&qv[4] = *(const float4*)(qr + 4);
        *(float4*)&ev[0] = *(const float4*)(We + lane * 8);
        *(float4*)&ev[4] = *(const float4*)(We + lane * 8 + 4);
    }
    float qe = 0.f;
#pragma unroll
    for (int i = 0; i < 8; ++i) qe = fmaf(qv[i], ev[i], qe);
#pragma unroll
    for (int o = 8; o; o >>= 1) qe += __shfl_xor_sync(0xffffffffu, qe, o);
    qe *= scale;

    float d = 0.f, cw = 0.f;
    float a[8] = {};

    int p = beg;
    // prefetched indices for the next pair
    int  nsa = 0, nsb = 0;
    float nwa = 0.f, nwb = 0.f;
    if (p + 1 < end) {
        nsa = g_csrc[p];     nwa = g_cw[p];
        nsb = g_csrc[p + 1]; nwb = g_cw[p + 1];
    }
    for (; p + 1 < end; p += 2) {
        int  sa = nsa,  sb = nsb;
        float wa = nwa, wb = nwb;
        if (p + 3 < end) {
            nsa = g_csrc[p + 2]; nwa = g_cw[p + 2];
            nsb = g_csrc[p + 3]; nwb = g_cw[p + 3];
        }
        const uint4* ra = (const uint4*)(kv + (size_t)sa * 512);
        const uint4* rb = (const uint4*)(kv + (size_t)sb * 512);
        uint4 kua = ra[lane], kub = rb[lane];
        uint4 vua = ra[32 + lane], vub = rb[32 + lane];

        float kfa[8], kfb[8];
        hf8_to_f(kua, kfa);
        hf8_to_f(kub, kfb);
        float ta = 0.f, tb = 0.f;
#pragma unroll
        for (int i = 0; i < 8; ++i) {
            ta = fmaf(qv[i], kfa[i], ta);
            tb = fmaf(qv[i], kfb[i], tb);
        }
#pragma unroll
        for (int o = 8; o; o >>= 1) {
            ta += __shfl_xor_sync(0xffffffffu, ta, o);
            tb += __shfl_xor_sync(0xffffffffu, tb, o);
        }
        float xa = __expf(fmaf(wa, qe, ta * scale));
        float xb = __expf(fmaf(wb, qe, tb * scale));
        d  += xa + xb;
        cw += xa * wa + xb * wb;
        float vfa[8], vfb[8];
        hf8_to_f(vua, vfa);
        hf8_to_f(vub, vfb);
#pragma unroll
        for (int i = 0; i < 8; ++i)
            a[i] += xa * vfa[i] + xb * vfb[i];
    }
    for (; p < end; ++p) {
        int s = g_csrc[p];
        float w = g_cw[p];
        const uint4* r = (const uint4*)(kv + (size_t)s * 512);
        uint4 ku = r[lane], vu = r[32 + lane];
        float kf[8];
        hf8_to_f(ku, kf);
        float t = 0.f;
#pragma unroll
        for (int i = 0; i < 8; ++i) t = fmaf(qv[i], kf[i], t);
#pragma unroll
        for (int o = 8; o; o >>= 1) t += __shfl_xor_sync(0xffffffffu, t, o);
        float x = __expf(fmaf(w, qe, t * scale));
        d += x; cw += x * w;
        float vf[8];
        hf8_to_f(vu, vf);
#pragma unroll
        for (int i = 0; i < 8; ++i) a[i] += x * vf[i];
    }

    float r = d > 0.f ? 1.f / d : 0.f;
    float o8[8];
#pragma unroll
    for (int i = 0; i < 8; ++i) o8[i] = (a[i] + cw * ev[i]) * r;

    if (CONCAT) {
        float sk[8];
        const float* sr = skip + (size_t)n * 256 + lane * 8;
        *(float4*)&sk[0] = *(const float4*)(sr);
        *(float4*)&sk[4] = *(const float4*)(sr + 4);
        __align__(16) __half hb[8], lb[8];
#pragma unroll
        for (int i = 0; i < 8; ++i) {
            float o = fmaxf(o8[i] + sk[i], 0.f);
            hb[i] = __float2half_rn(o);
            lb[i] = __float2half_rn(o - __half2float(hb[i]));
        }
        *(uint4*)&ohi[(size_t)n * 256 + lane * 8] = *(uint4*)hb;
        *(uint4*)&olo[(size_t)n * 256 + lane * 8] = *(uint4*)lb;
    } else {
        // mean over heads (partner lane = lane ^ 16), + skip, pool into out[graph]
        float m[8];
#pragma unroll
        for (int i = 0; i < 8; ++i) {
            float other = __shfl_xor_sync(0xffffffffu, o8[i], 16);
            m[i] = 0.5f * (o8[i] + other);
        }
        int g = batch[n];
        if (lane < 16) {
            const float* sr = skip + (size_t)n * 128 + lane * 8;
            float4 s0 = *(const float4*)(sr);
            float4 s1 = *(const float4*)(sr + 4);
            float h0 = m[0] + s0.x, h1 = m[1] + s0.y, h2 = m[2] + s0.z, h3 = m[3] + s0.w;
            float h4 = m[4] + s1.x, h5 = m[5] + s1.y, h6 = m[6] + s1.z, h7 = m[7] + s1.w;
            float* dst = out + (size_t)g * 128 + lane * 8;
            atomicAdd(dst + 0, h0); atomicAdd(dst + 1, h1);
            atomicAdd(dst + 2, h2); atomicAdd(dst + 3, h3);
            atomicAdd(dst + 4, h4); atomicAdd(dst + 5, h5);
            atomicAdd(dst + 6, h6); atomicAdd(dst + 7, h7);
        }
        if (lane == 0) atomicAdd(&g_cnt[g], 1.f);
    }
}

// =============== pooling finish ================================================
__global__ __launch_bounds__(256) void pool_div_kernel(float* __restrict__ out) {
    int i = blockIdx.x * blockDim.x + threadIdx.x;
    if (i >= N_GRAPHS * 128) return;
    out[i] /= fmaxf(g_cnt[i >> 7], 1.f);
}

// =============== launch =========================================================
extern "C" void kernel_launch(void* const* d_in, const int* in_sizes, int n_in,
                              void* d_out, int out_size)
{
    const float* x     = (const float*)d_in[0];
    const int*   ei    = (const int*)d_in[1];
    const int*   batch = (const int*)d_in[2];
    const float* ea    = (const float*)d_in[3];
    const float* Wq1 = (const float*)d_in[4];
    const float* bq1 = (const float*)d_in[5];
    const float* Wk1 = (const float*)d_in[6];
    const float* bk1 = (const float*)d_in[7];
    const float* Wv1 = (const float*)d_in[8];
    const float* bv1 = (const float*)d_in[9];
    const float* We1 = (const float*)d_in[10];
    const float* Ws1 = (const float*)d_in[11];
    const float* bs1 = (const float*)d_in[12];
    const float* Wq2 = (const float*)d_in[13];
    const float* bq2 = (const float*)d_in[14];
    const float* Wk2 = (const float*)d_in[15];
    const float* bk2 = (const float*)d_in[16];
    const float* Wv2 = (const float*)d_in[17];
    const float* bv2 = (const float*)d_in[18];
    const float* We2 = (const float*)d_in[19];
    const float* Ws2 = (const float*)d_in[20];
    const float* bs2 = (const float*)d_in[21];
    float* out = (float*)d_out;

    float *pq, *pskip;
    __half *pkv, *pahi, *palo, *pwhi, *pwlo;
    cudaGetSymbolAddress((void**)&pq,    g_q);
    cudaGetSymbolAddress((void**)&pskip, g_skip);
    cudaGetSymbolAddress((void**)&pkv,   g_kv);
    cudaGetSymbolAddress((void**)&pahi,  g_ahi);
    cudaGetSymbolAddress((void**)&palo,  g_alo);
    cudaGetSymbolAddress((void**)&pwhi,  g_whi);
    cudaGetSymbolAddress((void**)&pwlo,  g_wlo);

    cudaFuncSetAttribute(gemm_qkvs_kernel<1>,
                         cudaFuncAttributeMaxDynamicSharedMemorySize, GSMEM_TOT);
    cudaFuncSetAttribute(gemm_qkvs_kernel<0>,
                         cudaFuncAttributeMaxDynamicSharedMemorySize, GSMEM_TOT);

    // side stream + events (created once, before any capture; reused every call)
    static cudaStream_t s1 = nullptr;
    static cudaEvent_t evFork = nullptr, evCSR = nullptr, evG1 = nullptr, evW2 = nullptr;
    if (s1 == nullptr) {
        cudaStreamCreateWithFlags(&s1, cudaStreamNonBlocking);
        cudaEventCreateWithFlags(&evFork, cudaEventDisableTiming);
        cudaEventCreateWithFlags(&evCSR,  cudaEventDisableTiming);
        cudaEventCreateWithFlags(&evG1,   cudaEventDisableTiming);
        cudaEventCreateWithFlags(&evW2,   cudaEventDisableTiming);
    }

    const int RT  = (N_NODES + 127) / 128;            // 391 row tiles
    const int EB  = (N_EDGES + 255) / 256;
    const int NB  = (N_NODES + 255) / 256;            // 196
    const int NWB = (N_NODES + 7) / 8;
    const int PZ  = (N_GRAPHS * 128 + 255) / 256;     // 1250

    // ---- fork: CSR build on side stream, overlapped with cvt+GEMM1 ----
    cudaEventRecord(evFork, 0);
    cudaStreamWaitEvent(s1, evFork, 0);

    init_zero_kernel<<<PZ, 256, 0, s1>>>(out);
    hist_kernel<<<EB, 256, 0, s1>>>(ei);
    scan1_kernel<<<NB, 256, 0, s1>>>();
    scan3_kernel<<<NB, 256, 0, s1>>>();
    csr_scatter_kernel<<<EB, 256, 0, s1>>>(ei, ea);
    cudaEventRecord(evCSR, s1);

    // ---- main stream: layer 1 cvt + merged GEMM ----
    cvt_split_kernel<<<(N_NODES * 128 / 4 + 255) / 256, 256>>>(x, pahi, palo, N_NODES * 128 / 4);
    cvt_split4_kernel<<<dim3(8192 / 256, 4), 256>>>(Wq1, Wk1, Wv1, Ws1,
                                                    pwhi, pwlo, 8192, 8192, 8192, 8192);
    gemm_qkvs_kernel<1><<<dim3(RT, 8), 256, GSMEM_TOT>>>(
        pahi, palo, bq1, bk1, bv1, bs1, pq, pkv, pskip, 128);
    cudaEventRecord(evG1, 0);

    // side stream: layer-2 weight conversion (after gemm1 done reading W bufs)
    cudaStreamWaitEvent(s1, evG1, 0);
    cvt_split4_kernel<<<dim3(16384 / 256, 4), 256, 0, s1>>>(Wq2, Wk2, Wv2, Ws2,
                                                            pwhi, pwlo, 16384, 16384, 16384, 8192);
    cudaEventRecord(evW2, s1);

    // main stream: attention layer 1 (needs CSR)
    cudaStreamWaitEvent(0, evCSR, 0);
    node_attn_kernel<1><<<NWB, 256>>>(pq, pkv, pskip, We1, batch, nullptr, pahi, palo);

    // ---- layer 2 (needs W2 conversion) ----
    cudaStreamWaitEvent(0, evW2, 0);
    gemm_qkvs_kernel<0><<<dim3(RT, 7), 256, GSMEM_TOT>>>(
        pahi, palo, bq2, bk2, bv2, bs2, pq, pkv, pskip, 256);
    node_attn_kernel<0><<<NWB, 256>>>(pq, pkv, pskip, We2, batch, out, nullptr, nullptr);

    // ---- pool finish ----
    pool_div_kernel<<<PZ, 256>>>(out);
}

// round 17
// speedup vs baseline: 1.8795x; 1.0734x over previous
#include <cuda_runtime.h>
#include <cuda_fp16.h>
#include <math.h>
#include <stdint.h>

#define N_NODES  50000
#define N_EDGES  800000
#define N_GRAPHS 2500

// ---------------- scratch (device globals; no allocations allowed) ----------
__device__ __align__(256) float g_q[N_NODES * 256];
__device__ __align__(256) float g_skip[N_NODES * 256];
__device__ __align__(256) float g_cw[N_EDGES];
__device__ __align__(256) int   g_csrc[N_EDGES];
__device__ __align__(256) int   g_rowptr[N_NODES + 1];
__device__ __align__(256) int   g_wof[N_NODES];
__device__ __align__(256) int   g_bsum[256];
__device__ __align__(256) float g_cnt[N_GRAPHS];
// fp16 operands (single precision level: plain fp16 round-to-nearest)
__device__ __align__(256) __half g_kv[N_NODES * 512];   // [k(256) | v(256)]
__device__ __align__(256) __half g_ah[N_NODES * 256];
__device__ __align__(256) __half g_wh[262144];

// ================= warp-MMA helpers ==========================================
__device__ __forceinline__ uint32_t smem_u32(const void* p) {
    uint32_t a;
    asm("{ .reg .u64 t; cvta.to.shared.u64 t, %1; cvt.u32.u64 %0, t; }"
        : "=r"(a) : "l"(p));
    return a;
}

__device__ __forceinline__ void ldsm_x4(uint32_t r[4], uint32_t addr) {
    asm volatile("ldmatrix.sync.aligned.m8n8.x4.shared.b16 {%0,%1,%2,%3}, [%4];"
        : "=r"(r[0]), "=r"(r[1]), "=r"(r[2]), "=r"(r[3]) : "r"(addr));
}
__device__ __forceinline__ void ldsm_x4_t(uint32_t r[4], uint32_t addr) {
    asm volatile("ldmatrix.sync.aligned.m8n8.x4.trans.shared.b16 {%0,%1,%2,%3}, [%4];"
        : "=r"(r[0]), "=r"(r[1]), "=r"(r[2]), "=r"(r[3]) : "r"(addr));
}

__device__ __forceinline__ void mma16816(float d[4], const uint32_t a[4],
                                         const uint32_t b[2]) {
    asm volatile(
        "mma.sync.aligned.m16n8k16.row.col.f32.f16.f16.f32 "
        "{%0,%1,%2,%3}, {%4,%5,%6,%7}, {%8,%9}, {%0,%1,%2,%3};"
        : "+f"(d[0]), "+f"(d[1]), "+f"(d[2]), "+f"(d[3])
        : "r"(a[0]), "r"(a[1]), "r"(a[2]), "r"(a[3]), "r"(b[0]), "r"(b[1]));
}

__device__ __forceinline__ void cp_async16(uint32_t dst, const void* src, int sz) {
    asm volatile("cp.async.cg.shared.global [%0], [%1], 16, %2;"
        :: "r"(dst), "l"(src), "r"(sz));
}
__device__ __forceinline__ void cp_commit() {
    asm volatile("cp.async.commit_group;" ::: "memory");
}

__device__ __forceinline__ void hf8_to_f(const uint4& u, float* f) {
    float2 p;
    p = __half22float2(*(const __half2*)&u.x); f[0] = p.x; f[1] = p.y;
    p = __half22float2(*(const __half2*)&u.y); f[2] = p.x; f[3] = p.y;
    p = __half22float2(*(const __half2*)&u.z); f[4] = p.x; f[5] = p.y;
    p = __half22float2(*(const __half2*)&u.w); f[6] = p.x; f[7] = p.y;
}

// =============== fp32 -> fp16 convert ==========================================
__device__ __forceinline__ uint2 cvt4(float4 v) {
    __half2 p0 = __floats2half2_rn(v.x, v.y);
    __half2 p1 = __floats2half2_rn(v.z, v.w);
    return make_uint2(*(uint32_t*)&p0, *(uint32_t*)&p1);
}

__global__ __launch_bounds__(256) void cvt_h_kernel(
    const float* __restrict__ src, __half* __restrict__ hi, int n4)
{
    int i = blockIdx.x * blockDim.x + threadIdx.x;
    if (i >= n4) return;
    *(uint2*)&hi[i * 4] = cvt4(((const float4*)src)[i]);
}

// 4 weight matrices in one launch (grid.y selects matrix)
__global__ __launch_bounds__(256) void cvt4_h_kernel(
    const float* s0, const float* s1, const float* s2, const float* s3,
    __half* hi, int n4_0, int n4_1, int n4_2, int n4_3)
{
    const float* srcs[4] = {s0, s1, s2, s3};
    int n4s[4]  = {n4_0, n4_1, n4_2, n4_3};
    int offs[4] = {0, 65536, 131072, 196608};
    int m = blockIdx.y;
    int i = blockIdx.x * blockDim.x + threadIdx.x;
    if (i >= n4s[m]) return;
    *(uint2*)&hi[offs[m] + i * 4] = cvt4(((const float4*)srcs[m])[i]);
}

// ================= tensor-core GEMM (cp.async double-buffered, fp16 1-term) ==
#define ST_A    0
#define ST_B    10240
#define ST_SIZE 18944
#define GSMEM_TOT (2 * ST_SIZE)

template <int NW>  // NW: W row width
__device__ __forceinline__ void gemm_core(
    const __half* __restrict__ aH, const __half* __restrict__ wH,
    int K, int r0, int c0, uint32_t sb, float acc[2][8][4])
{
    const int t    = threadIdx.x;
    const int lane = t & 31;
    const int wid  = t >> 5;
    const int wm   = wid & 3;
    const int wn   = wid >> 2;

    const int aRow = lane & 15;
    const int aCol = (lane >> 4) * 8;
    const int bK   = lane & 15;
    const int bN   = (lane >> 4) * 8;

    const int nChunks = K >> 5;

    auto stage = [&](int c, int buf) {
        uint32_t st = sb + buf * ST_SIZE;
        int kc = c << 5;
#pragma unroll
        for (int it = 0; it < 2; ++it) {
            int fid = t + it * 256;
            int row = fid >> 2;
            int col = (fid & 3) * 8;
            int rg  = r0 + row;
            int ok  = (rg < N_NODES) ? 16 : 0;
            int rc  = (rg < N_NODES) ? rg : (N_NODES - 1);
            size_t gidx = (size_t)rc * K + kc + col;
            cp_async16(st + ST_A + row * 80 + col * 2, &aH[gidx], ok);
        }
#pragma unroll
        for (int it = 0; it < 2; ++it) {
            int fid = t + it * 256;
            int kk  = fid >> 4;
            int n   = (fid & 15) * 8;
            size_t gidx = (size_t)(kc + kk) * NW + c0 + n;
            cp_async16(st + ST_B + kk * 272 + n * 2, &wH[gidx], 16);
        }
        cp_commit();
    };

    stage(0, 0);
    for (int c = 0; c < nChunks; ++c) {
        bool more = (c + 1 < nChunks);
        if (more) stage(c + 1, (c + 1) & 1);
        if (more) asm volatile("cp.async.wait_group 1;" ::: "memory");
        else      asm volatile("cp.async.wait_group 0;" ::: "memory");
        __syncthreads();

        uint32_t st = sb + (c & 1) * ST_SIZE;
#pragma unroll
        for (int ks = 0; ks < 2; ++ks) {
            uint32_t aF[2][4], bf[4][4];
#pragma unroll
            for (int mi = 0; mi < 2; ++mi)
                ldsm_x4(aF[mi], st + ST_A + (wm * 32 + mi * 16 + aRow) * 80
                                    + (ks * 16 + aCol) * 2);
#pragma unroll
            for (int pi = 0; pi < 4; ++pi)
                ldsm_x4_t(bf[pi], st + ST_B + (ks * 16 + bK) * 272
                                     + (wn * 64 + pi * 16 + bN) * 2);
#pragma unroll
            for (int mi = 0; mi < 2; ++mi)
#pragma unroll
                for (int pi = 0; pi < 4; ++pi) {
                    mma16816(acc[mi][2 * pi],     aF[mi], &bf[pi][0]);
                    mma16816(acc[mi][2 * pi + 1], aF[mi], &bf[pi][2]);
                }
        }
        __syncthreads();
    }
}

// ---- merged q/k/v(/skip) GEMM -------------------------------------------------
// SK256=1 (layer 1): y in [0,7], gi = y>>1 (0=q,1=k,2=v,3=skip w256).
// SK256=0 (layer 2): y in [0,6]; y==6 -> skip GEMM width 128 (c0=0).
template <int SK256>
__global__ __launch_bounds__(256) void gemm_qkvs_kernel(
    const __half* __restrict__ aH,
    const float* __restrict__ b0, const float* __restrict__ b1,
    const float* __restrict__ b2, const float* __restrict__ b3,
    float* __restrict__ Yq, __half* __restrict__ Ykv,
    float* __restrict__ Ys, int K)
{
    extern __shared__ __align__(16) char smem[];
    const uint32_t sb = smem_u32(smem);
    const int r0 = blockIdx.x * 128;

    const int lane = threadIdx.x & 31;
    const int wid  = threadIdx.x >> 5;
    const int wm   = wid & 3;
    const int wn   = wid >> 2;

    if (!SK256 && blockIdx.y == 6) {
        // layer-2 skip GEMM: W width 128
        float acc[2][8][4] = {};
        gemm_core<128>(aH, g_wh + 196608, K, r0, 0, sb, acc);
#pragma unroll
        for (int mi = 0; mi < 2; ++mi) {
            int rA = r0 + wm * 32 + mi * 16 + (lane >> 2);
            int rB = rA + 8;
#pragma unroll
            for (int ni = 0; ni < 8; ++ni) {
                int cc  = wn * 64 + ni * 8 + (lane & 3) * 2;
                float2 bv = *(const float2*)&b3[cc];
                if (rA < N_NODES)
                    *(float2*)&Ys[(size_t)rA * 128 + cc] =
                        make_float2(acc[mi][ni][0] + bv.x, acc[mi][ni][1] + bv.y);
                if (rB < N_NODES)
                    *(float2*)&Ys[(size_t)rB * 128 + cc] =
                        make_float2(acc[mi][ni][2] + bv.x, acc[mi][ni][3] + bv.y);
            }
        }
        return;
    }

    const int gi = blockIdx.y >> 1;
    const int c0 = (blockIdx.y & 1) * 128;

    const __half* wH = g_wh + gi * 65536;
    const float* bias = (gi == 0) ? b0 : (gi == 1) ? b1 : (gi == 2) ? b2 : b3;

    float acc[2][8][4] = {};
    gemm_core<256>(aH, wH, K, r0, c0, sb, acc);

#pragma unroll
    for (int mi = 0; mi < 2; ++mi) {
        int rA = r0 + wm * 32 + mi * 16 + (lane >> 2);
        int rB = rA + 8;
#pragma unroll
        for (int ni = 0; ni < 8; ++ni) {
            int cc  = c0 + wn * 64 + ni * 8 + (lane & 3) * 2;
            float2 bv = *(const float2*)&bias[cc];
            float x0 = acc[mi][ni][0] + bv.x, y0 = acc[mi][ni][1] + bv.y;
            float x1 = acc[mi][ni][2] + bv.x, y1 = acc[mi][ni][3] + bv.y;
            if (gi == 1 || gi == 2) {
                int kcol = cc + ((gi == 2) ? 256 : 0);
                if (rA < N_NODES)
                    *(__half2*)&Ykv[(size_t)rA * 512 + kcol] =
                        __floats2half2_rn(x0, y0);
                if (rB < N_NODES)
                    *(__half2*)&Ykv[(size_t)rB * 512 + kcol] =
                        __floats2half2_rn(x1, y1);
            } else {
                float* Y = (gi == 0) ? Yq : Ys;
                if (rA < N_NODES)
                    *(float2*)&Y[(size_t)rA * 256 + cc] = make_float2(x0, y0);
                if (rB < N_NODES)
                    *(float2*)&Y[(size_t)rB * 256 + cc] = make_float2(x1, y1);
            }
        }
    }
}

// =============== init + CSR build =============================================
__global__ __launch_bounds__(256) void init_zero_kernel(float* __restrict__ out) {
    int i = blockIdx.x * blockDim.x + threadIdx.x;
    if (i < N_GRAPHS * 128) out[i] = 0.f;
    if (i < N_NODES) g_wof[i] = 0;
    if (i < N_GRAPHS) g_cnt[i] = 0.f;
}

__global__ __launch_bounds__(256) void hist_kernel(const int* __restrict__ ei) {
    int e = blockIdx.x * blockDim.x + threadIdx.x;
    if (e < N_EDGES) atomicAdd(&g_wof[ei[N_EDGES + e]], 1);
}

__global__ __launch_bounds__(256) void scan1_kernel() {
    __shared__ int sb[2][256];
    int t = threadIdx.x;
    int i = blockIdx.x * 256 + t;
    int v = (i < N_NODES) ? g_wof[i] : 0;
    int pin = 0;
    sb[0][t] = v;
    __syncthreads();
#pragma unroll
    for (int off = 1; off < 256; off <<= 1) {
        int x = sb[pin][t];
        if (t >= off) x += sb[pin][t - off];
        sb[pin ^ 1][t] = x;
        __syncthreads();
        pin ^= 1;
    }
    int incl = sb[pin][t];
    if (i < N_NODES) g_rowptr[i] = incl - v;
    if (t == 255) g_bsum[blockIdx.x] = incl;
}

__global__ __launch_bounds__(256) void scan3_kernel() {
    __shared__ int sp[8];
    int t = threadIdx.x;
    int bid = blockIdx.x;
    int part = 0;
    for (int j = t; j < bid; j += 256) part += g_bsum[j];
#pragma unroll
    for (int o = 16; o; o >>= 1) part += __shfl_xor_sync(0xffffffffu, part, o);
    if ((t & 31) == 0) sp[t >> 5] = part;
    __syncthreads();
    if (t == 0) {
        int s = 0;
#pragma unroll
        for (int w = 0; w < 8; ++w) s += sp[w];
        sp[0] = s;
        if (bid == 0) g_rowptr[N_NODES] = N_EDGES;
    }
    __syncthreads();
    int off = sp[0];
    int i = bid * 256 + t;
    if (i < N_NODES) {
        int r = g_rowptr[i] + off;
        g_rowptr[i] = r;
        g_wof[i]    = r;
    }
}

__global__ __launch_bounds__(256) void csr_scatter_kernel(
    const int* __restrict__ ei, const float* __restrict__ ea)
{
    int e = blockIdx.x * blockDim.x + threadIdx.x;
    if (e >= N_EDGES) return;
    int src = ei[e];
    int dst = ei[N_EDGES + e];
    int pos = atomicAdd(&g_wof[dst], 1);
    g_csrc[pos] = src;
    g_cw[pos]   = ea[e];
}

// =============== per-node attention ===========================================
// CONCAT=1: writes fp16 relu(attn+skip) [N,256] into oh
// CONCAT=0: pools (mean_heads + skip) directly into out[graph] via atomics
template <int CONCAT>
__global__ __launch_bounds__(256, 3) void node_attn_kernel(
    const float* __restrict__ q, const __half* __restrict__ kv,
    const float* __restrict__ skip, const float* __restrict__ We,
    const int* __restrict__ batch, float* __restrict__ out,
    __half* __restrict__ oh)
{
    int n = blockIdx.x * 8 + (threadIdx.x >> 5);
    if (n >= N_NODES) return;
    int lane = threadIdx.x & 31;
    int beg = g_rowptr[n], end = g_rowptr[n + 1];

    const float scale = 0.08838834764831845f;   // 1/sqrt(128)

    float qv[8], ev[8];
    {
        const float* qr = q + (size_t)n * 256 + lane * 8;
        *(float4*)&qv[0] = *(const float4*)(qr);
        *(float4*)&qv[4] = *(const float4*)(qr + 4);
        *(float4*)&ev[0] = *(const float4*)(We + lane * 8);
        *(float4*)&ev[4] = *(const float4*)(We + lane * 8 + 4);
    }
    float qe = 0.f;
#pragma unroll
    for (int i = 0; i < 8; ++i) qe = fmaf(qv[i], ev[i], qe);
#pragma unroll
    for (int o = 8; o; o >>= 1) qe += __shfl_xor_sync(0xffffffffu, qe, o);
    qe *= scale;

    float d = 0.f, cw = 0.f;
    float a[8] = {};

    int p = beg;
    int  nsa = 0, nsb = 0;
    float nwa = 0.f, nwb = 0.f;
    if (p + 1 < end) {
        nsa = g_csrc[p];     nwa = g_cw[p];
        nsb = g_csrc[p + 1]; nwb = g_cw[p + 1];
    }
    for (; p + 1 < end; p += 2) {
        int  sa = nsa,  sb = nsb;
        float wa = nwa, wb = nwb;
        if (p + 3 < end) {
            nsa = g_csrc[p + 2]; nwa = g_cw[p + 2];
            nsb = g_csrc[p + 3]; nwb = g_cw[p + 3];
        }
        const uint4* ra = (const uint4*)(kv + (size_t)sa * 512);
        const uint4* rb = (const uint4*)(kv + (size_t)sb * 512);
        uint4 kua = ra[lane], kub = rb[lane];
        uint4 vua = ra[32 + lane], vub = rb[32 + lane];

        float kfa[8], kfb[8];
        hf8_to_f(kua, kfa);
        hf8_to_f(kub, kfb);
        float ta = 0.f, tb = 0.f;
#pragma unroll
        for (int i = 0; i < 8; ++i) {
            ta = fmaf(qv[i], kfa[i], ta);
            tb = fmaf(qv[i], kfb[i], tb);
        }
#pragma unroll
        for (int o = 8; o; o >>= 1) {
            ta += __shfl_xor_sync(0xffffffffu, ta, o);
            tb += __shfl_xor_sync(0xffffffffu, tb, o);
        }
        float xa = __expf(fmaf(wa, qe, ta * scale));
        float xb = __expf(fmaf(wb, qe, tb * scale));
        d  += xa + xb;
        cw += xa * wa + xb * wb;
        float vfa[8], vfb[8];
        hf8_to_f(vua, vfa);
        hf8_to_f(vub, vfb);
#pragma unroll
        for (int i = 0; i < 8; ++i)
            a[i] += xa * vfa[i] + xb * vfb[i];
    }
    for (; p < end; ++p) {
        int s = g_csrc[p];
        float w = g_cw[p];
        const uint4* r = (const uint4*)(kv + (size_t)s * 512);
        uint4 ku = r[lane], vu = r[32 + lane];
        float kf[8];
        hf8_to_f(ku, kf);
        float t = 0.f;
#pragma unroll
        for (int i = 0; i < 8; ++i) t = fmaf(qv[i], kf[i], t);
#pragma unroll
        for (int o = 8; o; o >>= 1) t += __shfl_xor_sync(0xffffffffu, t, o);
        float x = __expf(fmaf(w, qe, t * scale));
        d += x; cw += x * w;
        float vf[8];
        hf8_to_f(vu, vf);
#pragma unroll
        for (int i = 0; i < 8; ++i) a[i] += x * vf[i];
    }

    float r = d > 0.f ? 1.f / d : 0.f;
    float o8[8];
#pragma unroll
    for (int i = 0; i < 8; ++i) o8[i] = (a[i] + cw * ev[i]) * r;

    if (CONCAT) {
        float sk[8];
        const float* sr = skip + (size_t)n * 256 + lane * 8;
        *(float4*)&sk[0] = *(const float4*)(sr);
        *(float4*)&sk[4] = *(const float4*)(sr + 4);
        __align__(16) __half hb[8];
#pragma unroll
        for (int i = 0; i < 8; ++i)
            hb[i] = __float2half_rn(fmaxf(o8[i] + sk[i], 0.f));
        *(uint4*)&oh[(size_t)n * 256 + lane * 8] = *(uint4*)hb;
    } else {
        float m[8];
#pragma unroll
        for (int i = 0; i < 8; ++i) {
            float other = __shfl_xor_sync(0xffffffffu, o8[i], 16);
            m[i] = 0.5f * (o8[i] + other);
        }
        int g = batch[n];
        if (lane < 16) {
            const float* sr = skip + (size_t)n * 128 + lane * 8;
            float4 s0 = *(const float4*)(sr);
            float4 s1 = *(const float4*)(sr + 4);
            float h0 = m[0] + s0.x, h1 = m[1] + s0.y, h2 = m[2] + s0.z, h3 = m[3] + s0.w;
            float h4 = m[4] + s1.x, h5 = m[5] + s1.y, h6 = m[6] + s1.z, h7 = m[7] + s1.w;
            float* dst = out + (size_t)g * 128 + lane * 8;
            atomicAdd(dst + 0, h0); atomicAdd(dst + 1, h1);
            atomicAdd(dst + 2, h2); atomicAdd(dst + 3, h3);
            atomicAdd(dst + 4, h4); atomicAdd(dst + 5, h5);
            atomicAdd(dst + 6, h6); atomicAdd(dst + 7, h7);
        }
        if (lane == 0) atomicAdd(&g_cnt[g], 1.f);
    }
}

// =============== pooling finish ================================================
__global__ __launch_bounds__(256) void pool_div_kernel(float* __restrict__ out) {
    int i = blockIdx.x * blockDim.x + threadIdx.x;
    if (i >= N_GRAPHS * 128) return;
    out[i] /= fmaxf(g_cnt[i >> 7], 1.f);
}

// =============== launch =========================================================
extern "C" void kernel_launch(void* const* d_in, const int* in_sizes, int n_in,
                              void* d_out, int out_size)
{
    const float* x     = (const float*)d_in[0];
    const int*   ei    = (const int*)d_in[1];
    const int*   batch = (const int*)d_in[2];
    const float* ea    = (const float*)d_in[3];
    const float* Wq1 = (const float*)d_in[4];
    const float* bq1 = (const float*)d_in[5];
    const float* Wk1 = (const float*)d_in[6];
    const float* bk1 = (const float*)d_in[7];
    const float* Wv1 = (const float*)d_in[8];
    const float* bv1 = (const float*)d_in[9];
    const float* We1 = (const float*)d_in[10];
    const float* Ws1 = (const float*)d_in[11];
    const float* bs1 = (const float*)d_in[12];
    const float* Wq2 = (const float*)d_in[13];
    const float* bq2 = (const float*)d_in[14];
    const float* Wk2 = (const float*)d_in[15];
    const float* bk2 = (const float*)d_in[16];
    const float* Wv2 = (const float*)d_in[17];
    const float* bv2 = (const float*)d_in[18];
    const float* We2 = (const float*)d_in[19];
    const float* Ws2 = (const float*)d_in[20];
    const float* bs2 = (const float*)d_in[21];
    float* out = (float*)d_out;

    float *pq, *pskip;
    __half *pkv, *pah, *pwh;
    cudaGetSymbolAddress((void**)&pq,    g_q);
    cudaGetSymbolAddress((void**)&pskip, g_skip);
    cudaGetSymbolAddress((void**)&pkv,   g_kv);
    cudaGetSymbolAddress((void**)&pah,   g_ah);
    cudaGetSymbolAddress((void**)&pwh,   g_wh);

    cudaFuncSetAttribute(gemm_qkvs_kernel<1>,
                         cudaFuncAttributeMaxDynamicSharedMemorySize, GSMEM_TOT);
    cudaFuncSetAttribute(gemm_qkvs_kernel<0>,
                         cudaFuncAttributeMaxDynamicSharedMemorySize, GSMEM_TOT);

    // side stream + events (created once, before any capture; reused every call)
    static cudaStream_t s1 = nullptr;
    static cudaEvent_t evFork = nullptr, evCSR = nullptr, evG1 = nullptr, evW2 = nullptr;
    if (s1 == nullptr) {
        cudaStreamCreateWithFlags(&s1, cudaStreamNonBlocking);
        cudaEventCreateWithFlags(&evFork, cudaEventDisableTiming);
        cudaEventCreateWithFlags(&evCSR,  cudaEventDisableTiming);
        cudaEventCreateWithFlags(&evG1,   cudaEventDisableTiming);
        cudaEventCreateWithFlags(&evW2,   cudaEventDisableTiming);
    }

    const int RT  = (N_NODES + 127) / 128;            // 391 row tiles
    const int EB  = (N_EDGES + 255) / 256;
    const int NB  = (N_NODES + 255) / 256;            // 196
    const int NWB = (N_NODES + 7) / 8;
    const int PZ  = (N_GRAPHS * 128 + 255) / 256;     // 1250

    // ---- fork: CSR build on side stream, overlapped with cvt+GEMM1 ----
    cudaEventRecord(evFork, 0);
    cudaStreamWaitEvent(s1, evFork, 0);

    init_zero_kernel<<<PZ, 256, 0, s1>>>(out);
    hist_kernel<<<EB, 256, 0, s1>>>(ei);
    scan1_kernel<<<NB, 256, 0, s1>>>();
    scan3_kernel<<<NB, 256, 0, s1>>>();
    csr_scatter_kernel<<<EB, 256, 0, s1>>>(ei, ea);
    cudaEventRecord(evCSR, s1);

    // ---- main stream: layer 1 cvt + merged GEMM ----
    cvt_h_kernel<<<(N_NODES * 128 / 4 + 255) / 256, 256>>>(x, pah, N_NODES * 128 / 4);
    cvt4_h_kernel<<<dim3(8192 / 256, 4), 256>>>(Wq1, Wk1, Wv1, Ws1,
                                                pwh, 8192, 8192, 8192, 8192);
    gemm_qkvs_kernel<1><<<dim3(RT, 8), 256, GSMEM_TOT>>>(
        pah, bq1, bk1, bv1, bs1, pq, pkv, pskip, 128);
    cudaEventRecord(evG1, 0);

    // side stream: layer-2 weight conversion (after gemm1 done reading W buf)
    cudaStreamWaitEvent(s1, evG1, 0);
    cvt4_h_kernel<<<dim3(16384 / 256, 4), 256, 0, s1>>>(Wq2, Wk2, Wv2, Ws2,
                                                        pwh, 16384, 16384, 16384, 8192);
    cudaEventRecord(evW2, s1);

    // main stream: attention layer 1 (needs CSR); writes fp16 h into g_ah
    cudaStreamWaitEvent(0, evCSR, 0);
    node_attn_kernel<1><<<NWB, 256>>>(pq, pkv, pskip, We1, batch, nullptr, pah);

    // ---- layer 2 (needs W2 conversion) ----
    cudaStreamWaitEvent(0, evW2, 0);
    gemm_qkvs_kernel<0><<<dim3(RT, 7), 256, GSMEM_TOT>>>(
        pah, bq2, bk2, bv2, bs2, pq, pkv, pskip, 256);
    node_attn_kernel<0><<<NWB, 256>>>(pq, pkv, pskip, We2, batch, out, nullptr);

    // ---- pool finish ----
    pool_div_kernel<<<PZ, 256>>>(out);
}